// round 1
// baseline (speedup 1.0000x reference)
#include <cuda_runtime.h>
#include <cstdint>
#include <cstddef>

// Problem constants (fixed shapes)
#define BATCH 8
#define SEQ   4096
#define HID   1024
#define NHEAD 16
#define HDIM  64
#define MROWS (BATCH * SEQ)   // 32768

// -------------------- scratch (device globals; no allocations allowed) -----
__device__ float g_mq[(size_t)MROWS * HID];   // mixed_query
__device__ float g_mk[(size_t)MROWS * HID];   // mixed_key
__device__ float g_qs[(size_t)MROWS * NHEAD]; // q scores (pre scale/mask)
__device__ float g_ks[(size_t)MROWS * NHEAD]; // qk scores (pre scale/mask)
__device__ float g_pq[BATCH * HID];           // pooled_q  [b, h*64+d]
__device__ float g_pk[BATCH * HID];           // pooled_k  [b, h*64+d]

// -------------------- helpers ----------------------------------------------
__device__ __forceinline__ uint32_t f2tf32(float f) {
    uint32_t r;
    asm("cvt.rna.tf32.f32 %0, %1;" : "=r"(r) : "f"(f));
    return r;
}

// ============================================================================
// GEMM: C[m,n] = sum_k A[m,k] * (W[n,k] * (GATE? g[b,k]:1)) + bias[n]
//                (+ RESID? resid[m,n] : 0)
// A: [M,1024] row-major, W: [1024,1024] row-major (N-major, K contiguous)
// Tile 128x128x32, tf32 mma.sync m16n8k8, cp.async double buffer.
// ============================================================================
constexpr int BM = 128, BN = 128, BK = 32;
constexpr int LDT = BK + 4;   // padded smem stride (36 floats, 144B: 16B-aligned)
constexpr int NKB = HID / BK; // 32

template <bool GATE, bool RESID>
__global__ void __launch_bounds__(256, 2) gemm_tf32_kernel(
    const float* __restrict__ A, const float* __restrict__ W,
    const float* __restrict__ bias, const float* __restrict__ gate,
    const float* __restrict__ resid, float* __restrict__ C)
{
    extern __shared__ float sm[];
    float* sA = sm;                   // 2 * BM * LDT
    float* sB = sm + 2 * BM * LDT;    // 2 * BN * LDT
    float* sG = sm + 4 * BM * LDT;    // HID (gate vector)

    const int tid = threadIdx.x;
    const int m0 = blockIdx.y * BM;
    const int n0 = blockIdx.x * BN;

    if (GATE) {
        const int b = m0 / SEQ;
        for (int i = tid; i < HID; i += 256) sG[i] = gate[b * HID + i];
    }

    const int warp = tid >> 5, lane = tid & 31;
    const int wm = warp & 3, wn = warp >> 2;      // 4x2 warp grid (32x64 per warp)
    const int grp = lane >> 2, qid = lane & 3;

    float acc[2][8][4];
#pragma unroll
    for (int i = 0; i < 2; i++)
#pragma unroll
        for (int j = 0; j < 8; j++)
#pragma unroll
            for (int l = 0; l < 4; l++) acc[i][j][l] = 0.f;

    auto loadTile = [&](int kb, int buf) {
        const float* Ag = A + (size_t)m0 * HID + kb * BK;
        const float* Wg = W + (size_t)n0 * HID + kb * BK;
        float* sa = sA + buf * BM * LDT;
        float* sb = sB + buf * BN * LDT;
#pragma unroll
        for (int i = 0; i < 4; i++) {
            int id = tid + 256 * i;
            int r = id >> 3, c = (id & 7) * 4;
            uint32_t da = (uint32_t)__cvta_generic_to_shared(sa + r * LDT + c);
            asm volatile("cp.async.cg.shared.global [%0], [%1], 16;\n"
                         :: "r"(da), "l"(Ag + (size_t)r * HID + c));
            uint32_t db = (uint32_t)__cvta_generic_to_shared(sb + r * LDT + c);
            asm volatile("cp.async.cg.shared.global [%0], [%1], 16;\n"
                         :: "r"(db), "l"(Wg + (size_t)r * HID + c));
        }
        asm volatile("cp.async.commit_group;\n");
    };

    loadTile(0, 0);

    for (int kb = 0; kb < NKB; kb++) {
        asm volatile("cp.async.wait_group 0;\n");
        __syncthreads();
        if (kb + 1 < NKB) loadTile(kb + 1, (kb + 1) & 1);

        const float* sa = sA + (kb & 1) * BM * LDT;
        const float* sb = sB + (kb & 1) * BN * LDT;

#pragma unroll
        for (int ks = 0; ks < 4; ks++) {
            const int kk = ks * 8;
            uint32_t af[2][4], bf[8][2];
#pragma unroll
            for (int mt = 0; mt < 2; mt++) {
                const int rm = wm * 32 + mt * 16 + grp;
                float a0 = sa[rm * LDT + kk + qid];
                float a1 = sa[(rm + 8) * LDT + kk + qid];
                float a2 = sa[rm * LDT + kk + qid + 4];
                float a3 = sa[(rm + 8) * LDT + kk + qid + 4];
                if (GATE) {
                    float g0 = sG[kb * BK + kk + qid];
                    float g1 = sG[kb * BK + kk + qid + 4];
                    a0 *= g0; a1 *= g0; a2 *= g1; a3 *= g1;
                }
                af[mt][0] = f2tf32(a0); af[mt][1] = f2tf32(a1);
                af[mt][2] = f2tf32(a2); af[mt][3] = f2tf32(a3);
            }
#pragma unroll
            for (int nt = 0; nt < 8; nt++) {
                const int cn = wn * 64 + nt * 8 + grp;  // b: n = lane/4, k = lane%4 (+4)
                bf[nt][0] = f2tf32(sb[cn * LDT + kk + qid]);
                bf[nt][1] = f2tf32(sb[cn * LDT + kk + qid + 4]);
            }
#pragma unroll
            for (int mt = 0; mt < 2; mt++)
#pragma unroll
                for (int nt = 0; nt < 8; nt++) {
                    asm volatile(
                        "mma.sync.aligned.m16n8k8.row.col.f32.tf32.tf32.f32 "
                        "{%0,%1,%2,%3}, {%4,%5,%6,%7}, {%8,%9}, {%0,%1,%2,%3};"
                        : "+f"(acc[mt][nt][0]), "+f"(acc[mt][nt][1]),
                          "+f"(acc[mt][nt][2]), "+f"(acc[mt][nt][3])
                        : "r"(af[mt][0]), "r"(af[mt][1]), "r"(af[mt][2]), "r"(af[mt][3]),
                          "r"(bf[nt][0]), "r"(bf[nt][1]));
                }
        }
    }

    // Epilogue: bias (+ residual), write float2 pairs.
#pragma unroll
    for (int mt = 0; mt < 2; mt++) {
        const int r0 = m0 + wm * 32 + mt * 16 + grp;
#pragma unroll
        for (int nt = 0; nt < 8; nt++) {
            const int c = n0 + wn * 64 + nt * 8 + qid * 2;
            const float bv0 = bias[c], bv1 = bias[c + 1];
            float v0 = acc[mt][nt][0] + bv0, v1 = acc[mt][nt][1] + bv1;
            float v2 = acc[mt][nt][2] + bv0, v3 = acc[mt][nt][3] + bv1;
            if (RESID) {
                float2 ra = *(const float2*)(resid + (size_t)r0 * HID + c);
                float2 rb = *(const float2*)(resid + (size_t)(r0 + 8) * HID + c);
                v0 += ra.x; v1 += ra.y; v2 += rb.x; v3 += rb.y;
            }
            float2 oa = {v0, v1}, ob = {v2, v3};
            *(float2*)(C + (size_t)r0 * HID + c) = oa;
            *(float2*)(C + (size_t)(r0 + 8) * HID + c) = ob;
        }
    }
}

// ============================================================================
// Score kernel: out[m,h] = sum_k src[m,k] * (W[h,k] * (gate? g[b,k]:1)) + bias[h]
// Warp-per-row; gated W (16x1024 = 64KB) in dynamic SMEM.
// ============================================================================
constexpr int SCORE_ROWS = 128;

__global__ void score_kernel(const float* __restrict__ src,
                             const float* __restrict__ W,
                             const float* __restrict__ bias,
                             const float* __restrict__ gate,
                             float* __restrict__ out)
{
    extern __shared__ float sW[];  // [16][1024]
    const int row0 = blockIdx.x * SCORE_ROWS;
    const int b = row0 / SEQ;

    for (int i = threadIdx.x; i < NHEAD * HID; i += blockDim.x) {
        float w = W[i];
        if (gate) w *= gate[b * HID + (i & (HID - 1))];
        sW[i] = w;
    }
    __syncthreads();

    const int warp = threadIdx.x >> 5, lane = threadIdx.x & 31;
    for (int r = warp; r < SCORE_ROWS; r += 8) {
        const int row = row0 + r;
        const float* x = src + (size_t)row * HID;
        float p[NHEAD];
#pragma unroll
        for (int h = 0; h < NHEAD; h++) p[h] = 0.f;
        for (int k = lane; k < HID; k += 32) {
            const float xv = x[k];
#pragma unroll
            for (int h = 0; h < NHEAD; h++) p[h] += xv * sW[h * HID + k];
        }
        float vout = 0.f;
#pragma unroll
        for (int h = 0; h < NHEAD; h++) {
            float v = p[h];
#pragma unroll
            for (int o = 16; o; o >>= 1) v += __shfl_xor_sync(0xffffffffu, v, o);
            if (lane == h) vout = v;
        }
        if (lane < NHEAD) out[(size_t)row * NHEAD + lane] = vout + bias[lane];
    }
}

// ============================================================================
// Pool kernel: per (b,h): softmax_s(score[b,s,h]*scale + mask[b,s]),
// pooled[d] = (sum_s w_s * src[b,s,h*64+d]) * (postgate? pg[b,h*64+d]:1)
// One block per (b,h), 256 threads.
// ============================================================================
__global__ void pool_kernel(const float* __restrict__ src,
                            const float* __restrict__ scores,
                            const float* __restrict__ mask,
                            const float* __restrict__ postgate,
                            float* __restrict__ out)
{
    __shared__ float sE[SEQ];
    __shared__ float red[256];
    const int b = blockIdx.x >> 4, h = blockIdx.x & 15;
    const int t = threadIdx.x;
    const float scale = 0.125f;  // 1/sqrt(64)

    // logits + max
    float mx = -1e30f;
    for (int s = t; s < SEQ; s += 256) {
        float l = scores[((size_t)(b * SEQ + s)) * NHEAD + h] * scale + mask[b * SEQ + s];
        sE[s] = l;
        mx = fmaxf(mx, l);
    }
    red[t] = mx; __syncthreads();
    for (int o = 128; o; o >>= 1) { if (t < o) red[t] = fmaxf(red[t], red[t + o]); __syncthreads(); }
    mx = red[0]; __syncthreads();

    // exp + sum
    float ps = 0.f;
    for (int s = t; s < SEQ; s += 256) {
        float e = __expf(sE[s] - mx);
        sE[s] = e;
        ps += e;
    }
    red[t] = ps; __syncthreads();
    for (int o = 128; o; o >>= 1) { if (t < o) red[t] += red[t + o]; __syncthreads(); }
    const float denom = red[0]; __syncthreads();

    // weighted reduction over S for 64 dims
    const int d = t & 63, sg = t >> 6;
    const float* base = src + (size_t)b * SEQ * HID + h * HDIM + d;
    float acc = 0.f;
    for (int s = sg; s < SEQ; s += 4) acc += sE[s] * base[(size_t)s * HID];
    red[t] = acc; __syncthreads();
    if (sg == 0) {
        float v = (red[d] + red[64 + d] + red[128 + d] + red[192 + d]) / denom;
        const int oi = b * HID + h * HDIM + d;
        if (postgate) v *= postgate[oi];
        out[oi] = v;
    }
}

// ============================================================================
// kernel_launch
// ============================================================================
extern "C" void kernel_launch(void* const* d_in, const int* in_sizes, int n_in,
                              void* d_out, int out_size)
{
    const float* X    = (const float*)d_in[0];
    const float* mask = (const float*)d_in[1];
    const float* Wq   = (const float*)d_in[2];
    const float* bq   = (const float*)d_in[3];
    const float* Wqa  = (const float*)d_in[4];
    const float* bqa  = (const float*)d_in[5];
    const float* Wk   = (const float*)d_in[6];
    const float* bk   = (const float*)d_in[7];
    const float* Wka  = (const float*)d_in[8];
    const float* bka  = (const float*)d_in[9];
    const float* Wt   = (const float*)d_in[10];
    const float* bt   = (const float*)d_in[11];
    float* out = (float*)d_out;

    float *mq, *mk, *qs, *ks, *pq, *pk;
    cudaGetSymbolAddress((void**)&mq, g_mq);
    cudaGetSymbolAddress((void**)&mk, g_mk);
    cudaGetSymbolAddress((void**)&qs, g_qs);
    cudaGetSymbolAddress((void**)&ks, g_ks);
    cudaGetSymbolAddress((void**)&pq, g_pq);
    cudaGetSymbolAddress((void**)&pk, g_pk);

    const size_t gemm_smem = (size_t)(4 * BM * LDT + HID) * sizeof(float); // 77824B
    cudaFuncSetAttribute(gemm_tf32_kernel<false, false>,
                         cudaFuncAttributeMaxDynamicSharedMemorySize, (int)gemm_smem);
    cudaFuncSetAttribute(gemm_tf32_kernel<true, true>,
                         cudaFuncAttributeMaxDynamicSharedMemorySize, (int)gemm_smem);
    const size_t score_smem = (size_t)NHEAD * HID * sizeof(float);         // 65536B
    cudaFuncSetAttribute(score_kernel,
                         cudaFuncAttributeMaxDynamicSharedMemorySize, (int)score_smem);

    dim3 ggrid(HID / BN, MROWS / BM);  // (8, 256)

    // 1) mixed_query = X @ Wq^T + bq ; mixed_key = X @ Wk^T + bk
    gemm_tf32_kernel<false, false><<<ggrid, 256, gemm_smem>>>(X, Wq, bq, nullptr, nullptr, mq);
    gemm_tf32_kernel<false, false><<<ggrid, 256, gemm_smem>>>(X, Wk, bk, nullptr, nullptr, mk);

    // 2) q scores = mq @ Wqa^T + bqa
    score_kernel<<<MROWS / SCORE_ROWS, 256, score_smem>>>(mq, Wqa, bqa, nullptr, qs);

    // 3) pooled_q
    pool_kernel<<<BATCH * NHEAD, 256>>>(mq, qs, mask, nullptr, pq);

    // 4) qk scores = (mk * pq) @ Wka^T + bka  (gate folded into Wka)
    score_kernel<<<MROWS / SCORE_ROWS, 256, score_smem>>>(mk, Wka, bka, pq, ks);

    // 5) pooled_k = pq * pooled(mk)  (gate folded as post-gate)
    pool_kernel<<<BATCH * NHEAD, 256>>>(mk, ks, mask, pq, pk);

    // 6) out = mq @ (Wt * pk[b])^T + bt + mq
    gemm_tf32_kernel<true, true><<<ggrid, 256, gemm_smem>>>(mq, Wt, bt, pk, mq, out);
}

// round 2
// speedup vs baseline: 1.0003x; 1.0003x over previous
#include <cuda_runtime.h>
#include <cstdint>
#include <cstddef>

// Problem constants (fixed shapes)
#define BATCH 8
#define SEQ   4096
#define HID   1024
#define NHEAD 16
#define HDIM  64
#define MROWS (BATCH * SEQ)   // 32768

// -------------------- scratch (device globals; no allocations allowed) -----
__device__ float g_mq[(size_t)MROWS * HID];   // mixed_query
__device__ float g_mk[(size_t)MROWS * HID];   // mixed_key
__device__ float g_qs[(size_t)MROWS * NHEAD]; // q scores (pre scale/mask)
__device__ float g_ks[(size_t)MROWS * NHEAD]; // qk scores (pre scale/mask)
__device__ float g_pq[BATCH * HID];           // pooled_q  [b, h*64+d]
__device__ float g_pk[BATCH * HID];           // pooled_k  [b, h*64+d]

// -------------------- helpers ----------------------------------------------
__device__ __forceinline__ uint32_t f2tf32(float f) {
    uint32_t r;
    asm("cvt.rna.tf32.f32 %0, %1;" : "=r"(r) : "f"(f));
    return r;
}

// ============================================================================
// GEMM: C[m,n] = sum_k A[m,k] * (W[n,k] * (GATE? g[b,k]:1)) + bias[n]
//                (+ RESID? resid[m,n] : 0)
// A: [M,1024] row-major, W: [1024,1024] row-major (N-major, K contiguous)
// Tile 128x128x32, tf32 mma.sync m16n8k8, cp.async double buffer.
// ============================================================================
constexpr int BM = 128, BN = 128, BK = 32;
constexpr int LDT = BK + 4;   // padded smem stride (36 floats, 144B: 16B-aligned)
constexpr int NKB = HID / BK; // 32

template <bool GATE, bool RESID>
__global__ void __launch_bounds__(256, 2) gemm_tf32_kernel(
    const float* __restrict__ A, const float* __restrict__ W,
    const float* __restrict__ bias, const float* __restrict__ gate,
    const float* __restrict__ resid, float* __restrict__ C)
{
    extern __shared__ float sm[];
    float* sA = sm;                   // 2 * BM * LDT
    float* sB = sm + 2 * BM * LDT;    // 2 * BN * LDT
    float* sG = sm + 4 * BM * LDT;    // HID (gate vector)

    const int tid = threadIdx.x;
    const int m0 = blockIdx.y * BM;
    const int n0 = blockIdx.x * BN;

    if (GATE) {
        const int b = m0 / SEQ;
        for (int i = tid; i < HID; i += 256) sG[i] = gate[b * HID + i];
    }

    const int warp = tid >> 5, lane = tid & 31;
    const int wm = warp & 3, wn = warp >> 2;      // 4x2 warp grid (32x64 per warp)
    const int grp = lane >> 2, qid = lane & 3;

    float acc[2][8][4];
#pragma unroll
    for (int i = 0; i < 2; i++)
#pragma unroll
        for (int j = 0; j < 8; j++)
#pragma unroll
            for (int l = 0; l < 4; l++) acc[i][j][l] = 0.f;

    auto loadTile = [&](int kb, int buf) {
        const float* Ag = A + (size_t)m0 * HID + kb * BK;
        const float* Wg = W + (size_t)n0 * HID + kb * BK;
        float* sa = sA + buf * BM * LDT;
        float* sb = sB + buf * BN * LDT;
#pragma unroll
        for (int i = 0; i < 4; i++) {
            int id = tid + 256 * i;
            int r = id >> 3, c = (id & 7) * 4;
            uint32_t da = (uint32_t)__cvta_generic_to_shared(sa + r * LDT + c);
            asm volatile("cp.async.cg.shared.global [%0], [%1], 16;\n"
                         :: "r"(da), "l"(Ag + (size_t)r * HID + c));
            uint32_t db = (uint32_t)__cvta_generic_to_shared(sb + r * LDT + c);
            asm volatile("cp.async.cg.shared.global [%0], [%1], 16;\n"
                         :: "r"(db), "l"(Wg + (size_t)r * HID + c));
        }
        asm volatile("cp.async.commit_group;\n");
    };

    loadTile(0, 0);

    for (int kb = 0; kb < NKB; kb++) {
        asm volatile("cp.async.wait_group 0;\n");
        __syncthreads();
        if (kb + 1 < NKB) loadTile(kb + 1, (kb + 1) & 1);

        const float* sa = sA + (kb & 1) * BM * LDT;
        const float* sb = sB + (kb & 1) * BN * LDT;

#pragma unroll
        for (int ks = 0; ks < 4; ks++) {
            const int kk = ks * 8;
            uint32_t af[2][4], bf[8][2];
#pragma unroll
            for (int mt = 0; mt < 2; mt++) {
                const int rm = wm * 32 + mt * 16 + grp;
                float a0 = sa[rm * LDT + kk + qid];
                float a1 = sa[(rm + 8) * LDT + kk + qid];
                float a2 = sa[rm * LDT + kk + qid + 4];
                float a3 = sa[(rm + 8) * LDT + kk + qid + 4];
                if (GATE) {
                    float g0 = sG[kb * BK + kk + qid];
                    float g1 = sG[kb * BK + kk + qid + 4];
                    a0 *= g0; a1 *= g0; a2 *= g1; a3 *= g1;
                }
                af[mt][0] = f2tf32(a0); af[mt][1] = f2tf32(a1);
                af[mt][2] = f2tf32(a2); af[mt][3] = f2tf32(a3);
            }
#pragma unroll
            for (int nt = 0; nt < 8; nt++) {
                const int cn = wn * 64 + nt * 8 + grp;  // b: n = lane/4, k = lane%4 (+4)
                bf[nt][0] = f2tf32(sb[cn * LDT + kk + qid]);
                bf[nt][1] = f2tf32(sb[cn * LDT + kk + qid + 4]);
            }
#pragma unroll
            for (int mt = 0; mt < 2; mt++)
#pragma unroll
                for (int nt = 0; nt < 8; nt++) {
                    asm volatile(
                        "mma.sync.aligned.m16n8k8.row.col.f32.tf32.tf32.f32 "
                        "{%0,%1,%2,%3}, {%4,%5,%6,%7}, {%8,%9}, {%0,%1,%2,%3};"
                        : "+f"(acc[mt][nt][0]), "+f"(acc[mt][nt][1]),
                          "+f"(acc[mt][nt][2]), "+f"(acc[mt][nt][3])
                        : "r"(af[mt][0]), "r"(af[mt][1]), "r"(af[mt][2]), "r"(af[mt][3]),
                          "r"(bf[nt][0]), "r"(bf[nt][1]));
                }
        }
    }

    // Epilogue: bias (+ residual), write float2 pairs.
#pragma unroll
    for (int mt = 0; mt < 2; mt++) {
        const int r0 = m0 + wm * 32 + mt * 16 + grp;
#pragma unroll
        for (int nt = 0; nt < 8; nt++) {
            const int c = n0 + wn * 64 + nt * 8 + qid * 2;
            const float bv0 = bias[c], bv1 = bias[c + 1];
            float v0 = acc[mt][nt][0] + bv0, v1 = acc[mt][nt][1] + bv1;
            float v2 = acc[mt][nt][2] + bv0, v3 = acc[mt][nt][3] + bv1;
            if (RESID) {
                float2 ra = *(const float2*)(resid + (size_t)r0 * HID + c);
                float2 rb = *(const float2*)(resid + (size_t)(r0 + 8) * HID + c);
                v0 += ra.x; v1 += ra.y; v2 += rb.x; v3 += rb.y;
            }
            float2 oa = {v0, v1}, ob = {v2, v3};
            *(float2*)(C + (size_t)r0 * HID + c) = oa;
            *(float2*)(C + (size_t)(r0 + 8) * HID + c) = ob;
        }
    }
}

// ============================================================================
// Score kernel: out[m,h] = sum_k src[m,k] * (W[h,k] * (gate? g[b,k]:1)) + bias[h]
// Warp-per-row; gated W (16x1024 = 64KB) in dynamic SMEM.
// ============================================================================
constexpr int SCORE_ROWS = 128;

__global__ void score_kernel(const float* __restrict__ src,
                             const float* __restrict__ W,
                             const float* __restrict__ bias,
                             const float* __restrict__ gate,
                             float* __restrict__ out)
{
    extern __shared__ float sW[];  // [16][1024]
    const int row0 = blockIdx.x * SCORE_ROWS;
    const int b = row0 / SEQ;

    for (int i = threadIdx.x; i < NHEAD * HID; i += blockDim.x) {
        float w = W[i];
        if (gate) w *= gate[b * HID + (i & (HID - 1))];
        sW[i] = w;
    }
    __syncthreads();

    const int warp = threadIdx.x >> 5, lane = threadIdx.x & 31;
    for (int r = warp; r < SCORE_ROWS; r += 8) {
        const int row = row0 + r;
        const float* x = src + (size_t)row * HID;
        float p[NHEAD];
#pragma unroll
        for (int h = 0; h < NHEAD; h++) p[h] = 0.f;
        for (int k = lane; k < HID; k += 32) {
            const float xv = x[k];
#pragma unroll
            for (int h = 0; h < NHEAD; h++) p[h] += xv * sW[h * HID + k];
        }
        float vout = 0.f;
#pragma unroll
        for (int h = 0; h < NHEAD; h++) {
            float v = p[h];
#pragma unroll
            for (int o = 16; o; o >>= 1) v += __shfl_xor_sync(0xffffffffu, v, o);
            if (lane == h) vout = v;
        }
        if (lane < NHEAD) out[(size_t)row * NHEAD + lane] = vout + bias[lane];
    }
}

// ============================================================================
// Pool kernel: per (b,h): softmax_s(score[b,s,h]*scale + mask[b,s]),
// pooled[d] = (sum_s w_s * src[b,s,h*64+d]) * (postgate? pg[b,h*64+d]:1)
// One block per (b,h), 256 threads.
// ============================================================================
__global__ void pool_kernel(const float* __restrict__ src,
                            const float* __restrict__ scores,
                            const float* __restrict__ mask,
                            const float* __restrict__ postgate,
                            float* __restrict__ out)
{
    __shared__ float sE[SEQ];
    __shared__ float red[256];
    const int b = blockIdx.x >> 4, h = blockIdx.x & 15;
    const int t = threadIdx.x;
    const float scale = 0.125f;  // 1/sqrt(64)

    // logits + max
    float mx = -1e30f;
    for (int s = t; s < SEQ; s += 256) {
        float l = scores[((size_t)(b * SEQ + s)) * NHEAD + h] * scale + mask[b * SEQ + s];
        sE[s] = l;
        mx = fmaxf(mx, l);
    }
    red[t] = mx; __syncthreads();
    for (int o = 128; o; o >>= 1) { if (t < o) red[t] = fmaxf(red[t], red[t + o]); __syncthreads(); }
    mx = red[0]; __syncthreads();

    // exp + sum
    float ps = 0.f;
    for (int s = t; s < SEQ; s += 256) {
        float e = __expf(sE[s] - mx);
        sE[s] = e;
        ps += e;
    }
    red[t] = ps; __syncthreads();
    for (int o = 128; o; o >>= 1) { if (t < o) red[t] += red[t + o]; __syncthreads(); }
    const float denom = red[0]; __syncthreads();

    // weighted reduction over S for 64 dims
    const int d = t & 63, sg = t >> 6;
    const float* base = src + (size_t)b * SEQ * HID + h * HDIM + d;
    float acc = 0.f;
    for (int s = sg; s < SEQ; s += 4) acc += sE[s] * base[(size_t)s * HID];
    red[t] = acc; __syncthreads();
    if (sg == 0) {
        float v = (red[d] + red[64 + d] + red[128 + d] + red[192 + d]) / denom;
        const int oi = b * HID + h * HDIM + d;
        if (postgate) v *= postgate[oi];
        out[oi] = v;
    }
}

// ============================================================================
// kernel_launch
// ============================================================================
extern "C" void kernel_launch(void* const* d_in, const int* in_sizes, int n_in,
                              void* d_out, int out_size)
{
    const float* X    = (const float*)d_in[0];
    const float* mask = (const float*)d_in[1];
    const float* Wq   = (const float*)d_in[2];
    const float* bq   = (const float*)d_in[3];
    const float* Wqa  = (const float*)d_in[4];
    const float* bqa  = (const float*)d_in[5];
    const float* Wk   = (const float*)d_in[6];
    const float* bk   = (const float*)d_in[7];
    const float* Wka  = (const float*)d_in[8];
    const float* bka  = (const float*)d_in[9];
    const float* Wt   = (const float*)d_in[10];
    const float* bt   = (const float*)d_in[11];
    float* out = (float*)d_out;

    float *mq, *mk, *qs, *ks, *pq, *pk;
    cudaGetSymbolAddress((void**)&mq, g_mq);
    cudaGetSymbolAddress((void**)&mk, g_mk);
    cudaGetSymbolAddress((void**)&qs, g_qs);
    cudaGetSymbolAddress((void**)&ks, g_ks);
    cudaGetSymbolAddress((void**)&pq, g_pq);
    cudaGetSymbolAddress((void**)&pk, g_pk);

    const size_t gemm_smem = (size_t)(4 * BM * LDT + HID) * sizeof(float); // 77824B
    cudaFuncSetAttribute(gemm_tf32_kernel<false, false>,
                         cudaFuncAttributeMaxDynamicSharedMemorySize, (int)gemm_smem);
    cudaFuncSetAttribute(gemm_tf32_kernel<true, true>,
                         cudaFuncAttributeMaxDynamicSharedMemorySize, (int)gemm_smem);
    const size_t score_smem = (size_t)NHEAD * HID * sizeof(float);         // 65536B
    cudaFuncSetAttribute(score_kernel,
                         cudaFuncAttributeMaxDynamicSharedMemorySize, (int)score_smem);

    dim3 ggrid(HID / BN, MROWS / BM);  // (8, 256)

    // 1) mixed_query = X @ Wq^T + bq ; mixed_key = X @ Wk^T + bk
    gemm_tf32_kernel<false, false><<<ggrid, 256, gemm_smem>>>(X, Wq, bq, nullptr, nullptr, mq);
    gemm_tf32_kernel<false, false><<<ggrid, 256, gemm_smem>>>(X, Wk, bk, nullptr, nullptr, mk);

    // 2) q scores = mq @ Wqa^T + bqa
    score_kernel<<<MROWS / SCORE_ROWS, 256, score_smem>>>(mq, Wqa, bqa, nullptr, qs);

    // 3) pooled_q
    pool_kernel<<<BATCH * NHEAD, 256>>>(mq, qs, mask, nullptr, pq);

    // 4) qk scores = (mk * pq) @ Wka^T + bka  (gate folded into Wka)
    score_kernel<<<MROWS / SCORE_ROWS, 256, score_smem>>>(mk, Wka, bka, pq, ks);

    // 5) pooled_k = pq * pooled(mk)  (gate folded as post-gate)
    pool_kernel<<<BATCH * NHEAD, 256>>>(mk, ks, mask, pq, pk);

    // 6) out = mq @ (Wt * pk[b])^T + bt + mq
    gemm_tf32_kernel<true, true><<<ggrid, 256, gemm_smem>>>(mq, Wt, bt, pk, mq, out);
}

// round 4
// speedup vs baseline: 1.2370x; 1.2367x over previous
#include <cuda_runtime.h>
#include <cstdint>
#include <cstddef>

#define BATCH 8
#define SEQ   4096
#define HID   1024
#define NHEAD 16
#define MROWS (BATCH * SEQ)   // 32768

// ---------------- scratch (device globals; allocations forbidden) ----------
__device__ float  g_mq[(size_t)MROWS * HID];
__device__ float  g_mk[(size_t)MROWS * HID];
__device__ float  g_qs[(size_t)MROWS * NHEAD];
__device__ float  g_ks[(size_t)MROWS * NHEAD];
__device__ float  g_pq[BATCH * HID];
__device__ float  g_pk[BATCH * HID];
__device__ float2 g_stq[BATCH * NHEAD];
__device__ float2 g_stk[BATCH * NHEAD];
__device__ float  g_part[BATCH * NHEAD * 8 * 64];
__device__ float  g_wtg[(size_t)BATCH * HID * HID];

__device__ __forceinline__ uint32_t f2tf32(float f) {
    uint32_t r;
    asm("cvt.rna.tf32.f32 %0, %1;" : "=r"(r) : "f"(f));
    return r;
}

// ============================================================================
// GEMM: C[m,n] = sum_k A[m,k] * W[n,k] + bias[n] (+ resid[m,n])
// BM=256, BN=128, BK=32; 256 threads; 3-stage cp.async; mma.sync tf32 m16n8k8.
// DUAL: grid.x = 16; nb<8 -> (W0,b0,C0), else (W1,b1,C1).
// PERB: W indexed per batch (m0/SEQ).
// ============================================================================
constexpr int BM = 256, BN = 128, BK = 32;
constexpr int LDT = BK + 4;                 // 36 floats, 144B rows (16B aligned)
constexpr int NKB = HID / BK;               // 32
constexpr int STG = (BM + BN) * LDT;        // floats per stage (13824)
constexpr size_t GEMM_SMEM = (size_t)3 * STG * sizeof(float);  // 165888 B

template <bool DUAL, bool RESID, bool PERB>
__global__ void __launch_bounds__(256, 1) gemm_tf32(
    const float* __restrict__ A, const float* __restrict__ W0, const float* __restrict__ W1,
    const float* __restrict__ b0, const float* __restrict__ b1,
    const float* __restrict__ resid, float* __restrict__ C0, float* __restrict__ C1)
{
    extern __shared__ float sm[];
    const int tid = threadIdx.x;
    const int m0 = blockIdx.y * BM;
    int nb = blockIdx.x;

    const float* W; const float* bias; float* C;
    if (DUAL) {
        if (nb < 8) { W = W0; bias = b0; C = C0; }
        else        { nb -= 8; W = W1; bias = b1; C = C1; }
    } else {
        W = W0 + (PERB ? (size_t)(m0 / SEQ) * HID * HID : 0);
        bias = b0; C = C0;
    }
    const int n0 = nb * BN;

    const int warp = tid >> 5, lane = tid & 31;
    const int wm = warp & 3, wn = warp >> 2;    // 4x2 warps -> 64x64 per warp
    const int grp = lane >> 2, qid = lane & 3;

    float acc[4][8][4];
#pragma unroll
    for (int i = 0; i < 4; i++)
#pragma unroll
        for (int j = 0; j < 8; j++)
#pragma unroll
            for (int l = 0; l < 4; l++) acc[i][j][l] = 0.f;

    const float* Ab = A + (size_t)m0 * HID;
    const float* Wb = W + (size_t)n0 * HID;

    auto loadTile = [&](int kb, int s) {
        const float* Ag = Ab + kb * BK;
        const float* Wg = Wb + kb * BK;
        float* sa = sm + s * STG;
        float* sb = sa + BM * LDT;
#pragma unroll
        for (int i = 0; i < 8; i++) {               // A: 256 rows x 32 cols
            int id = tid + 256 * i;
            int r = id >> 3, c = (id & 7) * 4;
            uint32_t d = (uint32_t)__cvta_generic_to_shared(sa + r * LDT + c);
            asm volatile("cp.async.cg.shared.global [%0], [%1], 16;"
                         :: "r"(d), "l"(Ag + (size_t)r * HID + c));
        }
#pragma unroll
        for (int i = 0; i < 4; i++) {               // B: 128 rows x 32 cols
            int id = tid + 256 * i;
            int r = id >> 3, c = (id & 7) * 4;
            uint32_t d = (uint32_t)__cvta_generic_to_shared(sb + r * LDT + c);
            asm volatile("cp.async.cg.shared.global [%0], [%1], 16;"
                         :: "r"(d), "l"(Wg + (size_t)r * HID + c));
        }
        asm volatile("cp.async.commit_group;");
    };

    loadTile(0, 0);
    loadTile(1, 1);

    int s = 0;
    for (int kb = 0; kb < NKB; kb++) {
        asm volatile("cp.async.wait_group 1;");
        __syncthreads();
        if (kb + 2 < NKB) loadTile(kb + 2, (s + 2) % 3);

        const float* sa = sm + s * STG;
        const float* sb = sa + BM * LDT;

#pragma unroll
        for (int ks = 0; ks < 4; ks++) {
            const int kk = ks * 8;
            uint32_t af[4][4], bf[8][2];
#pragma unroll
            for (int mt = 0; mt < 4; mt++) {
                const int rm = wm * 64 + mt * 16 + grp;
                af[mt][0] = f2tf32(sa[rm * LDT + kk + qid]);
                af[mt][1] = f2tf32(sa[(rm + 8) * LDT + kk + qid]);
                af[mt][2] = f2tf32(sa[rm * LDT + kk + qid + 4]);
                af[mt][3] = f2tf32(sa[(rm + 8) * LDT + kk + qid + 4]);
            }
#pragma unroll
            for (int nt = 0; nt < 8; nt++) {
                const int cn = wn * 64 + nt * 8 + grp;
                bf[nt][0] = f2tf32(sb[cn * LDT + kk + qid]);
                bf[nt][1] = f2tf32(sb[cn * LDT + kk + qid + 4]);
            }
#pragma unroll
            for (int mt = 0; mt < 4; mt++)
#pragma unroll
                for (int nt = 0; nt < 8; nt++) {
                    asm volatile(
                        "mma.sync.aligned.m16n8k8.row.col.f32.tf32.tf32.f32 "
                        "{%0,%1,%2,%3}, {%4,%5,%6,%7}, {%8,%9}, {%0,%1,%2,%3};"
                        : "+f"(acc[mt][nt][0]), "+f"(acc[mt][nt][1]),
                          "+f"(acc[mt][nt][2]), "+f"(acc[mt][nt][3])
                        : "r"(af[mt][0]), "r"(af[mt][1]), "r"(af[mt][2]), "r"(af[mt][3]),
                          "r"(bf[nt][0]), "r"(bf[nt][1]));
                }
        }
        s = (s + 1) % 3;
    }

    // epilogue
#pragma unroll
    for (int mt = 0; mt < 4; mt++) {
        const int r0 = m0 + wm * 64 + mt * 16 + grp;
#pragma unroll
        for (int nt = 0; nt < 8; nt++) {
            const int c = n0 + wn * 64 + nt * 8 + qid * 2;
            const float bv0 = bias[c], bv1 = bias[c + 1];
            float v0 = acc[mt][nt][0] + bv0, v1 = acc[mt][nt][1] + bv1;
            float v2 = acc[mt][nt][2] + bv0, v3 = acc[mt][nt][3] + bv1;
            if (RESID) {
                float2 ra = *(const float2*)(resid + (size_t)r0 * HID + c);
                float2 rb = *(const float2*)(resid + (size_t)(r0 + 8) * HID + c);
                v0 += ra.x; v1 += ra.y; v2 += rb.x; v3 += rb.y;
            }
            float2 oa = {v0, v1}, ob = {v2, v3};
            *(float2*)(C + (size_t)r0 * HID + c) = oa;
            *(float2*)(C + (size_t)(r0 + 8) * HID + c) = ob;
        }
    }
}

// ============================================================================
// Score: out[m,h] = sum_k src[m,k]*(W[h,k]*(gate?g[b,k]:1)) + bias[h]
// 4 rows per warp iteration: one sW load feeds 4 FMAs.
// ============================================================================
constexpr int SCORE_ROWS = 128;

__global__ void score_kernel(const float* __restrict__ src,
                             const float* __restrict__ W,
                             const float* __restrict__ bias,
                             const float* __restrict__ gate,
                             float* __restrict__ out)
{
    extern __shared__ float sW[];  // [16][1024]
    const int row0 = blockIdx.x * SCORE_ROWS;
    const int b = row0 / SEQ;

    for (int i = threadIdx.x; i < NHEAD * HID; i += blockDim.x) {
        float w = W[i];
        if (gate) w *= gate[b * HID + (i & (HID - 1))];
        sW[i] = w;
    }
    __syncthreads();

    const int warp = threadIdx.x >> 5, lane = threadIdx.x & 31;
    for (int g = warp; g < SCORE_ROWS / 4; g += 8) {
        const int row = row0 + g * 4;
        const float* x0 = src + (size_t)row * HID;
        float p[4][NHEAD];
#pragma unroll
        for (int r = 0; r < 4; r++)
#pragma unroll
            for (int h = 0; h < NHEAD; h++) p[r][h] = 0.f;
        for (int k = lane; k < HID; k += 32) {
            float xv0 = x0[k];
            float xv1 = x0[HID + k];
            float xv2 = x0[2 * HID + k];
            float xv3 = x0[3 * HID + k];
#pragma unroll
            for (int h = 0; h < NHEAD; h++) {
                const float wv = sW[h * HID + k];
                p[0][h] += xv0 * wv; p[1][h] += xv1 * wv;
                p[2][h] += xv2 * wv; p[3][h] += xv3 * wv;
            }
        }
#pragma unroll
        for (int r = 0; r < 4; r++) {
            float vout = 0.f;
#pragma unroll
            for (int h = 0; h < NHEAD; h++) {
                float v = p[r][h];
#pragma unroll
                for (int o = 16; o; o >>= 1) v += __shfl_xor_sync(0xffffffffu, v, o);
                if (lane == h) vout = v;
            }
            if (lane < NHEAD)
                out[(size_t)(row + r) * NHEAD + lane] = vout + bias[lane];
        }
    }
}

// ============================================================================
// Softmax stats per (b,h): max & denom over S
// ============================================================================
__global__ void stats_kernel(const float* __restrict__ scores,
                             const float* __restrict__ mask, float2* __restrict__ st)
{
    __shared__ float red[256];
    const int bh = blockIdx.x, b = bh >> 4, h = bh & 15;
    const int t = threadIdx.x;
    const float* sc = scores + (size_t)b * SEQ * NHEAD + h;
    const float* mk = mask + b * SEQ;
    float mx = -1e30f;
    for (int s = t; s < SEQ; s += 256) mx = fmaxf(mx, sc[(size_t)s * NHEAD] * 0.125f + mk[s]);
    red[t] = mx; __syncthreads();
    for (int o = 128; o; o >>= 1) { if (t < o) red[t] = fmaxf(red[t], red[t + o]); __syncthreads(); }
    mx = red[0]; __syncthreads();
    float ps = 0.f;
    for (int s = t; s < SEQ; s += 256) ps += __expf(sc[(size_t)s * NHEAD] * 0.125f + mk[s] - mx);
    red[t] = ps; __syncthreads();
    for (int o = 128; o; o >>= 1) { if (t < o) red[t] += red[t + o]; __syncthreads(); }
    if (t == 0) st[bh] = make_float2(mx, red[0]);
}

// ============================================================================
// Pool partials: block = (bh, chunk of 512 rows); deterministic, no atomics
// ============================================================================
__global__ void accum_kernel(const float* __restrict__ src,
                             const float* __restrict__ scores,
                             const float* __restrict__ mask,
                             const float2* __restrict__ st, float* __restrict__ part)
{
    __shared__ float red[256];
    const int blk = blockIdx.x, bh = blk >> 3, ch = blk & 7;
    const int b = bh >> 4, h = bh & 15;
    const int t = threadIdx.x, d = t & 63, sg = t >> 6;
    const float2 s2 = st[bh];
    const float mx = s2.x, inv = 1.0f / s2.y;
    const float* base = src + (size_t)b * SEQ * HID + h * 64 + d;
    const float* sc = scores + (size_t)b * SEQ * NHEAD + h;
    const float* mk = mask + b * SEQ;
    float acc = 0.f;
    const int s0 = ch * 512;
    for (int s = s0 + sg; s < s0 + 512; s += 4) {
        float w = __expf(sc[(size_t)s * NHEAD] * 0.125f + mk[s] - mx);
        acc += w * base[(size_t)s * HID];
    }
    red[t] = acc; __syncthreads();
    if (sg == 0)
        part[(size_t)blk * 64 + d] = (red[d] + red[64 + d] + red[128 + d] + red[192 + d]) * inv;
}

__global__ void finalize_kernel(const float* __restrict__ part,
                                const float* __restrict__ postgate, float* __restrict__ out)
{
    const int idx = blockIdx.x * 256 + threadIdx.x;   // 8192
    const int bh = idx >> 6, d = idx & 63;
    float v = 0.f;
#pragma unroll
    for (int c = 0; c < 8; c++) v += part[(size_t)(bh * 8 + c) * 64 + d];
    if (postgate) v *= postgate[idx];
    out[idx] = v;
}

// wtg[b,n,k] = Wt[n,k] * pk[b,k]
__global__ void wtg_kernel(const float* __restrict__ Wt, const float* __restrict__ pk,
                           float* __restrict__ wtg)
{
    const size_t i4 = (size_t)blockIdx.x * 256 + threadIdx.x;  // 2,097,152
    const int j4 = (int)(i4 & 255);
    const int n  = (int)((i4 >> 8) & 1023);
    const int b  = (int)(i4 >> 18);
    float4 w = ((const float4*)Wt)[n * 256 + j4];
    float4 g = ((const float4*)pk)[b * 256 + j4];
    w.x *= g.x; w.y *= g.y; w.z *= g.z; w.w *= g.w;
    ((float4*)wtg)[i4] = w;
}

// ============================================================================
extern "C" void kernel_launch(void* const* d_in, const int* in_sizes, int n_in,
                              void* d_out, int out_size)
{
    const float* X    = (const float*)d_in[0];
    const float* mask = (const float*)d_in[1];
    const float* Wq   = (const float*)d_in[2];
    const float* bq   = (const float*)d_in[3];
    const float* Wqa  = (const float*)d_in[4];
    const float* bqa  = (const float*)d_in[5];
    const float* Wk   = (const float*)d_in[6];
    const float* bk   = (const float*)d_in[7];
    const float* Wka  = (const float*)d_in[8];
    const float* bka  = (const float*)d_in[9];
    const float* Wt   = (const float*)d_in[10];
    const float* bt   = (const float*)d_in[11];
    float* out = (float*)d_out;

    float *mq, *mk, *qs, *ks, *pq, *pk, *part, *wtg;
    float2 *stq, *stk;
    cudaGetSymbolAddress((void**)&mq, g_mq);
    cudaGetSymbolAddress((void**)&mk, g_mk);
    cudaGetSymbolAddress((void**)&qs, g_qs);
    cudaGetSymbolAddress((void**)&ks, g_ks);
    cudaGetSymbolAddress((void**)&pq, g_pq);
    cudaGetSymbolAddress((void**)&pk, g_pk);
    cudaGetSymbolAddress((void**)&part, g_part);
    cudaGetSymbolAddress((void**)&wtg, g_wtg);
    cudaGetSymbolAddress((void**)&stq, g_stq);
    cudaGetSymbolAddress((void**)&stk, g_stk);

    cudaFuncSetAttribute(gemm_tf32<true, false, false>,
                         cudaFuncAttributeMaxDynamicSharedMemorySize, (int)GEMM_SMEM);
    cudaFuncSetAttribute(gemm_tf32<false, true, true>,
                         cudaFuncAttributeMaxDynamicSharedMemorySize, (int)GEMM_SMEM);
    const size_t score_smem = (size_t)NHEAD * HID * sizeof(float);
    cudaFuncSetAttribute(score_kernel,
                         cudaFuncAttributeMaxDynamicSharedMemorySize, (int)score_smem);

    // 1) fused: mq = X@Wq^T + bq ; mk = X@Wk^T + bk
    gemm_tf32<true, false, false><<<dim3(16, MROWS / BM), 256, GEMM_SMEM>>>(
        X, Wq, Wk, bq, bk, nullptr, mq, mk);

    // 2) q scores -> pooled_q
    score_kernel<<<MROWS / SCORE_ROWS, 256, score_smem>>>(mq, Wqa, bqa, nullptr, qs);
    stats_kernel<<<BATCH * NHEAD, 256>>>(qs, mask, stq);
    accum_kernel<<<BATCH * NHEAD * 8, 256>>>(mq, qs, mask, stq, part);
    finalize_kernel<<<BATCH * HID / 256, 256>>>(part, nullptr, pq);

    // 3) qk scores (gate folded into Wka) -> pooled_k (post-gate pq)
    score_kernel<<<MROWS / SCORE_ROWS, 256, score_smem>>>(mk, Wka, bka, pq, ks);
    stats_kernel<<<BATCH * NHEAD, 256>>>(ks, mask, stk);
    accum_kernel<<<BATCH * NHEAD * 8, 256>>>(mk, ks, mask, stk, part);
    finalize_kernel<<<BATCH * HID / 256, 256>>>(part, pq, pk);

    // 4) wtg = Wt * pk_full[b] ; out = mq @ wtg[b]^T + bt + mq
    wtg_kernel<<<(BATCH * HID * HID / 4) / 256, 256>>>(Wt, pk, wtg);
    gemm_tf32<false, true, true><<<dim3(8, MROWS / BM), 256, GEMM_SMEM>>>(
        mq, wtg, nullptr, bt, nullptr, mq, out, nullptr);
}

// round 6
// speedup vs baseline: 2.0179x; 1.6313x over previous
#include <cuda_runtime.h>
#include <cuda_fp16.h>
#include <cstdint>
#include <cstddef>

#define BATCH 8
#define SEQ   4096
#define HID   1024
#define NHEAD 16
#define MROWS (BATCH * SEQ)   // 32768

// ---------------- scratch (device globals; allocations forbidden) ----------
__device__ float  g_mq[(size_t)MROWS * HID];
__device__ float  g_mk[(size_t)MROWS * HID];
__device__ __half g_xh[(size_t)MROWS * HID];
__device__ __half g_mqh[(size_t)MROWS * HID];
__device__ __half g_wqh[(size_t)HID * HID];
__device__ __half g_wkh[(size_t)HID * HID];
__device__ __half g_wtgh[(size_t)BATCH * HID * HID];
__device__ float  g_qs[(size_t)MROWS * NHEAD];
__device__ float  g_ks[(size_t)MROWS * NHEAD];
__device__ float  g_pq[BATCH * HID];
__device__ float  g_pk[BATCH * HID];
__device__ float2 g_stq[BATCH * NHEAD];
__device__ float2 g_stk[BATCH * NHEAD];
__device__ float  g_part[BATCH * NHEAD * 8 * 64];

// ============================================================================
// fp16 GEMM: C[m,n] = sum_k A[m,k]*W[n,k] (+bias[n]) (+resid) [*2^-14 if SCALED]
// BM=256, BN=128, BK=64 halves; 256 thr; 3-stage cp.async; mma m16n8k16 f16.
// DUAL: grid.x=16, nb<8 -> (W0,b0,C0[,H0]), else (W1,b1,C1).
// PERB: W indexed per batch. HCOPY: also emit fp16 copy of C0.
// ============================================================================
constexpr int BM = 256, BN = 128, BK = 64;
constexpr int SROW = 72;                      // halves per smem row (144B, padded)
constexpr int NKB = HID / BK;                 // 16
constexpr int STGH = (BM + BN) * SROW;        // 27648 halves per stage
constexpr size_t GEMM_SMEM = (size_t)3 * STGH * sizeof(__half);  // 165888 B

template <bool DUAL, bool RESID, bool PERB, bool HCOPY, bool SCALED>
__global__ void __launch_bounds__(256, 1) gemm_fp16(
    const __half* __restrict__ A, const __half* __restrict__ W0, const __half* __restrict__ W1,
    const float* __restrict__ b0, const float* __restrict__ b1,
    const float* __restrict__ resid, float* __restrict__ C0, float* __restrict__ C1,
    __half* __restrict__ H0)
{
    extern __shared__ __half smh[];
    const int tid = threadIdx.x;
    const int m0 = blockIdx.y * BM;
    int nb = blockIdx.x;

    const __half* W; const float* bias; float* C;
    bool isC0 = true;
    if (DUAL) {
        if (nb < 8) { W = W0; bias = b0; C = C0; }
        else        { nb -= 8; W = W1; bias = b1; C = C1; isC0 = false; }
    } else {
        W = W0 + (PERB ? (size_t)(m0 / SEQ) * HID * HID : 0);
        bias = b0; C = C0;
    }
    const int n0 = nb * BN;

    const int warp = tid >> 5, lane = tid & 31;
    const int wm = warp & 3, wn = warp >> 2;    // 4x2 warps -> 64x64 per warp
    const int grp = lane >> 2, qid = lane & 3;

    float acc[4][8][4];
#pragma unroll
    for (int i = 0; i < 4; i++)
#pragma unroll
        for (int j = 0; j < 8; j++)
#pragma unroll
            for (int l = 0; l < 4; l++) acc[i][j][l] = 0.f;

    const __half* Ab = A + (size_t)m0 * HID;
    const __half* Wb = W + (size_t)n0 * HID;

    auto loadTile = [&](int kb, int s) {
        __half* sa = smh + s * STGH;
        __half* sb = sa + BM * SROW;
        const __half* Ag = Ab + kb * BK;
        const __half* Wg = Wb + kb * BK;
#pragma unroll
        for (int i = 0; i < 12; i++) {         // 3072 granules of 16B
            const int id = tid + 256 * i;
            if (id < 2048) {                   // A: 256 rows x 8 granules
                const int r = id >> 3, c = id & 7;
                uint32_t d = (uint32_t)__cvta_generic_to_shared(sa + r * SROW + c * 8);
                asm volatile("cp.async.cg.shared.global [%0], [%1], 16;"
                             :: "r"(d), "l"(Ag + (size_t)r * HID + c * 8));
            } else {                           // B: 128 rows x 8 granules
                const int id2 = id - 2048;
                const int r = id2 >> 3, c = id2 & 7;
                uint32_t d = (uint32_t)__cvta_generic_to_shared(sb + r * SROW + c * 8);
                asm volatile("cp.async.cg.shared.global [%0], [%1], 16;"
                             :: "r"(d), "l"(Wg + (size_t)r * HID + c * 8));
            }
        }
        asm volatile("cp.async.commit_group;");
    };

    loadTile(0, 0);
    loadTile(1, 1);

    int s = 0;
    for (int kb = 0; kb < NKB; kb++) {
        asm volatile("cp.async.wait_group 1;");
        __syncthreads();
        if (kb + 2 < NKB) loadTile(kb + 2, (s + 2) % 3);

        const __half* sa = smh + s * STGH;
        const __half* sb = sa + BM * SROW;

#pragma unroll
        for (int ks = 0; ks < 4; ks++) {
            const int kk = ks * 16;
            uint32_t af[4][4], bf[8][2];
#pragma unroll
            for (int mt = 0; mt < 4; mt++) {
                const int rm = wm * 64 + mt * 16 + grp;
                const __half* pa = sa + rm * SROW + kk + 2 * qid;
                af[mt][0] = *(const uint32_t*)(pa);
                af[mt][1] = *(const uint32_t*)(pa + 8 * SROW);
                af[mt][2] = *(const uint32_t*)(pa + 8);
                af[mt][3] = *(const uint32_t*)(pa + 8 * SROW + 8);
            }
#pragma unroll
            for (int nt = 0; nt < 8; nt++) {
                const int cn = wn * 64 + nt * 8 + grp;
                const __half* pb = sb + cn * SROW + kk + 2 * qid;
                bf[nt][0] = *(const uint32_t*)(pb);
                bf[nt][1] = *(const uint32_t*)(pb + 8);
            }
#pragma unroll
            for (int mt = 0; mt < 4; mt++)
#pragma unroll
                for (int nt = 0; nt < 8; nt++) {
                    asm volatile(
                        "mma.sync.aligned.m16n8k16.row.col.f32.f16.f16.f32 "
                        "{%0,%1,%2,%3}, {%4,%5,%6,%7}, {%8,%9}, {%0,%1,%2,%3};"
                        : "+f"(acc[mt][nt][0]), "+f"(acc[mt][nt][1]),
                          "+f"(acc[mt][nt][2]), "+f"(acc[mt][nt][3])
                        : "r"(af[mt][0]), "r"(af[mt][1]), "r"(af[mt][2]), "r"(af[mt][3]),
                          "r"(bf[nt][0]), "r"(bf[nt][1]));
                }
        }
        s = (s + 1) % 3;
    }

    const float sc = SCALED ? 6.103515625e-5f : 1.0f;   // 2^-14

    // epilogue
#pragma unroll
    for (int mt = 0; mt < 4; mt++) {
        const int r0 = m0 + wm * 64 + mt * 16 + grp;
#pragma unroll
        for (int nt = 0; nt < 8; nt++) {
            const int c = n0 + wn * 64 + nt * 8 + qid * 2;
            const float bv0 = bias[c], bv1 = bias[c + 1];
            float v0 = acc[mt][nt][0] * sc + bv0, v1 = acc[mt][nt][1] * sc + bv1;
            float v2 = acc[mt][nt][2] * sc + bv0, v3 = acc[mt][nt][3] * sc + bv1;
            if (RESID) {
                float2 ra = *(const float2*)(resid + (size_t)r0 * HID + c);
                float2 rb = *(const float2*)(resid + (size_t)(r0 + 8) * HID + c);
                v0 += ra.x; v1 += ra.y; v2 += rb.x; v3 += rb.y;
            }
            float2 oa = {v0, v1}, ob = {v2, v3};
            *(float2*)(C + (size_t)r0 * HID + c) = oa;
            *(float2*)(C + (size_t)(r0 + 8) * HID + c) = ob;
            if (HCOPY && isC0) {
                *(__half2*)(H0 + (size_t)r0 * HID + c) = __floats2half2_rn(v0, v1);
                *(__half2*)(H0 + (size_t)(r0 + 8) * HID + c) = __floats2half2_rn(v2, v3);
            }
        }
    }
}

// ============================================================================
// fp32 -> fp16 converter (vectorized by 4)
// ============================================================================
__global__ void f2h_kernel(const float* __restrict__ src, __half* __restrict__ dst, int n4)
{
    const int i = blockIdx.x * 256 + threadIdx.x;
    if (i >= n4) return;
    float4 v = ((const float4*)src)[i];
    ((__half2*)dst)[2 * i]     = __floats2half2_rn(v.x, v.y);
    ((__half2*)dst)[2 * i + 1] = __floats2half2_rn(v.z, v.w);
}

// ============================================================================
// Score: out[m,h] = sum_k src[m,k]*(W[h,k]*(gate?g[b,k]:1)) + bias[h]
// ============================================================================
constexpr int SCORE_ROWS = 128;

__global__ void score_kernel(const float* __restrict__ src,
                             const float* __restrict__ W,
                             const float* __restrict__ bias,
                             const float* __restrict__ gate,
                             float* __restrict__ out)
{
    extern __shared__ float sW[];  // [16][1024]
    const int row0 = blockIdx.x * SCORE_ROWS;
    const int b = row0 / SEQ;

    for (int i = threadIdx.x; i < NHEAD * HID; i += blockDim.x) {
        float w = W[i];
        if (gate) w *= gate[b * HID + (i & (HID - 1))];
        sW[i] = w;
    }
    __syncthreads();

    const int warp = threadIdx.x >> 5, lane = threadIdx.x & 31;
    for (int g = warp; g < SCORE_ROWS / 4; g += 8) {
        const int row = row0 + g * 4;
        const float* x0 = src + (size_t)row * HID;
        float p[4][NHEAD];
#pragma unroll
        for (int r = 0; r < 4; r++)
#pragma unroll
            for (int h = 0; h < NHEAD; h++) p[r][h] = 0.f;
        for (int k = lane; k < HID; k += 32) {
            float xv0 = x0[k];
            float xv1 = x0[HID + k];
            float xv2 = x0[2 * HID + k];
            float xv3 = x0[3 * HID + k];
#pragma unroll
            for (int h = 0; h < NHEAD; h++) {
                const float wv = sW[h * HID + k];
                p[0][h] += xv0 * wv; p[1][h] += xv1 * wv;
                p[2][h] += xv2 * wv; p[3][h] += xv3 * wv;
            }
        }
#pragma unroll
        for (int r = 0; r < 4; r++) {
            float vout = 0.f;
#pragma unroll
            for (int h = 0; h < NHEAD; h++) {
                float v = p[r][h];
#pragma unroll
                for (int o = 16; o; o >>= 1) v += __shfl_xor_sync(0xffffffffu, v, o);
                if (lane == h) vout = v;
            }
            if (lane < NHEAD)
                out[(size_t)(row + r) * NHEAD + lane] = vout + bias[lane];
        }
    }
}

// ============================================================================
__global__ void stats_kernel(const float* __restrict__ scores,
                             const float* __restrict__ mask, float2* __restrict__ st)
{
    __shared__ float red[256];
    const int bh = blockIdx.x, b = bh >> 4, h = bh & 15;
    const int t = threadIdx.x;
    const float* sc = scores + (size_t)b * SEQ * NHEAD + h;
    const float* mk = mask + b * SEQ;
    float mx = -1e30f;
    for (int s = t; s < SEQ; s += 256) mx = fmaxf(mx, sc[(size_t)s * NHEAD] * 0.125f + mk[s]);
    red[t] = mx; __syncthreads();
    for (int o = 128; o; o >>= 1) { if (t < o) red[t] = fmaxf(red[t], red[t + o]); __syncthreads(); }
    mx = red[0]; __syncthreads();
    float ps = 0.f;
    for (int s = t; s < SEQ; s += 256) ps += __expf(sc[(size_t)s * NHEAD] * 0.125f + mk[s] - mx);
    red[t] = ps; __syncthreads();
    for (int o = 128; o; o >>= 1) { if (t < o) red[t] += red[t + o]; __syncthreads(); }
    if (t == 0) st[bh] = make_float2(mx, red[0]);
}

__global__ void accum_kernel(const float* __restrict__ src,
                             const float* __restrict__ scores,
                             const float* __restrict__ mask,
                             const float2* __restrict__ st, float* __restrict__ part)
{
    __shared__ float red[256];
    const int blk = blockIdx.x, bh = blk >> 3, ch = blk & 7;
    const int b = bh >> 4, h = bh & 15;
    const int t = threadIdx.x, d = t & 63, sg = t >> 6;
    const float2 s2 = st[bh];
    const float mx = s2.x, inv = 1.0f / s2.y;
    const float* base = src + (size_t)b * SEQ * HID + h * 64 + d;
    const float* sc = scores + (size_t)b * SEQ * NHEAD + h;
    const float* mk = mask + b * SEQ;
    float acc = 0.f;
    const int s0 = ch * 512;
    for (int s = s0 + sg; s < s0 + 512; s += 4) {
        float w = __expf(sc[(size_t)s * NHEAD] * 0.125f + mk[s] - mx);
        acc += w * base[(size_t)s * HID];
    }
    red[t] = acc; __syncthreads();
    if (sg == 0)
        part[(size_t)blk * 64 + d] = (red[d] + red[64 + d] + red[128 + d] + red[192 + d]) * inv;
}

__global__ void finalize_kernel(const float* __restrict__ part,
                                const float* __restrict__ postgate, float* __restrict__ out)
{
    const int idx = blockIdx.x * 256 + threadIdx.x;   // 8192
    const int bh = idx >> 6, d = idx & 63;
    float v = 0.f;
#pragma unroll
    for (int c = 0; c < 8; c++) v += part[(size_t)(bh * 8 + c) * 64 + d];
    if (postgate) v *= postgate[idx];
    out[idx] = v;
}

// wtgh[b,n,k] = (half)(Wt[n,k] * pk[b,k] * 2^14)   (scale avoids fp16 subnormals)
__global__ void wtg_kernel(const float* __restrict__ Wt, const float* __restrict__ pk,
                           __half* __restrict__ wtgh)
{
    const size_t i4 = (size_t)blockIdx.x * 256 + threadIdx.x;  // 2,097,152
    const int j4 = (int)(i4 & 255);
    const int n  = (int)((i4 >> 8) & 1023);
    const int b  = (int)(i4 >> 18);
    float4 w = ((const float4*)Wt)[n * 256 + j4];
    float4 g = ((const float4*)pk)[b * 256 + j4];
    const float S = 16384.0f;
    __half2 h0 = __floats2half2_rn(w.x * g.x * S, w.y * g.y * S);
    __half2 h1 = __floats2half2_rn(w.z * g.z * S, w.w * g.w * S);
    ((__half2*)wtgh)[2 * i4]     = h0;
    ((__half2*)wtgh)[2 * i4 + 1] = h1;
}

// ============================================================================
extern "C" void kernel_launch(void* const* d_in, const int* in_sizes, int n_in,
                              void* d_out, int out_size)
{
    const float* X    = (const float*)d_in[0];
    const float* mask = (const float*)d_in[1];
    const float* Wq   = (const float*)d_in[2];
    const float* bq   = (const float*)d_in[3];
    const float* Wqa  = (const float*)d_in[4];
    const float* bqa  = (const float*)d_in[5];
    const float* Wk   = (const float*)d_in[6];
    const float* bk   = (const float*)d_in[7];
    const float* Wka  = (const float*)d_in[8];
    const float* bka  = (const float*)d_in[9];
    const float* Wt   = (const float*)d_in[10];
    const float* bt   = (const float*)d_in[11];
    float* out = (float*)d_out;

    float *mq, *mk, *qs, *ks, *pq, *pk, *part;
    float2 *stq, *stk;
    __half *xh, *mqh, *wqh, *wkh, *wtgh;
    cudaGetSymbolAddress((void**)&mq, g_mq);
    cudaGetSymbolAddress((void**)&mk, g_mk);
    cudaGetSymbolAddress((void**)&qs, g_qs);
    cudaGetSymbolAddress((void**)&ks, g_ks);
    cudaGetSymbolAddress((void**)&pq, g_pq);
    cudaGetSymbolAddress((void**)&pk, g_pk);
    cudaGetSymbolAddress((void**)&part, g_part);
    cudaGetSymbolAddress((void**)&stq, g_stq);
    cudaGetSymbolAddress((void**)&stk, g_stk);
    cudaGetSymbolAddress((void**)&xh, g_xh);
    cudaGetSymbolAddress((void**)&mqh, g_mqh);
    cudaGetSymbolAddress((void**)&wqh, g_wqh);
    cudaGetSymbolAddress((void**)&wkh, g_wkh);
    cudaGetSymbolAddress((void**)&wtgh, g_wtgh);

    cudaFuncSetAttribute(gemm_fp16<true, false, false, true, false>,
                         cudaFuncAttributeMaxDynamicSharedMemorySize, (int)GEMM_SMEM);
    cudaFuncSetAttribute(gemm_fp16<false, true, true, false, true>,
                         cudaFuncAttributeMaxDynamicSharedMemorySize, (int)GEMM_SMEM);
    const size_t score_smem = (size_t)NHEAD * HID * sizeof(float);
    cudaFuncSetAttribute(score_kernel,
                         cudaFuncAttributeMaxDynamicSharedMemorySize, (int)score_smem);

    const __half* nullh = nullptr;
    const float*  nullf = nullptr;

    // 0) fp16 conversions
    f2h_kernel<<<(MROWS * HID / 4 + 255) / 256, 256>>>(X, xh, MROWS * HID / 4);
    f2h_kernel<<<(HID * HID / 4 + 255) / 256, 256>>>(Wq, wqh, HID * HID / 4);
    f2h_kernel<<<(HID * HID / 4 + 255) / 256, 256>>>(Wk, wkh, HID * HID / 4);

    // 1) fused: mq = X@Wq^T + bq (also fp16 copy) ; mk = X@Wk^T + bk
    gemm_fp16<true, false, false, true, false><<<dim3(16, MROWS / BM), 256, GEMM_SMEM>>>(
        xh, wqh, wkh, bq, bk, nullf, mq, mk, mqh);

    // 2) q scores -> pooled_q
    score_kernel<<<MROWS / SCORE_ROWS, 256, score_smem>>>(mq, Wqa, bqa, nullf, qs);
    stats_kernel<<<BATCH * NHEAD, 256>>>(qs, mask, stq);
    accum_kernel<<<BATCH * NHEAD * 8, 256>>>(mq, qs, mask, stq, part);
    finalize_kernel<<<BATCH * HID / 256, 256>>>(part, nullf, pq);

    // 3) qk scores (gate folded into Wka) -> pooled_k (post-gate pq)
    score_kernel<<<MROWS / SCORE_ROWS, 256, score_smem>>>(mk, Wka, bka, pq, ks);
    stats_kernel<<<BATCH * NHEAD, 256>>>(ks, mask, stk);
    accum_kernel<<<BATCH * NHEAD * 8, 256>>>(mk, ks, mask, stk, part);
    finalize_kernel<<<BATCH * HID / 256, 256>>>(part, pq, pk);

    // 4) wtgh = Wt * pk_full[b] * 2^14 ; out = mqh @ wtgh[b]^T * 2^-14 + bt + mq
    wtg_kernel<<<(BATCH * HID * HID / 4) / 256, 256>>>(Wt, pk, wtgh);
    gemm_fp16<false, true, true, false, true><<<dim3(8, MROWS / BM), 256, GEMM_SMEM>>>(
        mqh, wtgh, nullh, bt, nullf, mq, out, (float*)nullptr, (__half*)nullptr);
}

// round 7
// speedup vs baseline: 2.0350x; 1.0085x over previous
#include <cuda_runtime.h>
#include <cuda_fp16.h>
#include <cstdint>
#include <cstddef>

#define BATCH 8
#define SEQ   4096
#define HID   1024
#define NHEAD 16
#define MROWS (BATCH * SEQ)   // 32768

// ---------------- scratch (device globals; allocations forbidden) ----------
__device__ float  g_mq[(size_t)MROWS * HID];
__device__ float  g_mk[(size_t)MROWS * HID];
__device__ __half g_xh[(size_t)MROWS * HID];
__device__ __half g_mqh[(size_t)MROWS * HID];
__device__ __half g_wqh[(size_t)HID * HID];
__device__ __half g_wkh[(size_t)HID * HID];
__device__ __half g_wtgh[(size_t)BATCH * HID * HID];
__device__ float  g_qs[(size_t)MROWS * NHEAD];
__device__ float  g_ks[(size_t)MROWS * NHEAD];
__device__ float  g_pq[BATCH * HID];
__device__ float  g_pk[BATCH * HID];
__device__ float2 g_stq[BATCH * NHEAD];
__device__ float2 g_stk[BATCH * NHEAD];
__device__ float  g_part[BATCH * NHEAD * 8 * 64];

// ============================================================================
// fp16 GEMM: C[m,n] = sum_k A[m,k]*W[n,k] (+bias[n]) (+resid) [*2^-14 if SCALED]
// BM=256, BN=128, BK=64 halves; 256 thr; 3-stage cp.async; mma m16n8k16 f16.
// Operand loads via ldmatrix.m8n8.x4 (conflict-free on 144B row stride).
// DUAL: grid.x=16, nb<8 -> (W0,b0,C0[,H0]), else (W1,b1,C1).
// PERB: W indexed per batch. HCOPY: also emit fp16 copy of C0.
// ============================================================================
constexpr int BM = 256, BN = 128, BK = 64;
constexpr int SROW = 72;                      // halves per smem row (144B, padded)
constexpr int NKB = HID / BK;                 // 16
constexpr int STGH = (BM + BN) * SROW;        // 27648 halves per stage
constexpr size_t GEMM_SMEM = (size_t)3 * STGH * sizeof(__half);  // 165888 B

#define LDSM_X4(r0, r1, r2, r3, addr)                                             \
    asm volatile("ldmatrix.sync.aligned.m8n8.x4.shared.b16 {%0,%1,%2,%3}, [%4];"  \
                 : "=r"(r0), "=r"(r1), "=r"(r2), "=r"(r3) : "r"(addr))

template <bool DUAL, bool RESID, bool PERB, bool HCOPY, bool SCALED>
__global__ void __launch_bounds__(256, 1) gemm_fp16(
    const __half* __restrict__ A, const __half* __restrict__ W0, const __half* __restrict__ W1,
    const float* __restrict__ b0, const float* __restrict__ b1,
    const float* __restrict__ resid, float* __restrict__ C0, float* __restrict__ C1,
    __half* __restrict__ H0)
{
    extern __shared__ __half smh[];
    const int tid = threadIdx.x;
    const int m0 = blockIdx.y * BM;
    int nb = blockIdx.x;

    const __half* W; const float* bias; float* C;
    bool isC0 = true;
    if (DUAL) {
        if (nb < 8) { W = W0; bias = b0; C = C0; }
        else        { nb -= 8; W = W1; bias = b1; C = C1; isC0 = false; }
    } else {
        W = W0 + (PERB ? (size_t)(m0 / SEQ) * HID * HID : 0);
        bias = b0; C = C0;
    }
    const int n0 = nb * BN;

    const int warp = tid >> 5, lane = tid & 31;
    const int wm = warp & 3, wn = warp >> 2;    // 4x2 warps -> 64x64 per warp
    const int grp = lane >> 2, qid = lane & 3;

    // ldmatrix per-lane address components
    const int lr = lane & 7;            // row within 8x8 matrix
    const int lh = (lane >> 3) & 1;     // matrix pair selector (rows+8 for A / k+8 for B)
    const int lk = (lane >> 4) & 1;     // k+8 for A / rows+8 for B

    // byte offsets within a stage for each mt / nt-pair
    uint32_t offA[4], offB[4];
#pragma unroll
    for (int mt = 0; mt < 4; mt++)
        offA[mt] = (uint32_t)(((wm * 64 + mt * 16 + lh * 8 + lr) * SROW + lk * 8) * 2);
#pragma unroll
    for (int p = 0; p < 4; p++)
        offB[p] = (uint32_t)(((wn * 64 + p * 16 + lk * 8 + lr) * SROW + lh * 8) * 2
                             + BM * SROW * 2);

    const uint32_t smBase = (uint32_t)__cvta_generic_to_shared(smh);

    float acc[4][8][4];
#pragma unroll
    for (int i = 0; i < 4; i++)
#pragma unroll
        for (int j = 0; j < 8; j++)
#pragma unroll
            for (int l = 0; l < 4; l++) acc[i][j][l] = 0.f;

    const __half* Ab = A + (size_t)m0 * HID;
    const __half* Wb = W + (size_t)n0 * HID;

    auto loadTile = [&](int kb, int s) {
        __half* sa = smh + s * STGH;
        __half* sb = sa + BM * SROW;
        const __half* Ag = Ab + kb * BK;
        const __half* Wg = Wb + kb * BK;
#pragma unroll
        for (int i = 0; i < 12; i++) {         // 3072 granules of 16B
            const int id = tid + 256 * i;
            if (id < 2048) {                   // A: 256 rows x 8 granules
                const int r = id >> 3, c = id & 7;
                uint32_t d = (uint32_t)__cvta_generic_to_shared(sa + r * SROW + c * 8);
                asm volatile("cp.async.cg.shared.global [%0], [%1], 16;"
                             :: "r"(d), "l"(Ag + (size_t)r * HID + c * 8));
            } else {                           // B: 128 rows x 8 granules
                const int id2 = id - 2048;
                const int r = id2 >> 3, c = id2 & 7;
                uint32_t d = (uint32_t)__cvta_generic_to_shared(sb + r * SROW + c * 8);
                asm volatile("cp.async.cg.shared.global [%0], [%1], 16;"
                             :: "r"(d), "l"(Wg + (size_t)r * HID + c * 8));
            }
        }
        asm volatile("cp.async.commit_group;");
    };

    loadTile(0, 0);
    loadTile(1, 1);

    int s = 0;
    for (int kb = 0; kb < NKB; kb++) {
        asm volatile("cp.async.wait_group 1;");
        __syncthreads();
        if (kb + 2 < NKB) loadTile(kb + 2, (s + 2) % 3);

        const uint32_t stBase = smBase + s * (STGH * 2);

#pragma unroll
        for (int ks = 0; ks < 4; ks++) {
            const uint32_t kkb = ks * 32;      // kk halves * 2 bytes
            uint32_t af[4][4], bf[8][2];
#pragma unroll
            for (int mt = 0; mt < 4; mt++)
                LDSM_X4(af[mt][0], af[mt][1], af[mt][2], af[mt][3],
                        stBase + offA[mt] + kkb);
#pragma unroll
            for (int p = 0; p < 4; p++)
                LDSM_X4(bf[2 * p][0], bf[2 * p][1], bf[2 * p + 1][0], bf[2 * p + 1][1],
                        stBase + offB[p] + kkb);
#pragma unroll
            for (int mt = 0; mt < 4; mt++)
#pragma unroll
                for (int nt = 0; nt < 8; nt++) {
                    asm volatile(
                        "mma.sync.aligned.m16n8k16.row.col.f32.f16.f16.f32 "
                        "{%0,%1,%2,%3}, {%4,%5,%6,%7}, {%8,%9}, {%0,%1,%2,%3};"
                        : "+f"(acc[mt][nt][0]), "+f"(acc[mt][nt][1]),
                          "+f"(acc[mt][nt][2]), "+f"(acc[mt][nt][3])
                        : "r"(af[mt][0]), "r"(af[mt][1]), "r"(af[mt][2]), "r"(af[mt][3]),
                          "r"(bf[nt][0]), "r"(bf[nt][1]));
                }
        }
        s = (s + 1) % 3;
    }

    const float sc = SCALED ? 6.103515625e-5f : 1.0f;   // 2^-14

    // epilogue
#pragma unroll
    for (int mt = 0; mt < 4; mt++) {
        const int r0 = m0 + wm * 64 + mt * 16 + grp;
#pragma unroll
        for (int nt = 0; nt < 8; nt++) {
            const int c = n0 + wn * 64 + nt * 8 + qid * 2;
            const float bv0 = bias[c], bv1 = bias[c + 1];
            float v0 = acc[mt][nt][0] * sc + bv0, v1 = acc[mt][nt][1] * sc + bv1;
            float v2 = acc[mt][nt][2] * sc + bv0, v3 = acc[mt][nt][3] * sc + bv1;
            if (RESID) {
                float2 ra = *(const float2*)(resid + (size_t)r0 * HID + c);
                float2 rb = *(const float2*)(resid + (size_t)(r0 + 8) * HID + c);
                v0 += ra.x; v1 += ra.y; v2 += rb.x; v3 += rb.y;
            }
            float2 oa = {v0, v1}, ob = {v2, v3};
            *(float2*)(C + (size_t)r0 * HID + c) = oa;
            *(float2*)(C + (size_t)(r0 + 8) * HID + c) = ob;
            if (HCOPY && isC0) {
                *(__half2*)(H0 + (size_t)r0 * HID + c) = __floats2half2_rn(v0, v1);
                *(__half2*)(H0 + (size_t)(r0 + 8) * HID + c) = __floats2half2_rn(v2, v3);
            }
        }
    }
}

// ============================================================================
// fp32 -> fp16 converter (vectorized by 4)
// ============================================================================
__global__ void f2h_kernel(const float* __restrict__ src, __half* __restrict__ dst, int n4)
{
    const int i = blockIdx.x * 256 + threadIdx.x;
    if (i >= n4) return;
    float4 v = ((const float4*)src)[i];
    ((__half2*)dst)[2 * i]     = __floats2half2_rn(v.x, v.y);
    ((__half2*)dst)[2 * i + 1] = __floats2half2_rn(v.z, v.w);
}

// ============================================================================
// Score: out[m,h] = sum_k src[m,k]*(W[h,k]*(gate?g[b,k]:1)) + bias[h]
// ============================================================================
constexpr int SCORE_ROWS = 128;

__global__ void score_kernel(const float* __restrict__ src,
                             const float* __restrict__ W,
                             const float* __restrict__ bias,
                             const float* __restrict__ gate,
                             float* __restrict__ out)
{
    extern __shared__ float sW[];  // [16][1024]
    const int row0 = blockIdx.x * SCORE_ROWS;
    const int b = row0 / SEQ;

    for (int i = threadIdx.x; i < NHEAD * HID; i += blockDim.x) {
        float w = W[i];
        if (gate) w *= gate[b * HID + (i & (HID - 1))];
        sW[i] = w;
    }
    __syncthreads();

    const int warp = threadIdx.x >> 5, lane = threadIdx.x & 31;
    for (int g = warp; g < SCORE_ROWS / 4; g += 8) {
        const int row = row0 + g * 4;
        const float* x0 = src + (size_t)row * HID;
        float p[4][NHEAD];
#pragma unroll
        for (int r = 0; r < 4; r++)
#pragma unroll
            for (int h = 0; h < NHEAD; h++) p[r][h] = 0.f;
        for (int k = lane; k < HID; k += 32) {
            float xv0 = x0[k];
            float xv1 = x0[HID + k];
            float xv2 = x0[2 * HID + k];
            float xv3 = x0[3 * HID + k];
#pragma unroll
            for (int h = 0; h < NHEAD; h++) {
                const float wv = sW[h * HID + k];
                p[0][h] += xv0 * wv; p[1][h] += xv1 * wv;
                p[2][h] += xv2 * wv; p[3][h] += xv3 * wv;
            }
        }
#pragma unroll
        for (int r = 0; r < 4; r++) {
            float vout = 0.f;
#pragma unroll
            for (int h = 0; h < NHEAD; h++) {
                float v = p[r][h];
#pragma unroll
                for (int o = 16; o; o >>= 1) v += __shfl_xor_sync(0xffffffffu, v, o);
                if (lane == h) vout = v;
            }
            if (lane < NHEAD)
                out[(size_t)(row + r) * NHEAD + lane] = vout + bias[lane];
        }
    }
}

// ============================================================================
__global__ void stats_kernel(const float* __restrict__ scores,
                             const float* __restrict__ mask, float2* __restrict__ st)
{
    __shared__ float red[256];
    const int bh = blockIdx.x, b = bh >> 4, h = bh & 15;
    const int t = threadIdx.x;
    const float* sc = scores + (size_t)b * SEQ * NHEAD + h;
    const float* mk = mask + b * SEQ;
    float mx = -1e30f;
    for (int s = t; s < SEQ; s += 256) mx = fmaxf(mx, sc[(size_t)s * NHEAD] * 0.125f + mk[s]);
    red[t] = mx; __syncthreads();
    for (int o = 128; o; o >>= 1) { if (t < o) red[t] = fmaxf(red[t], red[t + o]); __syncthreads(); }
    mx = red[0]; __syncthreads();
    float ps = 0.f;
    for (int s = t; s < SEQ; s += 256) ps += __expf(sc[(size_t)s * NHEAD] * 0.125f + mk[s] - mx);
    red[t] = ps; __syncthreads();
    for (int o = 128; o; o >>= 1) { if (t < o) red[t] += red[t + o]; __syncthreads(); }
    if (t == 0) st[bh] = make_float2(mx, red[0]);
}

__global__ void accum_kernel(const float* __restrict__ src,
                             const float* __restrict__ scores,
                             const float* __restrict__ mask,
                             const float2* __restrict__ st, float* __restrict__ part)
{
    __shared__ float red[256];
    const int blk = blockIdx.x, bh = blk >> 3, ch = blk & 7;
    const int b = bh >> 4, h = bh & 15;
    const int t = threadIdx.x, d = t & 63, sg = t >> 6;
    const float2 s2 = st[bh];
    const float mx = s2.x, inv = 1.0f / s2.y;
    const float* base = src + (size_t)b * SEQ * HID + h * 64 + d;
    const float* sc = scores + (size_t)b * SEQ * NHEAD + h;
    const float* mk = mask + b * SEQ;
    float acc = 0.f;
    const int s0 = ch * 512;
    for (int s = s0 + sg; s < s0 + 512; s += 4) {
        float w = __expf(sc[(size_t)s * NHEAD] * 0.125f + mk[s] - mx);
        acc += w * base[(size_t)s * HID];
    }
    red[t] = acc; __syncthreads();
    if (sg == 0)
        part[(size_t)blk * 64 + d] = (red[d] + red[64 + d] + red[128 + d] + red[192 + d]) * inv;
}

__global__ void finalize_kernel(const float* __restrict__ part,
                                const float* __restrict__ postgate, float* __restrict__ out)
{
    const int idx = blockIdx.x * 256 + threadIdx.x;   // 8192
    const int bh = idx >> 6, d = idx & 63;
    float v = 0.f;
#pragma unroll
    for (int c = 0; c < 8; c++) v += part[(size_t)(bh * 8 + c) * 64 + d];
    if (postgate) v *= postgate[idx];
    out[idx] = v;
}

// wtgh[b,n,k] = (half)(Wt[n,k] * pk[b,k] * 2^14)   (scale avoids fp16 subnormals)
__global__ void wtg_kernel(const float* __restrict__ Wt, const float* __restrict__ pk,
                           __half* __restrict__ wtgh)
{
    const size_t i4 = (size_t)blockIdx.x * 256 + threadIdx.x;  // 2,097,152
    const int j4 = (int)(i4 & 255);
    const int n  = (int)((i4 >> 8) & 1023);
    const int b  = (int)(i4 >> 18);
    float4 w = ((const float4*)Wt)[n * 256 + j4];
    float4 g = ((const float4*)pk)[b * 256 + j4];
    const float S = 16384.0f;
    __half2 h0 = __floats2half2_rn(w.x * g.x * S, w.y * g.y * S);
    __half2 h1 = __floats2half2_rn(w.z * g.z * S, w.w * g.w * S);
    ((__half2*)wtgh)[2 * i4]     = h0;
    ((__half2*)wtgh)[2 * i4 + 1] = h1;
}

// ============================================================================
extern "C" void kernel_launch(void* const* d_in, const int* in_sizes, int n_in,
                              void* d_out, int out_size)
{
    const float* X    = (const float*)d_in[0];
    const float* mask = (const float*)d_in[1];
    const float* Wq   = (const float*)d_in[2];
    const float* bq   = (const float*)d_in[3];
    const float* Wqa  = (const float*)d_in[4];
    const float* bqa  = (const float*)d_in[5];
    const float* Wk   = (const float*)d_in[6];
    const float* bk   = (const float*)d_in[7];
    const float* Wka  = (const float*)d_in[8];
    const float* bka  = (const float*)d_in[9];
    const float* Wt   = (const float*)d_in[10];
    const float* bt   = (const float*)d_in[11];
    float* out = (float*)d_out;

    float *mq, *mk, *qs, *ks, *pq, *pk, *part;
    float2 *stq, *stk;
    __half *xh, *mqh, *wqh, *wkh, *wtgh;
    cudaGetSymbolAddress((void**)&mq, g_mq);
    cudaGetSymbolAddress((void**)&mk, g_mk);
    cudaGetSymbolAddress((void**)&qs, g_qs);
    cudaGetSymbolAddress((void**)&ks, g_ks);
    cudaGetSymbolAddress((void**)&pq, g_pq);
    cudaGetSymbolAddress((void**)&pk, g_pk);
    cudaGetSymbolAddress((void**)&part, g_part);
    cudaGetSymbolAddress((void**)&stq, g_stq);
    cudaGetSymbolAddress((void**)&stk, g_stk);
    cudaGetSymbolAddress((void**)&xh, g_xh);
    cudaGetSymbolAddress((void**)&mqh, g_mqh);
    cudaGetSymbolAddress((void**)&wqh, g_wqh);
    cudaGetSymbolAddress((void**)&wkh, g_wkh);
    cudaGetSymbolAddress((void**)&wtgh, g_wtgh);

    cudaFuncSetAttribute(gemm_fp16<true, false, false, true, false>,
                         cudaFuncAttributeMaxDynamicSharedMemorySize, (int)GEMM_SMEM);
    cudaFuncSetAttribute(gemm_fp16<false, true, true, false, true>,
                         cudaFuncAttributeMaxDynamicSharedMemorySize, (int)GEMM_SMEM);
    const size_t score_smem = (size_t)NHEAD * HID * sizeof(float);
    cudaFuncSetAttribute(score_kernel,
                         cudaFuncAttributeMaxDynamicSharedMemorySize, (int)score_smem);

    const __half* nullh = nullptr;
    const float*  nullf = nullptr;

    // 0) fp16 conversions
    f2h_kernel<<<(MROWS * HID / 4 + 255) / 256, 256>>>(X, xh, MROWS * HID / 4);
    f2h_kernel<<<(HID * HID / 4 + 255) / 256, 256>>>(Wq, wqh, HID * HID / 4);
    f2h_kernel<<<(HID * HID / 4 + 255) / 256, 256>>>(Wk, wkh, HID * HID / 4);

    // 1) fused: mq = X@Wq^T + bq (also fp16 copy) ; mk = X@Wk^T + bk
    gemm_fp16<true, false, false, true, false><<<dim3(16, MROWS / BM), 256, GEMM_SMEM>>>(
        xh, wqh, wkh, bq, bk, nullf, mq, mk, mqh);

    // 2) q scores -> pooled_q
    score_kernel<<<MROWS / SCORE_ROWS, 256, score_smem>>>(mq, Wqa, bqa, nullf, qs);
    stats_kernel<<<BATCH * NHEAD, 256>>>(qs, mask, stq);
    accum_kernel<<<BATCH * NHEAD * 8, 256>>>(mq, qs, mask, stq, part);
    finalize_kernel<<<BATCH * HID / 256, 256>>>(part, nullf, pq);

    // 3) qk scores (gate folded into Wka) -> pooled_k (post-gate pq)
    score_kernel<<<MROWS / SCORE_ROWS, 256, score_smem>>>(mk, Wka, bka, pq, ks);
    stats_kernel<<<BATCH * NHEAD, 256>>>(ks, mask, stk);
    accum_kernel<<<BATCH * NHEAD * 8, 256>>>(mk, ks, mask, stk, part);
    finalize_kernel<<<BATCH * HID / 256, 256>>>(part, pq, pk);

    // 4) wtgh = Wt * pk_full[b] * 2^14 ; out = mqh @ wtgh[b]^T * 2^-14 + bt + mq
    wtg_kernel<<<(BATCH * HID * HID / 4) / 256, 256>>>(Wt, pk, wtgh);
    gemm_fp16<false, true, true, false, true><<<dim3(8, MROWS / BM), 256, GEMM_SMEM>>>(
        mqh, wtgh, nullh, bt, nullf, mq, out, (float*)nullptr, (__half*)nullptr);
}

// round 8
// speedup vs baseline: 2.1648x; 1.0638x over previous
#include <cuda_runtime.h>
#include <cuda_fp16.h>
#include <cstdint>
#include <cstddef>

#define BATCH 8
#define SEQ   4096
#define HID   1024
#define NHEAD 16
#define MROWS (BATCH * SEQ)   // 32768

// ---------------- scratch (device globals; allocations forbidden) ----------
__device__ float  g_mq[(size_t)MROWS * HID];
__device__ float  g_mk[(size_t)MROWS * HID];
__device__ __half g_xh[(size_t)MROWS * HID];
__device__ __half g_mqh[(size_t)MROWS * HID];
__device__ __half g_wqh[(size_t)HID * HID];
__device__ __half g_wkh[(size_t)HID * HID];
__device__ __half g_wtgh[(size_t)BATCH * HID * HID];
__device__ float  g_qs[(size_t)MROWS * NHEAD];
__device__ float  g_ks[(size_t)MROWS * NHEAD];
__device__ float  g_pq[BATCH * HID];
__device__ float  g_pk[BATCH * HID];
__device__ float2 g_stq[BATCH * NHEAD];
__device__ float2 g_stk[BATCH * NHEAD];
__device__ float  g_part[BATCH * NHEAD * 8 * 64];

// ============================================================================
// fp16 GEMM: C[m,n] = sum_k A[m,k]*W[n,k] (+bias[n]) (+resid) [*2^-14 if SCALED]
// BM=128, BN=128, BK=64; 256 thr; 3-stage cp.async; mma m16n8k16; ldmatrix.x4.
// 2 CTAs/SM (110.6KB smem, <=128 regs) for latency hiding.
// DUAL: grid.x=16, nb<8 -> (W0,b0,C0[,H0]), else (W1,b1,C1).
// PERB: W indexed per batch. HCOPY: also emit fp16 copy of C0.
// ============================================================================
constexpr int BM = 128, BN = 128, BK = 64;
constexpr int SROW = 72;                      // halves per smem row (144B, padded)
constexpr int NKB = HID / BK;                 // 16
constexpr int STGH = (BM + BN) * SROW;        // 18432 halves per stage
constexpr size_t GEMM_SMEM = (size_t)3 * STGH * sizeof(__half);  // 110592 B

#define LDSM_X4(r0, r1, r2, r3, addr)                                             \
    asm volatile("ldmatrix.sync.aligned.m8n8.x4.shared.b16 {%0,%1,%2,%3}, [%4];"  \
                 : "=r"(r0), "=r"(r1), "=r"(r2), "=r"(r3) : "r"(addr))

template <bool DUAL, bool RESID, bool PERB, bool HCOPY, bool SCALED>
__global__ void __launch_bounds__(256, 2) gemm_fp16(
    const __half* __restrict__ A, const __half* __restrict__ W0, const __half* __restrict__ W1,
    const float* __restrict__ b0, const float* __restrict__ b1,
    const float* __restrict__ resid, float* __restrict__ C0, float* __restrict__ C1,
    __half* __restrict__ H0)
{
    extern __shared__ __half smh[];
    const int tid = threadIdx.x;
    const int m0 = blockIdx.y * BM;
    int nb = blockIdx.x;

    const __half* W; const float* bias; float* C;
    bool isC0 = true;
    if (DUAL) {
        if (nb < 8) { W = W0; bias = b0; C = C0; }
        else        { nb -= 8; W = W1; bias = b1; C = C1; isC0 = false; }
    } else {
        W = W0 + (PERB ? (size_t)(m0 / SEQ) * HID * HID : 0);
        bias = b0; C = C0;
    }
    const int n0 = nb * BN;

    const int warp = tid >> 5, lane = tid & 31;
    const int wm = warp & 3, wn = warp >> 2;    // 4x2 warps -> 32x64 per warp
    const int grp = lane >> 2, qid = lane & 3;

    // ldmatrix per-lane address components
    const int lr = lane & 7;
    const int lh = (lane >> 3) & 1;
    const int lk = (lane >> 4) & 1;

    uint32_t offA[2], offB[4];
#pragma unroll
    for (int mt = 0; mt < 2; mt++)
        offA[mt] = (uint32_t)(((wm * 32 + mt * 16 + lh * 8 + lr) * SROW + lk * 8) * 2);
#pragma unroll
    for (int p = 0; p < 4; p++)
        offB[p] = (uint32_t)(((wn * 64 + p * 16 + lk * 8 + lr) * SROW + lh * 8) * 2
                             + BM * SROW * 2);

    const uint32_t smBase = (uint32_t)__cvta_generic_to_shared(smh);

    float acc[2][8][4];
#pragma unroll
    for (int i = 0; i < 2; i++)
#pragma unroll
        for (int j = 0; j < 8; j++)
#pragma unroll
            for (int l = 0; l < 4; l++) acc[i][j][l] = 0.f;

    const __half* Ab = A + (size_t)m0 * HID;
    const __half* Wb = W + (size_t)n0 * HID;

    auto loadTile = [&](int kb, int s) {
        __half* sa = smh + s * STGH;
        __half* sb = sa + BM * SROW;
        const __half* Ag = Ab + kb * BK;
        const __half* Wg = Wb + kb * BK;
#pragma unroll
        for (int i = 0; i < 8; i++) {          // 2048 granules of 16B
            const int id = tid + 256 * i;
            if (id < 1024) {                   // A: 128 rows x 8 granules
                const int r = id >> 3, c = id & 7;
                uint32_t d = (uint32_t)__cvta_generic_to_shared(sa + r * SROW + c * 8);
                asm volatile("cp.async.cg.shared.global [%0], [%1], 16;"
                             :: "r"(d), "l"(Ag + (size_t)r * HID + c * 8));
            } else {                           // B: 128 rows x 8 granules
                const int id2 = id - 1024;
                const int r = id2 >> 3, c = id2 & 7;
                uint32_t d = (uint32_t)__cvta_generic_to_shared(sb + r * SROW + c * 8);
                asm volatile("cp.async.cg.shared.global [%0], [%1], 16;"
                             :: "r"(d), "l"(Wg + (size_t)r * HID + c * 8));
            }
        }
        asm volatile("cp.async.commit_group;");
    };

    loadTile(0, 0);
    loadTile(1, 1);

    int s = 0;
    for (int kb = 0; kb < NKB; kb++) {
        asm volatile("cp.async.wait_group 1;");
        __syncthreads();
        if (kb + 2 < NKB) loadTile(kb + 2, (s + 2) % 3);

        const uint32_t stBase = smBase + s * (STGH * 2);

#pragma unroll
        for (int ks = 0; ks < 4; ks++) {
            const uint32_t kkb = ks * 32;
            uint32_t af[2][4], bf[8][2];
#pragma unroll
            for (int mt = 0; mt < 2; mt++)
                LDSM_X4(af[mt][0], af[mt][1], af[mt][2], af[mt][3],
                        stBase + offA[mt] + kkb);
#pragma unroll
            for (int p = 0; p < 4; p++)
                LDSM_X4(bf[2 * p][0], bf[2 * p][1], bf[2 * p + 1][0], bf[2 * p + 1][1],
                        stBase + offB[p] + kkb);
#pragma unroll
            for (int mt = 0; mt < 2; mt++)
#pragma unroll
                for (int nt = 0; nt < 8; nt++) {
                    asm volatile(
                        "mma.sync.aligned.m16n8k16.row.col.f32.f16.f16.f32 "
                        "{%0,%1,%2,%3}, {%4,%5,%6,%7}, {%8,%9}, {%0,%1,%2,%3};"
                        : "+f"(acc[mt][nt][0]), "+f"(acc[mt][nt][1]),
                          "+f"(acc[mt][nt][2]), "+f"(acc[mt][nt][3])
                        : "r"(af[mt][0]), "r"(af[mt][1]), "r"(af[mt][2]), "r"(af[mt][3]),
                          "r"(bf[nt][0]), "r"(bf[nt][1]));
                }
        }
        s = (s + 1) % 3;
    }

    const float sc = SCALED ? 6.103515625e-5f : 1.0f;   // 2^-14

    // epilogue
#pragma unroll
    for (int mt = 0; mt < 2; mt++) {
        const int r0 = m0 + wm * 32 + mt * 16 + grp;
#pragma unroll
        for (int nt = 0; nt < 8; nt++) {
            const int c = n0 + wn * 64 + nt * 8 + qid * 2;
            const float bv0 = bias[c], bv1 = bias[c + 1];
            float v0 = acc[mt][nt][0] * sc + bv0, v1 = acc[mt][nt][1] * sc + bv1;
            float v2 = acc[mt][nt][2] * sc + bv0, v3 = acc[mt][nt][3] * sc + bv1;
            if (RESID) {
                float2 ra = *(const float2*)(resid + (size_t)r0 * HID + c);
                float2 rb = *(const float2*)(resid + (size_t)(r0 + 8) * HID + c);
                v0 += ra.x; v1 += ra.y; v2 += rb.x; v3 += rb.y;
            }
            float2 oa = {v0, v1}, ob = {v2, v3};
            *(float2*)(C + (size_t)r0 * HID + c) = oa;
            *(float2*)(C + (size_t)(r0 + 8) * HID + c) = ob;
            if (HCOPY && isC0) {
                *(__half2*)(H0 + (size_t)r0 * HID + c) = __floats2half2_rn(v0, v1);
                *(__half2*)(H0 + (size_t)(r0 + 8) * HID + c) = __floats2half2_rn(v2, v3);
            }
        }
    }
}

// ============================================================================
// fp32 -> fp16 converter (vectorized by 4)
// ============================================================================
__global__ void f2h_kernel(const float* __restrict__ src, __half* __restrict__ dst, int n4)
{
    const int i = blockIdx.x * 256 + threadIdx.x;
    if (i >= n4) return;
    float4 v = ((const float4*)src)[i];
    ((__half2*)dst)[2 * i]     = __floats2half2_rn(v.x, v.y);
    ((__half2*)dst)[2 * i + 1] = __floats2half2_rn(v.z, v.w);
}

// ============================================================================
// Score: out[m,h] = sum_k src[m,k]*(W[h,k]*(gate?g[b,k]:1)) + bias[h]
// ============================================================================
constexpr int SCORE_ROWS = 128;

__global__ void score_kernel(const float* __restrict__ src,
                             const float* __restrict__ W,
                             const float* __restrict__ bias,
                             const float* __restrict__ gate,
                             float* __restrict__ out)
{
    extern __shared__ float sW[];  // [16][1024]
    const int row0 = blockIdx.x * SCORE_ROWS;
    const int b = row0 / SEQ;

    for (int i = threadIdx.x; i < NHEAD * HID; i += blockDim.x) {
        float w = W[i];
        if (gate) w *= gate[b * HID + (i & (HID - 1))];
        sW[i] = w;
    }
    __syncthreads();

    const int warp = threadIdx.x >> 5, lane = threadIdx.x & 31;
    for (int g = warp; g < SCORE_ROWS / 4; g += 8) {
        const int row = row0 + g * 4;
        const float* x0 = src + (size_t)row * HID;
        float p[4][NHEAD];
#pragma unroll
        for (int r = 0; r < 4; r++)
#pragma unroll
            for (int h = 0; h < NHEAD; h++) p[r][h] = 0.f;
        for (int k = lane; k < HID; k += 32) {
            float xv0 = x0[k];
            float xv1 = x0[HID + k];
            float xv2 = x0[2 * HID + k];
            float xv3 = x0[3 * HID + k];
#pragma unroll
            for (int h = 0; h < NHEAD; h++) {
                const float wv = sW[h * HID + k];
                p[0][h] += xv0 * wv; p[1][h] += xv1 * wv;
                p[2][h] += xv2 * wv; p[3][h] += xv3 * wv;
            }
        }
#pragma unroll
        for (int r = 0; r < 4; r++) {
            float vout = 0.f;
#pragma unroll
            for (int h = 0; h < NHEAD; h++) {
                float v = p[r][h];
#pragma unroll
                for (int o = 16; o; o >>= 1) v += __shfl_xor_sync(0xffffffffu, v, o);
                if (lane == h) vout = v;
            }
            if (lane < NHEAD)
                out[(size_t)(row + r) * NHEAD + lane] = vout + bias[lane];
        }
    }
}

// ============================================================================
__global__ void stats_kernel(const float* __restrict__ scores,
                             const float* __restrict__ mask, float2* __restrict__ st)
{
    __shared__ float red[256];
    const int bh = blockIdx.x, b = bh >> 4, h = bh & 15;
    const int t = threadIdx.x;
    const float* sc = scores + (size_t)b * SEQ * NHEAD + h;
    const float* mk = mask + b * SEQ;
    float mx = -1e30f;
    for (int s = t; s < SEQ; s += 256) mx = fmaxf(mx, sc[(size_t)s * NHEAD] * 0.125f + mk[s]);
    red[t] = mx; __syncthreads();
    for (int o = 128; o; o >>= 1) { if (t < o) red[t] = fmaxf(red[t], red[t + o]); __syncthreads(); }
    mx = red[0]; __syncthreads();
    float ps = 0.f;
    for (int s = t; s < SEQ; s += 256) ps += __expf(sc[(size_t)s * NHEAD] * 0.125f + mk[s] - mx);
    red[t] = ps; __syncthreads();
    for (int o = 128; o; o >>= 1) { if (t < o) red[t] += red[t + o]; __syncthreads(); }
    if (t == 0) st[bh] = make_float2(mx, red[0]);
}

__global__ void accum_kernel(const float* __restrict__ src,
                             const float* __restrict__ scores,
                             const float* __restrict__ mask,
                             const float2* __restrict__ st, float* __restrict__ part)
{
    __shared__ float red[256];
    const int blk = blockIdx.x, bh = blk >> 3, ch = blk & 7;
    const int b = bh >> 4, h = bh & 15;
    const int t = threadIdx.x, d = t & 63, sg = t >> 6;
    const float2 s2 = st[bh];
    const float mx = s2.x, inv = 1.0f / s2.y;
    const float* base = src + (size_t)b * SEQ * HID + h * 64 + d;
    const float* sc = scores + (size_t)b * SEQ * NHEAD + h;
    const float* mk = mask + b * SEQ;
    float acc = 0.f;
    const int s0 = ch * 512;
    for (int s = s0 + sg; s < s0 + 512; s += 4) {
        float w = __expf(sc[(size_t)s * NHEAD] * 0.125f + mk[s] - mx);
        acc += w * base[(size_t)s * HID];
    }
    red[t] = acc; __syncthreads();
    if (sg == 0)
        part[(size_t)blk * 64 + d] = (red[d] + red[64 + d] + red[128 + d] + red[192 + d]) * inv;
}

__global__ void finalize_kernel(const float* __restrict__ part,
                                const float* __restrict__ postgate, float* __restrict__ out)
{
    const int idx = blockIdx.x * 256 + threadIdx.x;   // 8192
    const int bh = idx >> 6, d = idx & 63;
    float v = 0.f;
#pragma unroll
    for (int c = 0; c < 8; c++) v += part[(size_t)(bh * 8 + c) * 64 + d];
    if (postgate) v *= postgate[idx];
    out[idx] = v;
}

// wtgh[b,n,k] = (half)(Wt[n,k] * pk[b,k] * 2^14)   (scale avoids fp16 subnormals)
__global__ void wtg_kernel(const float* __restrict__ Wt, const float* __restrict__ pk,
                           __half* __restrict__ wtgh)
{
    const size_t i4 = (size_t)blockIdx.x * 256 + threadIdx.x;  // 2,097,152
    const int j4 = (int)(i4 & 255);
    const int n  = (int)((i4 >> 8) & 1023);
    const int b  = (int)(i4 >> 18);
    float4 w = ((const float4*)Wt)[n * 256 + j4];
    float4 g = ((const float4*)pk)[b * 256 + j4];
    const float S = 16384.0f;
    __half2 h0 = __floats2half2_rn(w.x * g.x * S, w.y * g.y * S);
    __half2 h1 = __floats2half2_rn(w.z * g.z * S, w.w * g.w * S);
    ((__half2*)wtgh)[2 * i4]     = h0;
    ((__half2*)wtgh)[2 * i4 + 1] = h1;
}

// ============================================================================
extern "C" void kernel_launch(void* const* d_in, const int* in_sizes, int n_in,
                              void* d_out, int out_size)
{
    const float* X    = (const float*)d_in[0];
    const float* mask = (const float*)d_in[1];
    const float* Wq   = (const float*)d_in[2];
    const float* bq   = (const float*)d_in[3];
    const float* Wqa  = (const float*)d_in[4];
    const float* bqa  = (const float*)d_in[5];
    const float* Wk   = (const float*)d_in[6];
    const float* bk   = (const float*)d_in[7];
    const float* Wka  = (const float*)d_in[8];
    const float* bka  = (const float*)d_in[9];
    const float* Wt   = (const float*)d_in[10];
    const float* bt   = (const float*)d_in[11];
    float* out = (float*)d_out;

    float *mq, *mk, *qs, *ks, *pq, *pk, *part;
    float2 *stq, *stk;
    __half *xh, *mqh, *wqh, *wkh, *wtgh;
    cudaGetSymbolAddress((void**)&mq, g_mq);
    cudaGetSymbolAddress((void**)&mk, g_mk);
    cudaGetSymbolAddress((void**)&qs, g_qs);
    cudaGetSymbolAddress((void**)&ks, g_ks);
    cudaGetSymbolAddress((void**)&pq, g_pq);
    cudaGetSymbolAddress((void**)&pk, g_pk);
    cudaGetSymbolAddress((void**)&part, g_part);
    cudaGetSymbolAddress((void**)&stq, g_stq);
    cudaGetSymbolAddress((void**)&stk, g_stk);
    cudaGetSymbolAddress((void**)&xh, g_xh);
    cudaGetSymbolAddress((void**)&mqh, g_mqh);
    cudaGetSymbolAddress((void**)&wqh, g_wqh);
    cudaGetSymbolAddress((void**)&wkh, g_wkh);
    cudaGetSymbolAddress((void**)&wtgh, g_wtgh);

    cudaFuncSetAttribute(gemm_fp16<true, false, false, true, false>,
                         cudaFuncAttributeMaxDynamicSharedMemorySize, (int)GEMM_SMEM);
    cudaFuncSetAttribute(gemm_fp16<false, true, true, false, true>,
                         cudaFuncAttributeMaxDynamicSharedMemorySize, (int)GEMM_SMEM);
    const size_t score_smem = (size_t)NHEAD * HID * sizeof(float);
    cudaFuncSetAttribute(score_kernel,
                         cudaFuncAttributeMaxDynamicSharedMemorySize, (int)score_smem);

    const __half* nullh = nullptr;
    const float*  nullf = nullptr;

    // 0) fp16 conversions
    f2h_kernel<<<(MROWS * HID / 4 + 255) / 256, 256>>>(X, xh, MROWS * HID / 4);
    f2h_kernel<<<(HID * HID / 4 + 255) / 256, 256>>>(Wq, wqh, HID * HID / 4);
    f2h_kernel<<<(HID * HID / 4 + 255) / 256, 256>>>(Wk, wkh, HID * HID / 4);

    // 1) fused: mq = X@Wq^T + bq (also fp16 copy) ; mk = X@Wk^T + bk
    gemm_fp16<true, false, false, true, false><<<dim3(16, MROWS / BM), 256, GEMM_SMEM>>>(
        xh, wqh, wkh, bq, bk, nullf, mq, mk, mqh);

    // 2) q scores -> pooled_q
    score_kernel<<<MROWS / SCORE_ROWS, 256, score_smem>>>(mq, Wqa, bqa, nullf, qs);
    stats_kernel<<<BATCH * NHEAD, 256>>>(qs, mask, stq);
    accum_kernel<<<BATCH * NHEAD * 8, 256>>>(mq, qs, mask, stq, part);
    finalize_kernel<<<BATCH * HID / 256, 256>>>(part, nullf, pq);

    // 3) qk scores (gate folded into Wka) -> pooled_k (post-gate pq)
    score_kernel<<<MROWS / SCORE_ROWS, 256, score_smem>>>(mk, Wka, bka, pq, ks);
    stats_kernel<<<BATCH * NHEAD, 256>>>(ks, mask, stk);
    accum_kernel<<<BATCH * NHEAD * 8, 256>>>(mk, ks, mask, stk, part);
    finalize_kernel<<<BATCH * HID / 256, 256>>>(part, pq, pk);

    // 4) wtgh = Wt * pk_full[b] * 2^14 ; out = mqh @ wtgh[b]^T * 2^-14 + bt + mq
    wtg_kernel<<<(BATCH * HID * HID / 4) / 256, 256>>>(Wt, pk, wtgh);
    gemm_fp16<false, true, true, false, true><<<dim3(8, MROWS / BM), 256, GEMM_SMEM>>>(
        mqh, wtgh, nullh, bt, nullf, mq, out, (float*)nullptr, (__half*)nullptr);
}

// round 9
// speedup vs baseline: 2.4551x; 1.1341x over previous
#include <cuda_runtime.h>
#include <cuda_fp16.h>
#include <cstdint>
#include <cstddef>

#define BATCH 8
#define SEQ   4096
#define HID   1024
#define NHEAD 16
#define MROWS (BATCH * SEQ)   // 32768

// ---------------- scratch (device globals; allocations forbidden) ----------
__device__ __half g_xh[(size_t)MROWS * HID];
__device__ __half g_mqh[(size_t)MROWS * HID];
__device__ __half g_mkh[(size_t)MROWS * HID];
__device__ __half g_wqh[(size_t)HID * HID];
__device__ __half g_wkh[(size_t)HID * HID];
__device__ __half g_wtgh[(size_t)BATCH * HID * HID];
__device__ float  g_qs[(size_t)MROWS * NHEAD];
__device__ float  g_ks[(size_t)MROWS * NHEAD];
__device__ float  g_pq[BATCH * HID];
__device__ float  g_pk[BATCH * HID];
__device__ float2 g_stq[BATCH * NHEAD];
__device__ float2 g_stk[BATCH * NHEAD];
__device__ float  g_part[BATCH * NHEAD * 8 * 64];

// ============================================================================
// fp16 GEMM: acc[m,n] = sum_k A[m,k]*W[n,k]; out = acc*sc + bias (+resid)
// BM=128, BN=128, BK=64; 256 thr; 3-stage cp.async; mma m16n8k16; ldmatrix.x4.
// 2 CTAs/SM (110.6KB smem, <=128 regs).
// DUAL: grid.x=16, nb<8 -> (W0,b0,H0), else (W1,b1,H1).
// PERB: W indexed per batch. OUTH: write __half outputs H0/H1.
// !OUTH: write float Cf with fp16 residual residH added. SCALED: acc *= 2^-14.
// ============================================================================
constexpr int BM = 128, BN = 128, BK = 64;
constexpr int SROW = 72;                      // halves per smem row (144B, padded)
constexpr int NKB = HID / BK;                 // 16
constexpr int STGH = (BM + BN) * SROW;        // 18432 halves per stage
constexpr size_t GEMM_SMEM = (size_t)3 * STGH * sizeof(__half);  // 110592 B

#define LDSM_X4(r0, r1, r2, r3, addr)                                             \
    asm volatile("ldmatrix.sync.aligned.m8n8.x4.shared.b16 {%0,%1,%2,%3}, [%4];"  \
                 : "=r"(r0), "=r"(r1), "=r"(r2), "=r"(r3) : "r"(addr))

template <bool DUAL, bool PERB, bool OUTH, bool SCALED>
__global__ void __launch_bounds__(256, 2) gemm_fp16(
    const __half* __restrict__ A, const __half* __restrict__ W0, const __half* __restrict__ W1,
    const float* __restrict__ b0, const float* __restrict__ b1,
    const __half* __restrict__ residH, float* __restrict__ Cf,
    __half* __restrict__ H0, __half* __restrict__ H1)
{
    extern __shared__ __half smh[];
    const int tid = threadIdx.x;
    const int m0 = blockIdx.y * BM;
    int nb = blockIdx.x;

    const __half* W; const float* bias; __half* H = H0;
    if (DUAL) {
        if (nb < 8) { W = W0; bias = b0; H = H0; }
        else        { nb -= 8; W = W1; bias = b1; H = H1; }
    } else {
        W = W0 + (PERB ? (size_t)(m0 / SEQ) * HID * HID : 0);
        bias = b0;
    }
    const int n0 = nb * BN;

    const int warp = tid >> 5, lane = tid & 31;
    const int wm = warp & 3, wn = warp >> 2;    // 4x2 warps -> 32x64 per warp
    const int grp = lane >> 2, qid = lane & 3;

    // ldmatrix per-lane address components
    const int lr = lane & 7;
    const int lh = (lane >> 3) & 1;
    const int lk = (lane >> 4) & 1;

    uint32_t offA[2], offB[4];
#pragma unroll
    for (int mt = 0; mt < 2; mt++)
        offA[mt] = (uint32_t)(((wm * 32 + mt * 16 + lh * 8 + lr) * SROW + lk * 8) * 2);
#pragma unroll
    for (int p = 0; p < 4; p++)
        offB[p] = (uint32_t)(((wn * 64 + p * 16 + lk * 8 + lr) * SROW + lh * 8) * 2
                             + BM * SROW * 2);

    const uint32_t smBase = (uint32_t)__cvta_generic_to_shared(smh);

    float acc[2][8][4];
#pragma unroll
    for (int i = 0; i < 2; i++)
#pragma unroll
        for (int j = 0; j < 8; j++)
#pragma unroll
            for (int l = 0; l < 4; l++) acc[i][j][l] = 0.f;

    const __half* Ab = A + (size_t)m0 * HID;
    const __half* Wb = W + (size_t)n0 * HID;

    auto loadTile = [&](int kb, int s) {
        __half* sa = smh + s * STGH;
        __half* sb = sa + BM * SROW;
        const __half* Ag = Ab + kb * BK;
        const __half* Wg = Wb + kb * BK;
#pragma unroll
        for (int i = 0; i < 8; i++) {          // 2048 granules of 16B
            const int id = tid + 256 * i;
            if (id < 1024) {                   // A: 128 rows x 8 granules
                const int r = id >> 3, c = id & 7;
                uint32_t d = (uint32_t)__cvta_generic_to_shared(sa + r * SROW + c * 8);
                asm volatile("cp.async.cg.shared.global [%0], [%1], 16;"
                             :: "r"(d), "l"(Ag + (size_t)r * HID + c * 8));
            } else {                           // B: 128 rows x 8 granules
                const int id2 = id - 1024;
                const int r = id2 >> 3, c = id2 & 7;
                uint32_t d = (uint32_t)__cvta_generic_to_shared(sb + r * SROW + c * 8);
                asm volatile("cp.async.cg.shared.global [%0], [%1], 16;"
                             :: "r"(d), "l"(Wg + (size_t)r * HID + c * 8));
            }
        }
        asm volatile("cp.async.commit_group;");
    };

    loadTile(0, 0);
    loadTile(1, 1);

    int s = 0;
    for (int kb = 0; kb < NKB; kb++) {
        asm volatile("cp.async.wait_group 1;");
        __syncthreads();
        if (kb + 2 < NKB) loadTile(kb + 2, (s + 2) % 3);

        const uint32_t stBase = smBase + s * (STGH * 2);

#pragma unroll
        for (int ks = 0; ks < 4; ks++) {
            const uint32_t kkb = ks * 32;
            uint32_t af[2][4], bf[8][2];
#pragma unroll
            for (int mt = 0; mt < 2; mt++)
                LDSM_X4(af[mt][0], af[mt][1], af[mt][2], af[mt][3],
                        stBase + offA[mt] + kkb);
#pragma unroll
            for (int p = 0; p < 4; p++)
                LDSM_X4(bf[2 * p][0], bf[2 * p][1], bf[2 * p + 1][0], bf[2 * p + 1][1],
                        stBase + offB[p] + kkb);
#pragma unroll
            for (int mt = 0; mt < 2; mt++)
#pragma unroll
                for (int nt = 0; nt < 8; nt++) {
                    asm volatile(
                        "mma.sync.aligned.m16n8k16.row.col.f32.f16.f16.f32 "
                        "{%0,%1,%2,%3}, {%4,%5,%6,%7}, {%8,%9}, {%0,%1,%2,%3};"
                        : "+f"(acc[mt][nt][0]), "+f"(acc[mt][nt][1]),
                          "+f"(acc[mt][nt][2]), "+f"(acc[mt][nt][3])
                        : "r"(af[mt][0]), "r"(af[mt][1]), "r"(af[mt][2]), "r"(af[mt][3]),
                          "r"(bf[nt][0]), "r"(bf[nt][1]));
                }
        }
        s = (s + 1) % 3;
    }

    const float sc = SCALED ? 6.103515625e-5f : 1.0f;   // 2^-14

    // epilogue
#pragma unroll
    for (int mt = 0; mt < 2; mt++) {
        const int r0 = m0 + wm * 32 + mt * 16 + grp;
#pragma unroll
        for (int nt = 0; nt < 8; nt++) {
            const int c = n0 + wn * 64 + nt * 8 + qid * 2;
            const float bv0 = bias[c], bv1 = bias[c + 1];
            float v0 = acc[mt][nt][0] * sc + bv0, v1 = acc[mt][nt][1] * sc + bv1;
            float v2 = acc[mt][nt][2] * sc + bv0, v3 = acc[mt][nt][3] * sc + bv1;
            if (OUTH) {
                *(__half2*)(H + (size_t)r0 * HID + c)       = __floats2half2_rn(v0, v1);
                *(__half2*)(H + (size_t)(r0 + 8) * HID + c) = __floats2half2_rn(v2, v3);
            } else {
                __half2 ra = *(const __half2*)(residH + (size_t)r0 * HID + c);
                __half2 rb = *(const __half2*)(residH + (size_t)(r0 + 8) * HID + c);
                float2 raf = __half22float2(ra), rbf = __half22float2(rb);
                float2 oa = {v0 + raf.x, v1 + raf.y};
                float2 ob = {v2 + rbf.x, v3 + rbf.y};
                *(float2*)(Cf + (size_t)r0 * HID + c) = oa;
                *(float2*)(Cf + (size_t)(r0 + 8) * HID + c) = ob;
            }
        }
    }
}

// ============================================================================
// fp32 -> fp16 converter (vectorized by 4)
// ============================================================================
__global__ void f2h_kernel(const float* __restrict__ src, __half* __restrict__ dst, int n4)
{
    const int i = blockIdx.x * 256 + threadIdx.x;
    if (i >= n4) return;
    float4 v = ((const float4*)src)[i];
    ((__half2*)dst)[2 * i]     = __floats2half2_rn(v.x, v.y);
    ((__half2*)dst)[2 * i + 1] = __floats2half2_rn(v.z, v.w);
}

// ============================================================================
// Score: out[m,h] = sum_k src[m,k]*(W[h,k]*(gate?g[b,k]:1)) + bias[h]
// src is fp16; 4 rows per warp iteration.
// ============================================================================
constexpr int SCORE_ROWS = 128;

__global__ void score_kernel(const __half* __restrict__ src,
                             const float* __restrict__ W,
                             const float* __restrict__ bias,
                             const float* __restrict__ gate,
                             float* __restrict__ out)
{
    extern __shared__ float sW[];  // [16][1024]
    const int row0 = blockIdx.x * SCORE_ROWS;
    const int b = row0 / SEQ;

    for (int i = threadIdx.x; i < NHEAD * HID; i += blockDim.x) {
        float w = W[i];
        if (gate) w *= gate[b * HID + (i & (HID - 1))];
        sW[i] = w;
    }
    __syncthreads();

    const int warp = threadIdx.x >> 5, lane = threadIdx.x & 31;
    for (int g = warp; g < SCORE_ROWS / 4; g += 8) {
        const int row = row0 + g * 4;
        const __half* x0 = src + (size_t)row * HID;
        float p[4][NHEAD];
#pragma unroll
        for (int r = 0; r < 4; r++)
#pragma unroll
            for (int h = 0; h < NHEAD; h++) p[r][h] = 0.f;
        for (int k2 = lane; k2 < HID / 2; k2 += 32) {
            const int k = k2 * 2;
            float2 xv0 = __half22float2(*(const __half2*)(x0 + k));
            float2 xv1 = __half22float2(*(const __half2*)(x0 + HID + k));
            float2 xv2 = __half22float2(*(const __half2*)(x0 + 2 * HID + k));
            float2 xv3 = __half22float2(*(const __half2*)(x0 + 3 * HID + k));
#pragma unroll
            for (int h = 0; h < NHEAD; h++) {
                const float w0 = sW[h * HID + k], w1 = sW[h * HID + k + 1];
                p[0][h] += xv0.x * w0 + xv0.y * w1;
                p[1][h] += xv1.x * w0 + xv1.y * w1;
                p[2][h] += xv2.x * w0 + xv2.y * w1;
                p[3][h] += xv3.x * w0 + xv3.y * w1;
            }
        }
#pragma unroll
        for (int r = 0; r < 4; r++) {
            float vout = 0.f;
#pragma unroll
            for (int h = 0; h < NHEAD; h++) {
                float v = p[r][h];
#pragma unroll
                for (int o = 16; o; o >>= 1) v += __shfl_xor_sync(0xffffffffu, v, o);
                if (lane == h) vout = v;
            }
            if (lane < NHEAD)
                out[(size_t)(row + r) * NHEAD + lane] = vout + bias[lane];
        }
    }
}

// ============================================================================
__global__ void stats_kernel(const float* __restrict__ scores,
                             const float* __restrict__ mask, float2* __restrict__ st)
{
    __shared__ float red[256];
    const int bh = blockIdx.x, b = bh >> 4, h = bh & 15;
    const int t = threadIdx.x;
    const float* sc = scores + (size_t)b * SEQ * NHEAD + h;
    const float* mk = mask + b * SEQ;
    float mx = -1e30f;
    for (int s = t; s < SEQ; s += 256) mx = fmaxf(mx, sc[(size_t)s * NHEAD] * 0.125f + mk[s]);
    red[t] = mx; __syncthreads();
    for (int o = 128; o; o >>= 1) { if (t < o) red[t] = fmaxf(red[t], red[t + o]); __syncthreads(); }
    mx = red[0]; __syncthreads();
    float ps = 0.f;
    for (int s = t; s < SEQ; s += 256) ps += __expf(sc[(size_t)s * NHEAD] * 0.125f + mk[s] - mx);
    red[t] = ps; __syncthreads();
    for (int o = 128; o; o >>= 1) { if (t < o) red[t] += red[t + o]; __syncthreads(); }
    if (t == 0) st[bh] = make_float2(mx, red[0]);
}

// ============================================================================
// Pool partials from fp16 src: block = (bh, 512-row chunk); deterministic
// ============================================================================
__global__ void accum_kernel(const __half* __restrict__ src,
                             const float* __restrict__ scores,
                             const float* __restrict__ mask,
                             const float2* __restrict__ st, float* __restrict__ part)
{
    __shared__ float red[256];
    const int blk = blockIdx.x, bh = blk >> 3, ch = blk & 7;
    const int b = bh >> 4, h = bh & 15;
    const int t = threadIdx.x, d = t & 63, sg = t >> 6;
    const float2 s2 = st[bh];
    const float mx = s2.x, inv = 1.0f / s2.y;
    const __half* base = src + (size_t)b * SEQ * HID + h * 64 + d;
    const float* sc = scores + (size_t)b * SEQ * NHEAD + h;
    const float* mk = mask + b * SEQ;
    float acc = 0.f;
    const int s0 = ch * 512;
    for (int s = s0 + sg; s < s0 + 512; s += 4) {
        float w = __expf(sc[(size_t)s * NHEAD] * 0.125f + mk[s] - mx);
        acc += w * __half2float(base[(size_t)s * HID]);
    }
    red[t] = acc; __syncthreads();
    if (sg == 0)
        part[(size_t)blk * 64 + d] = (red[d] + red[64 + d] + red[128 + d] + red[192 + d]) * inv;
}

__global__ void finalize_kernel(const float* __restrict__ part,
                                const float* __restrict__ postgate, float* __restrict__ out)
{
    const int idx = blockIdx.x * 256 + threadIdx.x;   // 8192
    const int bh = idx >> 6, d = idx & 63;
    float v = 0.f;
#pragma unroll
    for (int c = 0; c < 8; c++) v += part[(size_t)(bh * 8 + c) * 64 + d];
    if (postgate) v *= postgate[idx];
    out[idx] = v;
}

// wtgh[b,n,k] = (half)(Wt[n,k] * pk[b,k] * 2^14)   (scale avoids fp16 subnormals)
__global__ void wtg_kernel(const float* __restrict__ Wt, const float* __restrict__ pk,
                           __half* __restrict__ wtgh)
{
    const size_t i4 = (size_t)blockIdx.x * 256 + threadIdx.x;  // 2,097,152
    const int j4 = (int)(i4 & 255);
    const int n  = (int)((i4 >> 8) & 1023);
    const int b  = (int)(i4 >> 18);
    float4 w = ((const float4*)Wt)[n * 256 + j4];
    float4 g = ((const float4*)pk)[b * 256 + j4];
    const float S = 16384.0f;
    __half2 h0 = __floats2half2_rn(w.x * g.x * S, w.y * g.y * S);
    __half2 h1 = __floats2half2_rn(w.z * g.z * S, w.w * g.w * S);
    ((__half2*)wtgh)[2 * i4]     = h0;
    ((__half2*)wtgh)[2 * i4 + 1] = h1;
}

// ============================================================================
extern "C" void kernel_launch(void* const* d_in, const int* in_sizes, int n_in,
                              void* d_out, int out_size)
{
    const float* X    = (const float*)d_in[0];
    const float* mask = (const float*)d_in[1];
    const float* Wq   = (const float*)d_in[2];
    const float* bq   = (const float*)d_in[3];
    const float* Wqa  = (const float*)d_in[4];
    const float* bqa  = (const float*)d_in[5];
    const float* Wk   = (const float*)d_in[6];
    const float* bk   = (const float*)d_in[7];
    const float* Wka  = (const float*)d_in[8];
    const float* bka  = (const float*)d_in[9];
    const float* Wt   = (const float*)d_in[10];
    const float* bt   = (const float*)d_in[11];
    float* out = (float*)d_out;

    float *qs, *ks, *pq, *pk, *part;
    float2 *stq, *stk;
    __half *xh, *mqh, *mkh, *wqh, *wkh, *wtgh;
    cudaGetSymbolAddress((void**)&qs, g_qs);
    cudaGetSymbolAddress((void**)&ks, g_ks);
    cudaGetSymbolAddress((void**)&pq, g_pq);
    cudaGetSymbolAddress((void**)&pk, g_pk);
    cudaGetSymbolAddress((void**)&part, g_part);
    cudaGetSymbolAddress((void**)&stq, g_stq);
    cudaGetSymbolAddress((void**)&stk, g_stk);
    cudaGetSymbolAddress((void**)&xh, g_xh);
    cudaGetSymbolAddress((void**)&mqh, g_mqh);
    cudaGetSymbolAddress((void**)&mkh, g_mkh);
    cudaGetSymbolAddress((void**)&wqh, g_wqh);
    cudaGetSymbolAddress((void**)&wkh, g_wkh);
    cudaGetSymbolAddress((void**)&wtgh, g_wtgh);

    cudaFuncSetAttribute(gemm_fp16<true, false, true, false>,
                         cudaFuncAttributeMaxDynamicSharedMemorySize, (int)GEMM_SMEM);
    cudaFuncSetAttribute(gemm_fp16<false, true, false, true>,
                         cudaFuncAttributeMaxDynamicSharedMemorySize, (int)GEMM_SMEM);
    const size_t score_smem = (size_t)NHEAD * HID * sizeof(float);
    cudaFuncSetAttribute(score_kernel,
                         cudaFuncAttributeMaxDynamicSharedMemorySize, (int)score_smem);

    const float* nullf = nullptr;

    // 0) fp16 conversions
    f2h_kernel<<<(MROWS * HID / 4 + 255) / 256, 256>>>(X, xh, MROWS * HID / 4);
    f2h_kernel<<<(HID * HID / 4 + 255) / 256, 256>>>(Wq, wqh, HID * HID / 4);
    f2h_kernel<<<(HID * HID / 4 + 255) / 256, 256>>>(Wk, wkh, HID * HID / 4);

    // 1) fused: mqh = X@Wq^T + bq ; mkh = X@Wk^T + bk  (fp16 outputs)
    gemm_fp16<true, false, true, false><<<dim3(16, MROWS / BM), 256, GEMM_SMEM>>>(
        xh, wqh, wkh, bq, bk, (const __half*)nullptr, (float*)nullptr, mqh, mkh);

    // 2) q scores -> pooled_q
    score_kernel<<<MROWS / SCORE_ROWS, 256, score_smem>>>(mqh, Wqa, bqa, nullf, qs);
    stats_kernel<<<BATCH * NHEAD, 256>>>(qs, mask, stq);
    accum_kernel<<<BATCH * NHEAD * 8, 256>>>(mqh, qs, mask, stq, part);
    finalize_kernel<<<BATCH * HID / 256, 256>>>(part, nullf, pq);

    // 3) qk scores (gate folded into Wka) -> pooled_k (post-gate pq)
    score_kernel<<<MROWS / SCORE_ROWS, 256, score_smem>>>(mkh, Wka, bka, pq, ks);
    stats_kernel<<<BATCH * NHEAD, 256>>>(ks, mask, stk);
    accum_kernel<<<BATCH * NHEAD * 8, 256>>>(mkh, ks, mask, stk, part);
    finalize_kernel<<<BATCH * HID / 256, 256>>>(part, pq, pk);

    // 4) wtgh = Wt * pk_full[b] * 2^14 ; out = mqh @ wtgh[b]^T * 2^-14 + bt + mqh
    wtg_kernel<<<(BATCH * HID * HID / 4) / 256, 256>>>(Wt, pk, wtgh);
    gemm_fp16<false, true, false, true><<<dim3(8, MROWS / BM), 256, GEMM_SMEM>>>(
        mqh, wtgh, (const __half*)nullptr, bt, nullf, mqh, out,
        (__half*)nullptr, (__half*)nullptr);
}

// round 10
// speedup vs baseline: 2.8143x; 1.1463x over previous
#include <cuda_runtime.h>
#include <cuda_fp16.h>
#include <cstdint>
#include <cstddef>

#define BATCH 8
#define SEQ   4096
#define HID   1024
#define NHEAD 16
#define MROWS (BATCH * SEQ)   // 32768

// ---------------- scratch (device globals; allocations forbidden) ----------
__device__ __half g_xh[(size_t)MROWS * HID];
__device__ __half g_mqh[(size_t)MROWS * HID];
__device__ __half g_mkh[(size_t)MROWS * HID];
__device__ __half g_wqh[(size_t)HID * HID];
__device__ __half g_wkh[(size_t)HID * HID];
__device__ __half g_wtgh[(size_t)BATCH * HID * HID];
__device__ float  g_qs[(size_t)MROWS * NHEAD];
__device__ float  g_ks[(size_t)MROWS * NHEAD];
__device__ float  g_pq[BATCH * HID];
__device__ float  g_pk[BATCH * HID];
__device__ float2 g_stq[BATCH * NHEAD];
__device__ float2 g_stk[BATCH * NHEAD];
__device__ float  g_part[BATCH * NHEAD * 8 * 64];

#define LDSM_X4(r0, r1, r2, r3, addr)                                             \
    asm volatile("ldmatrix.sync.aligned.m8n8.x4.shared.b16 {%0,%1,%2,%3}, [%4];"  \
                 : "=r"(r0), "=r"(r1), "=r"(r2), "=r"(r3) : "r"(addr))

// ============================================================================
// fp16 GEMM: acc[m,n] = sum_k A[m,k]*W[n,k]; out = acc*sc + bias (+resid)
// BM=64, BN=128, BK=64; 128 thr (4 warps, 2x2 grid, warp tile 32x64);
// 2-stage cp.async (wait_group 0 -> sync -> prefetch -> compute);
// 4 CTAs/SM (55.3KB smem, <=128 regs) -> 4 independent barrier domains.
// DUAL: grid.x=16, nb<8 -> (W0,b0,H0), else (W1,b1,H1).
// PERB: W indexed per batch. OUTH: write __half outputs H0/H1.
// !OUTH: write float Cf with fp16 residual residH added. SCALED: acc *= 2^-14.
// ============================================================================
constexpr int BM = 64, BN = 128, BK = 64;
constexpr int SROW = 72;                      // halves per smem row (144B, padded)
constexpr int NKB = HID / BK;                 // 16
constexpr int STGH = (BM + BN) * SROW;        // 13824 halves per stage
constexpr size_t GEMM_SMEM = (size_t)2 * STGH * sizeof(__half);  // 55296 B

template <bool DUAL, bool PERB, bool OUTH, bool SCALED>
__global__ void __launch_bounds__(128, 4) gemm_fp16(
    const __half* __restrict__ A, const __half* __restrict__ W0, const __half* __restrict__ W1,
    const float* __restrict__ b0, const float* __restrict__ b1,
    const __half* __restrict__ residH, float* __restrict__ Cf,
    __half* __restrict__ H0, __half* __restrict__ H1)
{
    extern __shared__ __half smh[];
    const int tid = threadIdx.x;
    const int m0 = blockIdx.y * BM;
    int nb = blockIdx.x;

    const __half* W; const float* bias; __half* H = H0;
    if (DUAL) {
        if (nb < 8) { W = W0; bias = b0; H = H0; }
        else        { nb -= 8; W = W1; bias = b1; H = H1; }
    } else {
        W = W0 + (PERB ? (size_t)(m0 / SEQ) * HID * HID : 0);
        bias = b0;
    }
    const int n0 = nb * BN;

    const int warp = tid >> 5, lane = tid & 31;
    const int wm = warp & 1, wn = warp >> 1;    // 2x2 warps -> 32x64 per warp
    const int grp = lane >> 2, qid = lane & 3;

    const int lr = lane & 7;
    const int lh = (lane >> 3) & 1;
    const int lk = (lane >> 4) & 1;

    uint32_t offA[2], offB[4];
#pragma unroll
    for (int mt = 0; mt < 2; mt++)
        offA[mt] = (uint32_t)(((wm * 32 + mt * 16 + lh * 8 + lr) * SROW + lk * 8) * 2);
#pragma unroll
    for (int p = 0; p < 4; p++)
        offB[p] = (uint32_t)(((wn * 64 + p * 16 + lk * 8 + lr) * SROW + lh * 8) * 2
                             + BM * SROW * 2);

    const uint32_t smBase = (uint32_t)__cvta_generic_to_shared(smh);

    float acc[2][8][4];
#pragma unroll
    for (int i = 0; i < 2; i++)
#pragma unroll
        for (int j = 0; j < 8; j++)
#pragma unroll
            for (int l = 0; l < 4; l++) acc[i][j][l] = 0.f;

    const __half* Ab = A + (size_t)m0 * HID;
    const __half* Wb = W + (size_t)n0 * HID;

    auto loadTile = [&](int kb, int s) {
        __half* sa = smh + s * STGH;
        __half* sb = sa + BM * SROW;
        const __half* Ag = Ab + kb * BK;
        const __half* Wg = Wb + kb * BK;
#pragma unroll
        for (int i = 0; i < 12; i++) {         // 1536 granules of 16B
            const int id = tid + 128 * i;
            if (id < 512) {                    // A: 64 rows x 8 granules
                const int r = id >> 3, c = id & 7;
                uint32_t d = (uint32_t)__cvta_generic_to_shared(sa + r * SROW + c * 8);
                asm volatile("cp.async.cg.shared.global [%0], [%1], 16;"
                             :: "r"(d), "l"(Ag + (size_t)r * HID + c * 8));
            } else {                           // B: 128 rows x 8 granules
                const int id2 = id - 512;
                const int r = id2 >> 3, c = id2 & 7;
                uint32_t d = (uint32_t)__cvta_generic_to_shared(sb + r * SROW + c * 8);
                asm volatile("cp.async.cg.shared.global [%0], [%1], 16;"
                             :: "r"(d), "l"(Wg + (size_t)r * HID + c * 8));
            }
        }
        asm volatile("cp.async.commit_group;");
    };

    loadTile(0, 0);

    for (int kb = 0; kb < NKB; kb++) {
        asm volatile("cp.async.wait_group 0;");   // tile kb fully arrived
        __syncthreads();                          // all warps done reading prev buffer
        if (kb + 1 < NKB) loadTile(kb + 1, (kb + 1) & 1);

        const uint32_t stBase = smBase + (kb & 1) * (STGH * 2);

#pragma unroll
        for (int ks = 0; ks < 4; ks++) {
            const uint32_t kkb = ks * 32;
            uint32_t af[2][4], bf[8][2];
#pragma unroll
            for (int mt = 0; mt < 2; mt++)
                LDSM_X4(af[mt][0], af[mt][1], af[mt][2], af[mt][3],
                        stBase + offA[mt] + kkb);
#pragma unroll
            for (int p = 0; p < 4; p++)
                LDSM_X4(bf[2 * p][0], bf[2 * p][1], bf[2 * p + 1][0], bf[2 * p + 1][1],
                        stBase + offB[p] + kkb);
#pragma unroll
            for (int mt = 0; mt < 2; mt++)
#pragma unroll
                for (int nt = 0; nt < 8; nt++) {
                    asm volatile(
                        "mma.sync.aligned.m16n8k16.row.col.f32.f16.f16.f32 "
                        "{%0,%1,%2,%3}, {%4,%5,%6,%7}, {%8,%9}, {%0,%1,%2,%3};"
                        : "+f"(acc[mt][nt][0]), "+f"(acc[mt][nt][1]),
                          "+f"(acc[mt][nt][2]), "+f"(acc[mt][nt][3])
                        : "r"(af[mt][0]), "r"(af[mt][1]), "r"(af[mt][2]), "r"(af[mt][3]),
                          "r"(bf[nt][0]), "r"(bf[nt][1]));
                }
        }
    }

    const float sc = SCALED ? 6.103515625e-5f : 1.0f;   // 2^-14

    // epilogue
#pragma unroll
    for (int mt = 0; mt < 2; mt++) {
        const int r0 = m0 + wm * 32 + mt * 16 + grp;
#pragma unroll
        for (int nt = 0; nt < 8; nt++) {
            const int c = n0 + wn * 64 + nt * 8 + qid * 2;
            const float bv0 = bias[c], bv1 = bias[c + 1];
            float v0 = acc[mt][nt][0] * sc + bv0, v1 = acc[mt][nt][1] * sc + bv1;
            float v2 = acc[mt][nt][2] * sc + bv0, v3 = acc[mt][nt][3] * sc + bv1;
            if (OUTH) {
                *(__half2*)(H + (size_t)r0 * HID + c)       = __floats2half2_rn(v0, v1);
                *(__half2*)(H + (size_t)(r0 + 8) * HID + c) = __floats2half2_rn(v2, v3);
            } else {
                __half2 ra = *(const __half2*)(residH + (size_t)r0 * HID + c);
                __half2 rb = *(const __half2*)(residH + (size_t)(r0 + 8) * HID + c);
                float2 raf = __half22float2(ra), rbf = __half22float2(rb);
                float2 oa = {v0 + raf.x, v1 + raf.y};
                float2 ob = {v2 + rbf.x, v3 + rbf.y};
                *(float2*)(Cf + (size_t)r0 * HID + c) = oa;
                *(float2*)(Cf + (size_t)(r0 + 8) * HID + c) = ob;
            }
        }
    }
}

// ============================================================================
// score_mma: out[m,h] = sum_k src[m,k]*(W[h,k]*(gate?g[b,k]:1)) + bias[h]
// Tensor-core skinny GEMM (N=16). Gated W resident in smem as fp16
// (row stride 1032 halves -> conflict-free LDSM); A 3-stage cp.async.
// 256 thr (8 warps x m16 = 128 rows/CTA), m16n8k16.
// ============================================================================
constexpr int SC_WROW = 1032;                 // Wg smem row stride (halves)
constexpr int SC_SROW = 72;                   // A smem row stride (halves)
constexpr int SC_NKT  = HID / 64;             // 16 K-tiles of 64
constexpr size_t SC_SMEM = (size_t)(16 * SC_WROW + 3 * 128 * SC_SROW) * 2; // 88320 B

__global__ void __launch_bounds__(256, 2) score_mma(
    const __half* __restrict__ src, const float* __restrict__ W,
    const float* __restrict__ bias, const float* __restrict__ gate,
    float* __restrict__ out)
{
    extern __shared__ __half ssc[];
    __half* sWg = ssc;                        // 16 x 1032
    __half* sA  = ssc + 16 * SC_WROW;         // 3 x 128 x 72
    const int tid = threadIdx.x, warp = tid >> 5, lane = tid & 31;
    const int row0 = blockIdx.x * 128;
    const int b = row0 / SEQ;

    // build gated fp16 weight in smem
    for (int i = tid; i < NHEAD * HID; i += 256) {
        const int h = i >> 10, k = i & 1023;
        float w = W[i];
        if (gate) w *= gate[b * HID + k];
        sWg[h * SC_WROW + k] = __float2half_rn(w);
    }

    const __half* Ab = src + (size_t)row0 * HID;
    auto loadA = [&](int kt, int s) {
        __half* sa = sA + s * 128 * SC_SROW;
        const __half* Ag = Ab + kt * 64;
#pragma unroll
        for (int i = 0; i < 4; i++) {          // 1024 granules of 16B
            const int id = tid + 256 * i;
            const int r = id >> 3, c = id & 7;
            uint32_t d = (uint32_t)__cvta_generic_to_shared(sa + r * SC_SROW + c * 8);
            asm volatile("cp.async.cg.shared.global [%0], [%1], 16;"
                         :: "r"(d), "l"(Ag + (size_t)r * HID + c * 8));
        }
        asm volatile("cp.async.commit_group;");
    };

    loadA(0, 0);
    loadA(1, 1);
    __syncthreads();                           // Wg visible to all warps

    const int lr = lane & 7;
    const int lh = (lane >> 3) & 1;
    const int lk = lane >> 4;
    const uint32_t offA = (uint32_t)(((warp * 16 + lh * 8 + lr) * SC_SROW + lk * 8) * 2);
    const uint32_t offBW = (uint32_t)(((lk * 8 + lr) * SC_WROW + lh * 8) * 2);
    const uint32_t smA = (uint32_t)__cvta_generic_to_shared(sA);
    const uint32_t smW = (uint32_t)__cvta_generic_to_shared(sWg);

    float acc0[4] = {0.f, 0.f, 0.f, 0.f};
    float acc1[4] = {0.f, 0.f, 0.f, 0.f};

    int s = 0;
    for (int kt = 0; kt < SC_NKT; kt++) {
        if (kt + 1 < SC_NKT) asm volatile("cp.async.wait_group 1;");
        else                 asm volatile("cp.async.wait_group 0;");
        __syncthreads();
        if (kt + 2 < SC_NKT) loadA(kt + 2, (s + 2) % 3);

        const uint32_t stA = smA + s * (128 * SC_SROW * 2);
#pragma unroll
        for (int ks = 0; ks < 4; ks++) {
            uint32_t a0, a1, a2, a3, b0, b1, b2, b3;
            LDSM_X4(a0, a1, a2, a3, stA + offA + ks * 32);
            LDSM_X4(b0, b1, b2, b3, smW + offBW + (uint32_t)((kt * 64 + ks * 16) * 2));
            asm volatile(
                "mma.sync.aligned.m16n8k16.row.col.f32.f16.f16.f32 "
                "{%0,%1,%2,%3}, {%4,%5,%6,%7}, {%8,%9}, {%0,%1,%2,%3};"
                : "+f"(acc0[0]), "+f"(acc0[1]), "+f"(acc0[2]), "+f"(acc0[3])
                : "r"(a0), "r"(a1), "r"(a2), "r"(a3), "r"(b0), "r"(b1));
            asm volatile(
                "mma.sync.aligned.m16n8k16.row.col.f32.f16.f16.f32 "
                "{%0,%1,%2,%3}, {%4,%5,%6,%7}, {%8,%9}, {%0,%1,%2,%3};"
                : "+f"(acc1[0]), "+f"(acc1[1]), "+f"(acc1[2]), "+f"(acc1[3])
                : "r"(a0), "r"(a1), "r"(a2), "r"(a3), "r"(b2), "r"(b3));
        }
        s = (s + 1) % 3;
    }

    const int grp = lane >> 2, qid = lane & 3;
    const int rlo = row0 + warp * 16 + grp;
    float2 bv0 = ((const float2*)bias)[qid];
    float2 bv1 = ((const float2*)bias)[4 + qid];
    float2 o;
    o.x = acc0[0] + bv0.x; o.y = acc0[1] + bv0.y;
    *(float2*)(out + (size_t)rlo * NHEAD + qid * 2) = o;
    o.x = acc0[2] + bv0.x; o.y = acc0[3] + bv0.y;
    *(float2*)(out + (size_t)(rlo + 8) * NHEAD + qid * 2) = o;
    o.x = acc1[0] + bv1.x; o.y = acc1[1] + bv1.y;
    *(float2*)(out + (size_t)rlo * NHEAD + 8 + qid * 2) = o;
    o.x = acc1[2] + bv1.x; o.y = acc1[3] + bv1.y;
    *(float2*)(out + (size_t)(rlo + 8) * NHEAD + 8 + qid * 2) = o;
}

// ============================================================================
// fp32 -> fp16 converter (vectorized by 4)
// ============================================================================
__global__ void f2h_kernel(const float* __restrict__ src, __half* __restrict__ dst, int n4)
{
    const int i = blockIdx.x * 256 + threadIdx.x;
    if (i >= n4) return;
    float4 v = ((const float4*)src)[i];
    ((__half2*)dst)[2 * i]     = __floats2half2_rn(v.x, v.y);
    ((__half2*)dst)[2 * i + 1] = __floats2half2_rn(v.z, v.w);
}

// ============================================================================
__global__ void stats_kernel(const float* __restrict__ scores,
                             const float* __restrict__ mask, float2* __restrict__ st)
{
    __shared__ float red[256];
    const int bh = blockIdx.x, b = bh >> 4, h = bh & 15;
    const int t = threadIdx.x;
    const float* sc = scores + (size_t)b * SEQ * NHEAD + h;
    const float* mk = mask + b * SEQ;
    float mx = -1e30f;
    for (int s = t; s < SEQ; s += 256) mx = fmaxf(mx, sc[(size_t)s * NHEAD] * 0.125f + mk[s]);
    red[t] = mx; __syncthreads();
    for (int o = 128; o; o >>= 1) { if (t < o) red[t] = fmaxf(red[t], red[t + o]); __syncthreads(); }
    mx = red[0]; __syncthreads();
    float ps = 0.f;
    for (int s = t; s < SEQ; s += 256) ps += __expf(sc[(size_t)s * NHEAD] * 0.125f + mk[s] - mx);
    red[t] = ps; __syncthreads();
    for (int o = 128; o; o >>= 1) { if (t < o) red[t] += red[t + o]; __syncthreads(); }
    if (t == 0) st[bh] = make_float2(mx, red[0]);
}

// ============================================================================
// Pool partials from fp16 src: block = (bh, 512-row chunk); deterministic
// ============================================================================
__global__ void accum_kernel(const __half* __restrict__ src,
                             const float* __restrict__ scores,
                             const float* __restrict__ mask,
                             const float2* __restrict__ st, float* __restrict__ part)
{
    __shared__ float red[256];
    const int blk = blockIdx.x, bh = blk >> 3, ch = blk & 7;
    const int b = bh >> 4, h = bh & 15;
    const int t = threadIdx.x, d = t & 63, sg = t >> 6;
    const float2 s2 = st[bh];
    const float mx = s2.x, inv = 1.0f / s2.y;
    const __half* base = src + (size_t)b * SEQ * HID + h * 64 + d;
    const float* sc = scores + (size_t)b * SEQ * NHEAD + h;
    const float* mk = mask + b * SEQ;
    float acc = 0.f;
    const int s0 = ch * 512;
    for (int s = s0 + sg; s < s0 + 512; s += 4) {
        float w = __expf(sc[(size_t)s * NHEAD] * 0.125f + mk[s] - mx);
        acc += w * __half2float(base[(size_t)s * HID]);
    }
    red[t] = acc; __syncthreads();
    if (sg == 0)
        part[(size_t)blk * 64 + d] = (red[d] + red[64 + d] + red[128 + d] + red[192 + d]) * inv;
}

__global__ void finalize_kernel(const float* __restrict__ part,
                                const float* __restrict__ postgate, float* __restrict__ out)
{
    const int idx = blockIdx.x * 256 + threadIdx.x;   // 8192
    const int bh = idx >> 6, d = idx & 63;
    float v = 0.f;
#pragma unroll
    for (int c = 0; c < 8; c++) v += part[(size_t)(bh * 8 + c) * 64 + d];
    if (postgate) v *= postgate[idx];
    out[idx] = v;
}

// wtgh[b,n,k] = (half)(Wt[n,k] * pk[b,k] * 2^14)   (scale avoids fp16 subnormals)
__global__ void wtg_kernel(const float* __restrict__ Wt, const float* __restrict__ pk,
                           __half* __restrict__ wtgh)
{
    const size_t i4 = (size_t)blockIdx.x * 256 + threadIdx.x;  // 2,097,152
    const int j4 = (int)(i4 & 255);
    const int n  = (int)((i4 >> 8) & 1023);
    const int b  = (int)(i4 >> 18);
    float4 w = ((const float4*)Wt)[n * 256 + j4];
    float4 g = ((const float4*)pk)[b * 256 + j4];
    const float S = 16384.0f;
    __half2 h0 = __floats2half2_rn(w.x * g.x * S, w.y * g.y * S);
    __half2 h1 = __floats2half2_rn(w.z * g.z * S, w.w * g.w * S);
    ((__half2*)wtgh)[2 * i4]     = h0;
    ((__half2*)wtgh)[2 * i4 + 1] = h1;
}

// ============================================================================
extern "C" void kernel_launch(void* const* d_in, const int* in_sizes, int n_in,
                              void* d_out, int out_size)
{
    const float* X    = (const float*)d_in[0];
    const float* mask = (const float*)d_in[1];
    const float* Wq   = (const float*)d_in[2];
    const float* bq   = (const float*)d_in[3];
    const float* Wqa  = (const float*)d_in[4];
    const float* bqa  = (const float*)d_in[5];
    const float* Wk   = (const float*)d_in[6];
    const float* bk   = (const float*)d_in[7];
    const float* Wka  = (const float*)d_in[8];
    const float* bka  = (const float*)d_in[9];
    const float* Wt   = (const float*)d_in[10];
    const float* bt   = (const float*)d_in[11];
    float* out = (float*)d_out;

    float *qs, *ks, *pq, *pk, *part;
    float2 *stq, *stk;
    __half *xh, *mqh, *mkh, *wqh, *wkh, *wtgh;
    cudaGetSymbolAddress((void**)&qs, g_qs);
    cudaGetSymbolAddress((void**)&ks, g_ks);
    cudaGetSymbolAddress((void**)&pq, g_pq);
    cudaGetSymbolAddress((void**)&pk, g_pk);
    cudaGetSymbolAddress((void**)&part, g_part);
    cudaGetSymbolAddress((void**)&stq, g_stq);
    cudaGetSymbolAddress((void**)&stk, g_stk);
    cudaGetSymbolAddress((void**)&xh, g_xh);
    cudaGetSymbolAddress((void**)&mqh, g_mqh);
    cudaGetSymbolAddress((void**)&mkh, g_mkh);
    cudaGetSymbolAddress((void**)&wqh, g_wqh);
    cudaGetSymbolAddress((void**)&wkh, g_wkh);
    cudaGetSymbolAddress((void**)&wtgh, g_wtgh);

    cudaFuncSetAttribute(gemm_fp16<true, false, true, false>,
                         cudaFuncAttributeMaxDynamicSharedMemorySize, (int)GEMM_SMEM);
    cudaFuncSetAttribute(gemm_fp16<false, true, false, true>,
                         cudaFuncAttributeMaxDynamicSharedMemorySize, (int)GEMM_SMEM);
    cudaFuncSetAttribute(score_mma,
                         cudaFuncAttributeMaxDynamicSharedMemorySize, (int)SC_SMEM);

    const float* nullf = nullptr;

    // 0) fp16 conversions
    f2h_kernel<<<(MROWS * HID / 4 + 255) / 256, 256>>>(X, xh, MROWS * HID / 4);
    f2h_kernel<<<(HID * HID / 4 + 255) / 256, 256>>>(Wq, wqh, HID * HID / 4);
    f2h_kernel<<<(HID * HID / 4 + 255) / 256, 256>>>(Wk, wkh, HID * HID / 4);

    // 1) fused: mqh = X@Wq^T + bq ; mkh = X@Wk^T + bk  (fp16 outputs)
    gemm_fp16<true, false, true, false><<<dim3(16, MROWS / BM), 128, GEMM_SMEM>>>(
        xh, wqh, wkh, bq, bk, (const __half*)nullptr, (float*)nullptr, mqh, mkh);

    // 2) q scores -> pooled_q
    score_mma<<<MROWS / 128, 256, SC_SMEM>>>(mqh, Wqa, bqa, nullf, qs);
    stats_kernel<<<BATCH * NHEAD, 256>>>(qs, mask, stq);
    accum_kernel<<<BATCH * NHEAD * 8, 256>>>(mqh, qs, mask, stq, part);
    finalize_kernel<<<BATCH * HID / 256, 256>>>(part, nullf, pq);

    // 3) qk scores (gate folded into Wka) -> pooled_k (post-gate pq)
    score_mma<<<MROWS / 128, 256, SC_SMEM>>>(mkh, Wka, bka, pq, ks);
    stats_kernel<<<BATCH * NHEAD, 256>>>(ks, mask, stk);
    accum_kernel<<<BATCH * NHEAD * 8, 256>>>(mkh, ks, mask, stk, part);
    finalize_kernel<<<BATCH * HID / 256, 256>>>(part, pq, pk);

    // 4) wtgh = Wt * pk_full[b] * 2^14 ; out = mqh @ wtgh[b]^T * 2^-14 + bt + mqh
    wtg_kernel<<<(BATCH * HID * HID / 4) / 256, 256>>>(Wt, pk, wtgh);
    gemm_fp16<false, true, false, true><<<dim3(8, MROWS / BM), 128, GEMM_SMEM>>>(
        mqh, wtgh, (const __half*)nullptr, bt, nullf, mqh, out,
        (__half*)nullptr, (__half*)nullptr);
}

// round 11
// speedup vs baseline: 2.8483x; 1.0121x over previous
#include <cuda_runtime.h>
#include <cuda_fp16.h>
#include <cstdint>
#include <cstddef>

#define BATCH 8
#define SEQ   4096
#define HID   1024
#define NHEAD 16
#define MROWS (BATCH * SEQ)   // 32768

// ---------------- scratch (device globals; allocations forbidden) ----------
__device__ __half g_xh[(size_t)MROWS * HID];
__device__ __half g_mqh[(size_t)MROWS * HID];
__device__ __half g_mkh[(size_t)MROWS * HID];
__device__ __half g_wqh[(size_t)HID * HID];
__device__ __half g_wkh[(size_t)HID * HID];
__device__ __half g_wtgh[(size_t)BATCH * HID * HID];
__device__ float  g_qs[(size_t)MROWS * NHEAD];
__device__ float  g_ks[(size_t)MROWS * NHEAD];
__device__ float  g_pq[BATCH * HID];
__device__ float  g_pk[BATCH * HID];
__device__ float2 g_stq[BATCH * NHEAD];
__device__ float2 g_stk[BATCH * NHEAD];
__device__ float  g_part[BATCH * NHEAD * 8 * 64];

#define LDSM_X4(r0, r1, r2, r3, addr)                                             \
    asm volatile("ldmatrix.sync.aligned.m8n8.x4.shared.b16 {%0,%1,%2,%3}, [%4];"  \
                 : "=r"(r0), "=r"(r1), "=r"(r2), "=r"(r3) : "r"(addr))

#define BAR_ARRIVE(id) asm volatile("bar.arrive %0, 256;" :: "r"(id) : "memory")
#define BAR_SYNCN(id)  asm volatile("bar.sync %0, 256;"   :: "r"(id) : "memory")

// ============================================================================
// fp16 GEMM: acc[m,n] = sum_k A[m,k]*W[n,k]; out = acc*sc + bias (+resid)
// BM=64, BN=128, BK=64; 128 thr (4 warps, 2x2 grid, warp tile 32x64);
// 2-stage cp.async with SPLIT producer/consumer named barriers:
//   A_b (ids 1,2): data-ready  (arrive after own wait_group; sync before LDSM)
//   F_b (ids 3,4): buffer-free (arrive after compute;      sync before refill)
// 4 CTAs/SM (55.3KB smem, <=128 regs).
// DUAL: grid.x=16, nb<8 -> (W0,b0,H0), else (W1,b1,H1).
// PERB: W indexed per batch. OUTH: write __half outputs H0/H1.
// !OUTH: write float Cf with fp16 residual residH added. SCALED: acc *= 2^-14.
// ============================================================================
constexpr int BM = 64, BN = 128, BK = 64;
constexpr int SROW = 72;                      // halves per smem row (144B, padded)
constexpr int NKB = HID / BK;                 // 16
constexpr int STGH = (BM + BN) * SROW;        // 13824 halves per stage
constexpr size_t GEMM_SMEM = (size_t)2 * STGH * sizeof(__half);  // 55296 B

template <bool DUAL, bool PERB, bool OUTH, bool SCALED>
__global__ void __launch_bounds__(128, 4) gemm_fp16(
    const __half* __restrict__ A, const __half* __restrict__ W0, const __half* __restrict__ W1,
    const float* __restrict__ b0, const float* __restrict__ b1,
    const __half* __restrict__ residH, float* __restrict__ Cf,
    __half* __restrict__ H0, __half* __restrict__ H1)
{
    extern __shared__ __half smh[];
    const int tid = threadIdx.x;
    const int m0 = blockIdx.y * BM;
    int nb = blockIdx.x;

    const __half* W; const float* bias; __half* H = H0;
    if (DUAL) {
        if (nb < 8) { W = W0; bias = b0; H = H0; }
        else        { nb -= 8; W = W1; bias = b1; H = H1; }
    } else {
        W = W0 + (PERB ? (size_t)(m0 / SEQ) * HID * HID : 0);
        bias = b0;
    }
    const int n0 = nb * BN;

    const int warp = tid >> 5, lane = tid & 31;
    const int wm = warp & 1, wn = warp >> 1;    // 2x2 warps -> 32x64 per warp
    const int grp = lane >> 2, qid = lane & 3;

    const int lr = lane & 7;
    const int lh = (lane >> 3) & 1;
    const int lk = (lane >> 4) & 1;

    uint32_t offA[2], offB[4];
#pragma unroll
    for (int mt = 0; mt < 2; mt++)
        offA[mt] = (uint32_t)(((wm * 32 + mt * 16 + lh * 8 + lr) * SROW + lk * 8) * 2);
#pragma unroll
    for (int p = 0; p < 4; p++)
        offB[p] = (uint32_t)(((wn * 64 + p * 16 + lk * 8 + lr) * SROW + lh * 8) * 2
                             + BM * SROW * 2);

    const uint32_t smBase = (uint32_t)__cvta_generic_to_shared(smh);

    float acc[2][8][4];
#pragma unroll
    for (int i = 0; i < 2; i++)
#pragma unroll
        for (int j = 0; j < 8; j++)
#pragma unroll
            for (int l = 0; l < 4; l++) acc[i][j][l] = 0.f;

    const __half* Ab = A + (size_t)m0 * HID;
    const __half* Wb = W + (size_t)n0 * HID;

    auto loadTile = [&](int kb, int s) {
        __half* sa = smh + s * STGH;
        __half* sb = sa + BM * SROW;
        const __half* Ag = Ab + kb * BK;
        const __half* Wg = Wb + kb * BK;
#pragma unroll
        for (int i = 0; i < 12; i++) {         // 1536 granules of 16B
            const int id = tid + 128 * i;
            if (id < 512) {                    // A: 64 rows x 8 granules
                const int r = id >> 3, c = id & 7;
                uint32_t d = (uint32_t)__cvta_generic_to_shared(sa + r * SROW + c * 8);
                asm volatile("cp.async.cg.shared.global [%0], [%1], 16;"
                             :: "r"(d), "l"(Ag + (size_t)r * HID + c * 8));
            } else {                           // B: 128 rows x 8 granules
                const int id2 = id - 512;
                const int r = id2 >> 3, c = id2 & 7;
                uint32_t d = (uint32_t)__cvta_generic_to_shared(sb + r * SROW + c * 8);
                asm volatile("cp.async.cg.shared.global [%0], [%1], 16;"
                             :: "r"(d), "l"(Wg + (size_t)r * HID + c * 8));
            }
        }
        asm volatile("cp.async.commit_group;");
    };

    loadTile(0, 0);

    for (int kb = 0; kb < NKB; kb++) {
        const int b = kb & 1, onb = b ^ 1;
        asm volatile("cp.async.wait_group 0;");   // my loads for tile kb landed
        BAR_ARRIVE(1 + b);                        // A_b: my data for kb ready
        if (kb >= 1) BAR_SYNCN(3 + onb);          // F_onb: buffer onb freed (compute kb-1 done)
        if (kb + 1 < NKB) loadTile(kb + 1, onb);
        BAR_SYNCN(1 + b);                         // A_b: ALL data for kb visible

        const uint32_t stBase = smBase + b * (STGH * 2);

#pragma unroll
        for (int ks = 0; ks < 4; ks++) {
            const uint32_t kkb = ks * 32;
            uint32_t af[2][4], bf[8][2];
#pragma unroll
            for (int mt = 0; mt < 2; mt++)
                LDSM_X4(af[mt][0], af[mt][1], af[mt][2], af[mt][3],
                        stBase + offA[mt] + kkb);
#pragma unroll
            for (int p = 0; p < 4; p++)
                LDSM_X4(bf[2 * p][0], bf[2 * p][1], bf[2 * p + 1][0], bf[2 * p + 1][1],
                        stBase + offB[p] + kkb);
#pragma unroll
            for (int mt = 0; mt < 2; mt++)
#pragma unroll
                for (int nt = 0; nt < 8; nt++) {
                    asm volatile(
                        "mma.sync.aligned.m16n8k16.row.col.f32.f16.f16.f32 "
                        "{%0,%1,%2,%3}, {%4,%5,%6,%7}, {%8,%9}, {%0,%1,%2,%3};"
                        : "+f"(acc[mt][nt][0]), "+f"(acc[mt][nt][1]),
                          "+f"(acc[mt][nt][2]), "+f"(acc[mt][nt][3])
                        : "r"(af[mt][0]), "r"(af[mt][1]), "r"(af[mt][2]), "r"(af[mt][3]),
                          "r"(bf[nt][0]), "r"(bf[nt][1]));
                }
        }
        BAR_ARRIVE(3 + b);                        // F_b: I'm done reading buffer b
    }

    const float sc = SCALED ? 6.103515625e-5f : 1.0f;   // 2^-14

    // epilogue
#pragma unroll
    for (int mt = 0; mt < 2; mt++) {
        const int r0 = m0 + wm * 32 + mt * 16 + grp;
#pragma unroll
        for (int nt = 0; nt < 8; nt++) {
            const int c = n0 + wn * 64 + nt * 8 + qid * 2;
            const float bv0 = bias[c], bv1 = bias[c + 1];
            float v0 = acc[mt][nt][0] * sc + bv0, v1 = acc[mt][nt][1] * sc + bv1;
            float v2 = acc[mt][nt][2] * sc + bv0, v3 = acc[mt][nt][3] * sc + bv1;
            if (OUTH) {
                *(__half2*)(H + (size_t)r0 * HID + c)       = __floats2half2_rn(v0, v1);
                *(__half2*)(H + (size_t)(r0 + 8) * HID + c) = __floats2half2_rn(v2, v3);
            } else {
                __half2 ra = *(const __half2*)(residH + (size_t)r0 * HID + c);
                __half2 rb = *(const __half2*)(residH + (size_t)(r0 + 8) * HID + c);
                float2 raf = __half22float2(ra), rbf = __half22float2(rb);
                float2 oa = {v0 + raf.x, v1 + raf.y};
                float2 ob = {v2 + rbf.x, v3 + rbf.y};
                *(float2*)(Cf + (size_t)r0 * HID + c) = oa;
                *(float2*)(Cf + (size_t)(r0 + 8) * HID + c) = ob;
            }
        }
    }
}

// ============================================================================
// score_mma: out[m,h] = sum_k src[m,k]*(W[h,k]*(gate?g[b,k]:1)) + bias[h]
// Tensor-core skinny GEMM (N=16). Gated W resident in smem as fp16
// (row stride 1032 halves -> conflict-free LDSM); A 3-stage cp.async.
// 256 thr (8 warps x m16 = 128 rows/CTA), m16n8k16.
// ============================================================================
constexpr int SC_WROW = 1032;                 // Wg smem row stride (halves)
constexpr int SC_SROW = 72;                   // A smem row stride (halves)
constexpr int SC_NKT  = HID / 64;             // 16 K-tiles of 64
constexpr size_t SC_SMEM = (size_t)(16 * SC_WROW + 3 * 128 * SC_SROW) * 2; // 88320 B

__global__ void __launch_bounds__(256, 2) score_mma(
    const __half* __restrict__ src, const float* __restrict__ W,
    const float* __restrict__ bias, const float* __restrict__ gate,
    float* __restrict__ out)
{
    extern __shared__ __half ssc[];
    __half* sWg = ssc;                        // 16 x 1032
    __half* sA  = ssc + 16 * SC_WROW;         // 3 x 128 x 72
    const int tid = threadIdx.x, warp = tid >> 5, lane = tid & 31;
    const int row0 = blockIdx.x * 128;
    const int b = row0 / SEQ;

    // build gated fp16 weight in smem
    for (int i = tid; i < NHEAD * HID; i += 256) {
        const int h = i >> 10, k = i & 1023;
        float w = W[i];
        if (gate) w *= gate[b * HID + k];
        sWg[h * SC_WROW + k] = __float2half_rn(w);
    }

    const __half* Ab = src + (size_t)row0 * HID;
    auto loadA = [&](int kt, int s) {
        __half* sa = sA + s * 128 * SC_SROW;
        const __half* Ag = Ab + kt * 64;
#pragma unroll
        for (int i = 0; i < 4; i++) {          // 1024 granules of 16B
            const int id = tid + 256 * i;
            const int r = id >> 3, c = id & 7;
            uint32_t d = (uint32_t)__cvta_generic_to_shared(sa + r * SC_SROW + c * 8);
            asm volatile("cp.async.cg.shared.global [%0], [%1], 16;"
                         :: "r"(d), "l"(Ag + (size_t)r * HID + c * 8));
        }
        asm volatile("cp.async.commit_group;");
    };

    loadA(0, 0);
    loadA(1, 1);
    __syncthreads();                           // Wg visible to all warps

    const int lr = lane & 7;
    const int lh = (lane >> 3) & 1;
    const int lk = lane >> 4;
    const uint32_t offA = (uint32_t)(((warp * 16 + lh * 8 + lr) * SC_SROW + lk * 8) * 2);
    const uint32_t offBW = (uint32_t)(((lk * 8 + lr) * SC_WROW + lh * 8) * 2);
    const uint32_t smA = (uint32_t)__cvta_generic_to_shared(sA);
    const uint32_t smW = (uint32_t)__cvta_generic_to_shared(sWg);

    float acc0[4] = {0.f, 0.f, 0.f, 0.f};
    float acc1[4] = {0.f, 0.f, 0.f, 0.f};

    int s = 0;
    for (int kt = 0; kt < SC_NKT; kt++) {
        if (kt + 1 < SC_NKT) asm volatile("cp.async.wait_group 1;");
        else                 asm volatile("cp.async.wait_group 0;");
        __syncthreads();
        if (kt + 2 < SC_NKT) loadA(kt + 2, (s + 2) % 3);

        const uint32_t stA = smA + s * (128 * SC_SROW * 2);
#pragma unroll
        for (int ks = 0; ks < 4; ks++) {
            uint32_t a0, a1, a2, a3, b0, b1, b2, b3;
            LDSM_X4(a0, a1, a2, a3, stA + offA + ks * 32);
            LDSM_X4(b0, b1, b2, b3, smW + offBW + (uint32_t)((kt * 64 + ks * 16) * 2));
            asm volatile(
                "mma.sync.aligned.m16n8k16.row.col.f32.f16.f16.f32 "
                "{%0,%1,%2,%3}, {%4,%5,%6,%7}, {%8,%9}, {%0,%1,%2,%3};"
                : "+f"(acc0[0]), "+f"(acc0[1]), "+f"(acc0[2]), "+f"(acc0[3])
                : "r"(a0), "r"(a1), "r"(a2), "r"(a3), "r"(b0), "r"(b1));
            asm volatile(
                "mma.sync.aligned.m16n8k16.row.col.f32.f16.f16.f32 "
                "{%0,%1,%2,%3}, {%4,%5,%6,%7}, {%8,%9}, {%0,%1,%2,%3};"
                : "+f"(acc1[0]), "+f"(acc1[1]), "+f"(acc1[2]), "+f"(acc1[3])
                : "r"(a0), "r"(a1), "r"(a2), "r"(a3), "r"(b2), "r"(b3));
        }
        s = (s + 1) % 3;
    }

    const int grp = lane >> 2, qid = lane & 3;
    const int rlo = row0 + warp * 16 + grp;
    float2 bv0 = ((const float2*)bias)[qid];
    float2 bv1 = ((const float2*)bias)[4 + qid];
    float2 o;
    o.x = acc0[0] + bv0.x; o.y = acc0[1] + bv0.y;
    *(float2*)(out + (size_t)rlo * NHEAD + qid * 2) = o;
    o.x = acc0[2] + bv0.x; o.y = acc0[3] + bv0.y;
    *(float2*)(out + (size_t)(rlo + 8) * NHEAD + qid * 2) = o;
    o.x = acc1[0] + bv1.x; o.y = acc1[1] + bv1.y;
    *(float2*)(out + (size_t)rlo * NHEAD + 8 + qid * 2) = o;
    o.x = acc1[2] + bv1.x; o.y = acc1[3] + bv1.y;
    *(float2*)(out + (size_t)(rlo + 8) * NHEAD + 8 + qid * 2) = o;
}

// ============================================================================
// fp32 -> fp16 converter (vectorized by 4)
// ============================================================================
__global__ void f2h_kernel(const float* __restrict__ src, __half* __restrict__ dst, int n4)
{
    const int i = blockIdx.x * 256 + threadIdx.x;
    if (i >= n4) return;
    float4 v = ((const float4*)src)[i];
    ((__half2*)dst)[2 * i]     = __floats2half2_rn(v.x, v.y);
    ((__half2*)dst)[2 * i + 1] = __floats2half2_rn(v.z, v.w);
}

// ============================================================================
__global__ void stats_kernel(const float* __restrict__ scores,
                             const float* __restrict__ mask, float2* __restrict__ st)
{
    __shared__ float red[256];
    const int bh = blockIdx.x, b = bh >> 4, h = bh & 15;
    const int t = threadIdx.x;
    const float* sc = scores + (size_t)b * SEQ * NHEAD + h;
    const float* mk = mask + b * SEQ;
    float mx = -1e30f;
    for (int s = t; s < SEQ; s += 256) mx = fmaxf(mx, sc[(size_t)s * NHEAD] * 0.125f + mk[s]);
    red[t] = mx; __syncthreads();
    for (int o = 128; o; o >>= 1) { if (t < o) red[t] = fmaxf(red[t], red[t + o]); __syncthreads(); }
    mx = red[0]; __syncthreads();
    float ps = 0.f;
    for (int s = t; s < SEQ; s += 256) ps += __expf(sc[(size_t)s * NHEAD] * 0.125f + mk[s] - mx);
    red[t] = ps; __syncthreads();
    for (int o = 128; o; o >>= 1) { if (t < o) red[t] += red[t + o]; __syncthreads(); }
    if (t == 0) st[bh] = make_float2(mx, red[0]);
}

// ============================================================================
// Pool partials from fp16 src: block = (bh, 512-row chunk); deterministic
// ============================================================================
__global__ void accum_kernel(const __half* __restrict__ src,
                             const float* __restrict__ scores,
                             const float* __restrict__ mask,
                             const float2* __restrict__ st, float* __restrict__ part)
{
    __shared__ float red[256];
    const int blk = blockIdx.x, bh = blk >> 3, ch = blk & 7;
    const int b = bh >> 4, h = bh & 15;
    const int t = threadIdx.x, d = t & 63, sg = t >> 6;
    const float2 s2 = st[bh];
    const float mx = s2.x, inv = 1.0f / s2.y;
    const __half* base = src + (size_t)b * SEQ * HID + h * 64 + d;
    const float* sc = scores + (size_t)b * SEQ * NHEAD + h;
    const float* mk = mask + b * SEQ;
    float acc = 0.f;
    const int s0 = ch * 512;
    for (int s = s0 + sg; s < s0 + 512; s += 4) {
        float w = __expf(sc[(size_t)s * NHEAD] * 0.125f + mk[s] - mx);
        acc += w * __half2float(base[(size_t)s * HID]);
    }
    red[t] = acc; __syncthreads();
    if (sg == 0)
        part[(size_t)blk * 64 + d] = (red[d] + red[64 + d] + red[128 + d] + red[192 + d]) * inv;
}

__global__ void finalize_kernel(const float* __restrict__ part,
                                const float* __restrict__ postgate, float* __restrict__ out)
{
    const int idx = blockIdx.x * 256 + threadIdx.x;   // 8192
    const int bh = idx >> 6, d = idx & 63;
    float v = 0.f;
#pragma unroll
    for (int c = 0; c < 8; c++) v += part[(size_t)(bh * 8 + c) * 64 + d];
    if (postgate) v *= postgate[idx];
    out[idx] = v;
}

// wtgh[b,n,k] = (half)(Wt[n,k] * pk[b,k] * 2^14)   (scale avoids fp16 subnormals)
__global__ void wtg_kernel(const float* __restrict__ Wt, const float* __restrict__ pk,
                           __half* __restrict__ wtgh)
{
    const size_t i4 = (size_t)blockIdx.x * 256 + threadIdx.x;  // 2,097,152
    const int j4 = (int)(i4 & 255);
    const int n  = (int)((i4 >> 8) & 1023);
    const int b  = (int)(i4 >> 18);
    float4 w = ((const float4*)Wt)[n * 256 + j4];
    float4 g = ((const float4*)pk)[b * 256 + j4];
    const float S = 16384.0f;
    __half2 h0 = __floats2half2_rn(w.x * g.x * S, w.y * g.y * S);
    __half2 h1 = __floats2half2_rn(w.z * g.z * S, w.w * g.w * S);
    ((__half2*)wtgh)[2 * i4]     = h0;
    ((__half2*)wtgh)[2 * i4 + 1] = h1;
}

// ============================================================================
extern "C" void kernel_launch(void* const* d_in, const int* in_sizes, int n_in,
                              void* d_out, int out_size)
{
    const float* X    = (const float*)d_in[0];
    const float* mask = (const float*)d_in[1];
    const float* Wq   = (const float*)d_in[2];
    const float* bq   = (const float*)d_in[3];
    const float* Wqa  = (const float*)d_in[4];
    const float* bqa  = (const float*)d_in[5];
    const float* Wk   = (const float*)d_in[6];
    const float* bk   = (const float*)d_in[7];
    const float* Wka  = (const float*)d_in[8];
    const float* bka  = (const float*)d_in[9];
    const float* Wt   = (const float*)d_in[10];
    const float* bt   = (const float*)d_in[11];
    float* out = (float*)d_out;

    float *qs, *ks, *pq, *pk, *part;
    float2 *stq, *stk;
    __half *xh, *mqh, *mkh, *wqh, *wkh, *wtgh;
    cudaGetSymbolAddress((void**)&qs, g_qs);
    cudaGetSymbolAddress((void**)&ks, g_ks);
    cudaGetSymbolAddress((void**)&pq, g_pq);
    cudaGetSymbolAddress((void**)&pk, g_pk);
    cudaGetSymbolAddress((void**)&part, g_part);
    cudaGetSymbolAddress((void**)&stq, g_stq);
    cudaGetSymbolAddress((void**)&stk, g_stk);
    cudaGetSymbolAddress((void**)&xh, g_xh);
    cudaGetSymbolAddress((void**)&mqh, g_mqh);
    cudaGetSymbolAddress((void**)&mkh, g_mkh);
    cudaGetSymbolAddress((void**)&wqh, g_wqh);
    cudaGetSymbolAddress((void**)&wkh, g_wkh);
    cudaGetSymbolAddress((void**)&wtgh, g_wtgh);

    cudaFuncSetAttribute(gemm_fp16<true, false, true, false>,
                         cudaFuncAttributeMaxDynamicSharedMemorySize, (int)GEMM_SMEM);
    cudaFuncSetAttribute(gemm_fp16<false, true, false, true>,
                         cudaFuncAttributeMaxDynamicSharedMemorySize, (int)GEMM_SMEM);
    cudaFuncSetAttribute(score_mma,
                         cudaFuncAttributeMaxDynamicSharedMemorySize, (int)SC_SMEM);

    const float* nullf = nullptr;

    // 0) fp16 conversions
    f2h_kernel<<<(MROWS * HID / 4 + 255) / 256, 256>>>(X, xh, MROWS * HID / 4);
    f2h_kernel<<<(HID * HID / 4 + 255) / 256, 256>>>(Wq, wqh, HID * HID / 4);
    f2h_kernel<<<(HID * HID / 4 + 255) / 256, 256>>>(Wk, wkh, HID * HID / 4);

    // 1) fused: mqh = X@Wq^T + bq ; mkh = X@Wk^T + bk  (fp16 outputs)
    gemm_fp16<true, false, true, false><<<dim3(16, MROWS / BM), 128, GEMM_SMEM>>>(
        xh, wqh, wkh, bq, bk, (const __half*)nullptr, (float*)nullptr, mqh, mkh);

    // 2) q scores -> pooled_q
    score_mma<<<MROWS / 128, 256, SC_SMEM>>>(mqh, Wqa, bqa, nullf, qs);
    stats_kernel<<<BATCH * NHEAD, 256>>>(qs, mask, stq);
    accum_kernel<<<BATCH * NHEAD * 8, 256>>>(mqh, qs, mask, stq, part);
    finalize_kernel<<<BATCH * HID / 256, 256>>>(part, nullf, pq);

    // 3) qk scores (gate folded into Wka) -> pooled_k (post-gate pq)
    score_mma<<<MROWS / 128, 256, SC_SMEM>>>(mkh, Wka, bka, pq, ks);
    stats_kernel<<<BATCH * NHEAD, 256>>>(ks, mask, stk);
    accum_kernel<<<BATCH * NHEAD * 8, 256>>>(mkh, ks, mask, stk, part);
    finalize_kernel<<<BATCH * HID / 256, 256>>>(part, pq, pk);

    // 4) wtgh = Wt * pk_full[b] * 2^14 ; out = mqh @ wtgh[b]^T * 2^-14 + bt + mqh
    wtg_kernel<<<(BATCH * HID * HID / 4) / 256, 256>>>(Wt, pk, wtgh);
    gemm_fp16<false, true, false, true><<<dim3(8, MROWS / BM), 128, GEMM_SMEM>>>(
        mqh, wtgh, (const __half*)nullptr, bt, nullf, mqh, out,
        (__half*)nullptr, (__half*)nullptr);
}

// round 12
// speedup vs baseline: 3.0281x; 1.0631x over previous
#include <cuda_runtime.h>
#include <cuda_fp16.h>
#include <cstdint>
#include <cstddef>

#define BATCH 8
#define SEQ   4096
#define HID   1024
#define NHEAD 16
#define MROWS (BATCH * SEQ)   // 32768

// ---------------- scratch (device globals; allocations forbidden) ----------
__device__ __half g_xh[(size_t)MROWS * HID];
__device__ __half g_mqh[(size_t)MROWS * HID];
__device__ __half g_mkh[(size_t)MROWS * HID];
__device__ __half g_wqh[(size_t)HID * HID];
__device__ __half g_wkh[(size_t)HID * HID];
__device__ __half g_wtgh[(size_t)BATCH * HID * HID];
__device__ float  g_qs[(size_t)MROWS * NHEAD];
__device__ float  g_ks[(size_t)MROWS * NHEAD];
__device__ float  g_pq[BATCH * HID];
__device__ float  g_pk[BATCH * HID];
__device__ float  g_part[BATCH * NHEAD * 8 * 64];
__device__ float2 g_ms[BATCH * NHEAD * 8];

#define LDSM_X4(r0, r1, r2, r3, addr)                                             \
    asm volatile("ldmatrix.sync.aligned.m8n8.x4.shared.b16 {%0,%1,%2,%3}, [%4];"  \
                 : "=r"(r0), "=r"(r1), "=r"(r2), "=r"(r3) : "r"(addr))

#define BAR_ARRIVE(id) asm volatile("bar.arrive %0, 256;" :: "r"(id) : "memory")
#define BAR_SYNCN(id)  asm volatile("bar.sync %0, 256;"   :: "r"(id) : "memory")

// ============================================================================
// fp16 GEMM: acc[m,n] = sum_k A[m,k]*W[n,k]; out = acc*sc + bias (+resid)
// BM=64, BN=128, BK=64; 128 thr (4 warps, 2x2 grid, warp tile 32x64);
// 2-stage cp.async with split producer/consumer named barriers.
// 4 CTAs/SM (55.3KB smem, <=128 regs).
// DUAL: grid.x=16, nb<8 -> (W0,b0,H0), else (W1,b1,H1).
// PERB: W indexed per batch. OUTH: write __half outputs H0/H1.
// !OUTH: write float Cf with fp16 residual residH added. SCALED: acc *= 2^-14.
// ============================================================================
constexpr int BM = 64, BN = 128, BK = 64;
constexpr int SROW = 72;                      // halves per smem row (144B, padded)
constexpr int NKB = HID / BK;                 // 16
constexpr int STGH = (BM + BN) * SROW;        // 13824 halves per stage
constexpr size_t GEMM_SMEM = (size_t)2 * STGH * sizeof(__half);  // 55296 B

template <bool DUAL, bool PERB, bool OUTH, bool SCALED>
__global__ void __launch_bounds__(128, 4) gemm_fp16(
    const __half* __restrict__ A, const __half* __restrict__ W0, const __half* __restrict__ W1,
    const float* __restrict__ b0, const float* __restrict__ b1,
    const __half* __restrict__ residH, float* __restrict__ Cf,
    __half* __restrict__ H0, __half* __restrict__ H1)
{
    extern __shared__ __half smh[];
    const int tid = threadIdx.x;
    const int m0 = blockIdx.y * BM;
    int nb = blockIdx.x;

    const __half* W; const float* bias; __half* H = H0;
    if (DUAL) {
        if (nb < 8) { W = W0; bias = b0; H = H0; }
        else        { nb -= 8; W = W1; bias = b1; H = H1; }
    } else {
        W = W0 + (PERB ? (size_t)(m0 / SEQ) * HID * HID : 0);
        bias = b0;
    }
    const int n0 = nb * BN;

    const int warp = tid >> 5, lane = tid & 31;
    const int wm = warp & 1, wn = warp >> 1;    // 2x2 warps -> 32x64 per warp
    const int grp = lane >> 2, qid = lane & 3;

    const int lr = lane & 7;
    const int lh = (lane >> 3) & 1;
    const int lk = (lane >> 4) & 1;

    uint32_t offA[2], offB[4];
#pragma unroll
    for (int mt = 0; mt < 2; mt++)
        offA[mt] = (uint32_t)(((wm * 32 + mt * 16 + lh * 8 + lr) * SROW + lk * 8) * 2);
#pragma unroll
    for (int p = 0; p < 4; p++)
        offB[p] = (uint32_t)(((wn * 64 + p * 16 + lk * 8 + lr) * SROW + lh * 8) * 2
                             + BM * SROW * 2);

    const uint32_t smBase = (uint32_t)__cvta_generic_to_shared(smh);

    float acc[2][8][4];
#pragma unroll
    for (int i = 0; i < 2; i++)
#pragma unroll
        for (int j = 0; j < 8; j++)
#pragma unroll
            for (int l = 0; l < 4; l++) acc[i][j][l] = 0.f;

    const __half* Ab = A + (size_t)m0 * HID;
    const __half* Wb = W + (size_t)n0 * HID;

    auto loadTile = [&](int kb, int s) {
        __half* sa = smh + s * STGH;
        __half* sb = sa + BM * SROW;
        const __half* Ag = Ab + kb * BK;
        const __half* Wg = Wb + kb * BK;
#pragma unroll
        for (int i = 0; i < 12; i++) {         // 1536 granules of 16B
            const int id = tid + 128 * i;
            if (id < 512) {                    // A: 64 rows x 8 granules
                const int r = id >> 3, c = id & 7;
                uint32_t d = (uint32_t)__cvta_generic_to_shared(sa + r * SROW + c * 8);
                asm volatile("cp.async.cg.shared.global [%0], [%1], 16;"
                             :: "r"(d), "l"(Ag + (size_t)r * HID + c * 8));
            } else {                           // B: 128 rows x 8 granules
                const int id2 = id - 512;
                const int r = id2 >> 3, c = id2 & 7;
                uint32_t d = (uint32_t)__cvta_generic_to_shared(sb + r * SROW + c * 8);
                asm volatile("cp.async.cg.shared.global [%0], [%1], 16;"
                             :: "r"(d), "l"(Wg + (size_t)r * HID + c * 8));
            }
        }
        asm volatile("cp.async.commit_group;");
    };

    loadTile(0, 0);

    for (int kb = 0; kb < NKB; kb++) {
        const int b = kb & 1, onb = b ^ 1;
        asm volatile("cp.async.wait_group 0;");   // my loads for tile kb landed
        BAR_ARRIVE(1 + b);                        // A_b: my data for kb ready
        if (kb >= 1) BAR_SYNCN(3 + onb);          // F_onb: buffer onb freed
        if (kb + 1 < NKB) loadTile(kb + 1, onb);
        BAR_SYNCN(1 + b);                         // A_b: ALL data for kb visible

        const uint32_t stBase = smBase + b * (STGH * 2);

#pragma unroll
        for (int ks = 0; ks < 4; ks++) {
            const uint32_t kkb = ks * 32;
            uint32_t af[2][4], bf[8][2];
#pragma unroll
            for (int mt = 0; mt < 2; mt++)
                LDSM_X4(af[mt][0], af[mt][1], af[mt][2], af[mt][3],
                        stBase + offA[mt] + kkb);
#pragma unroll
            for (int p = 0; p < 4; p++)
                LDSM_X4(bf[2 * p][0], bf[2 * p][1], bf[2 * p + 1][0], bf[2 * p + 1][1],
                        stBase + offB[p] + kkb);
#pragma unroll
            for (int mt = 0; mt < 2; mt++)
#pragma unroll
                for (int nt = 0; nt < 8; nt++) {
                    asm volatile(
                        "mma.sync.aligned.m16n8k16.row.col.f32.f16.f16.f32 "
                        "{%0,%1,%2,%3}, {%4,%5,%6,%7}, {%8,%9}, {%0,%1,%2,%3};"
                        : "+f"(acc[mt][nt][0]), "+f"(acc[mt][nt][1]),
                          "+f"(acc[mt][nt][2]), "+f"(acc[mt][nt][3])
                        : "r"(af[mt][0]), "r"(af[mt][1]), "r"(af[mt][2]), "r"(af[mt][3]),
                          "r"(bf[nt][0]), "r"(bf[nt][1]));
                }
        }
        BAR_ARRIVE(3 + b);                        // F_b: I'm done reading buffer b
    }

    const float sc = SCALED ? 6.103515625e-5f : 1.0f;   // 2^-14

    // epilogue
#pragma unroll
    for (int mt = 0; mt < 2; mt++) {
        const int r0 = m0 + wm * 32 + mt * 16 + grp;
#pragma unroll
        for (int nt = 0; nt < 8; nt++) {
            const int c = n0 + wn * 64 + nt * 8 + qid * 2;
            const float bv0 = bias[c], bv1 = bias[c + 1];
            float v0 = acc[mt][nt][0] * sc + bv0, v1 = acc[mt][nt][1] * sc + bv1;
            float v2 = acc[mt][nt][2] * sc + bv0, v3 = acc[mt][nt][3] * sc + bv1;
            if (OUTH) {
                *(__half2*)(H + (size_t)r0 * HID + c)       = __floats2half2_rn(v0, v1);
                *(__half2*)(H + (size_t)(r0 + 8) * HID + c) = __floats2half2_rn(v2, v3);
            } else {
                __half2 ra = *(const __half2*)(residH + (size_t)r0 * HID + c);
                __half2 rb = *(const __half2*)(residH + (size_t)(r0 + 8) * HID + c);
                float2 raf = __half22float2(ra), rbf = __half22float2(rb);
                float2 oa = {v0 + raf.x, v1 + raf.y};
                float2 ob = {v2 + rbf.x, v3 + rbf.y};
                *(float2*)(Cf + (size_t)r0 * HID + c) = oa;
                *(float2*)(Cf + (size_t)(r0 + 8) * HID + c) = ob;
            }
        }
    }
}

// ============================================================================
// score_mma: out[m,h] = sum_k src[m,k]*(W[h,k]*(gate?g[b,k]:1)) + bias[h]
// Tensor-core skinny GEMM (N=16). Gated W resident in smem as fp16
// (row stride 1032 halves -> conflict-free LDSM); A 3-stage cp.async.
// 256 thr (8 warps x m16 = 128 rows/CTA), m16n8k16.
// ============================================================================
constexpr int SC_WROW = 1032;                 // Wg smem row stride (halves)
constexpr int SC_SROW = 72;                   // A smem row stride (halves)
constexpr int SC_NKT  = HID / 64;             // 16 K-tiles of 64
constexpr size_t SC_SMEM = (size_t)(16 * SC_WROW + 3 * 128 * SC_SROW) * 2; // 88320 B

__global__ void __launch_bounds__(256, 2) score_mma(
    const __half* __restrict__ src, const float* __restrict__ W,
    const float* __restrict__ bias, const float* __restrict__ gate,
    float* __restrict__ out)
{
    extern __shared__ __half ssc[];
    __half* sWg = ssc;                        // 16 x 1032
    __half* sA  = ssc + 16 * SC_WROW;         // 3 x 128 x 72
    const int tid = threadIdx.x, warp = tid >> 5, lane = tid & 31;
    const int row0 = blockIdx.x * 128;
    const int b = row0 / SEQ;

    // build gated fp16 weight in smem
    for (int i = tid; i < NHEAD * HID; i += 256) {
        const int h = i >> 10, k = i & 1023;
        float w = W[i];
        if (gate) w *= gate[b * HID + k];
        sWg[h * SC_WROW + k] = __float2half_rn(w);
    }

    const __half* Ab = src + (size_t)row0 * HID;
    auto loadA = [&](int kt, int s) {
        __half* sa = sA + s * 128 * SC_SROW;
        const __half* Ag = Ab + kt * 64;
#pragma unroll
        for (int i = 0; i < 4; i++) {          // 1024 granules of 16B
            const int id = tid + 256 * i;
            const int r = id >> 3, c = id & 7;
            uint32_t d = (uint32_t)__cvta_generic_to_shared(sa + r * SC_SROW + c * 8);
            asm volatile("cp.async.cg.shared.global [%0], [%1], 16;"
                         :: "r"(d), "l"(Ag + (size_t)r * HID + c * 8));
        }
        asm volatile("cp.async.commit_group;");
    };

    loadA(0, 0);
    loadA(1, 1);
    __syncthreads();                           // Wg visible to all warps

    const int lr = lane & 7;
    const int lh = (lane >> 3) & 1;
    const int lk = lane >> 4;
    const uint32_t offA = (uint32_t)(((warp * 16 + lh * 8 + lr) * SC_SROW + lk * 8) * 2);
    const uint32_t offBW = (uint32_t)(((lk * 8 + lr) * SC_WROW + lh * 8) * 2);
    const uint32_t smA = (uint32_t)__cvta_generic_to_shared(sA);
    const uint32_t smW = (uint32_t)__cvta_generic_to_shared(sWg);

    float acc0[4] = {0.f, 0.f, 0.f, 0.f};
    float acc1[4] = {0.f, 0.f, 0.f, 0.f};

    int s = 0;
    for (int kt = 0; kt < SC_NKT; kt++) {
        if (kt + 1 < SC_NKT) asm volatile("cp.async.wait_group 1;");
        else                 asm volatile("cp.async.wait_group 0;");
        __syncthreads();
        if (kt + 2 < SC_NKT) loadA(kt + 2, (s + 2) % 3);

        const uint32_t stA = smA + s * (128 * SC_SROW * 2);
#pragma unroll
        for (int ks = 0; ks < 4; ks++) {
            uint32_t a0, a1, a2, a3, b0, b1, b2, b3;
            LDSM_X4(a0, a1, a2, a3, stA + offA + ks * 32);
            LDSM_X4(b0, b1, b2, b3, smW + offBW + (uint32_t)((kt * 64 + ks * 16) * 2));
            asm volatile(
                "mma.sync.aligned.m16n8k16.row.col.f32.f16.f16.f32 "
                "{%0,%1,%2,%3}, {%4,%5,%6,%7}, {%8,%9}, {%0,%1,%2,%3};"
                : "+f"(acc0[0]), "+f"(acc0[1]), "+f"(acc0[2]), "+f"(acc0[3])
                : "r"(a0), "r"(a1), "r"(a2), "r"(a3), "r"(b0), "r"(b1));
            asm volatile(
                "mma.sync.aligned.m16n8k16.row.col.f32.f16.f16.f32 "
                "{%0,%1,%2,%3}, {%4,%5,%6,%7}, {%8,%9}, {%0,%1,%2,%3};"
                : "+f"(acc1[0]), "+f"(acc1[1]), "+f"(acc1[2]), "+f"(acc1[3])
                : "r"(a0), "r"(a1), "r"(a2), "r"(a3), "r"(b2), "r"(b3));
        }
        s = (s + 1) % 3;
    }

    const int grp = lane >> 2, qid = lane & 3;
    const int rlo = row0 + warp * 16 + grp;
    float2 bv0 = ((const float2*)bias)[qid];
    float2 bv1 = ((const float2*)bias)[4 + qid];
    float2 o;
    o.x = acc0[0] + bv0.x; o.y = acc0[1] + bv0.y;
    *(float2*)(out + (size_t)rlo * NHEAD + qid * 2) = o;
    o.x = acc0[2] + bv0.x; o.y = acc0[3] + bv0.y;
    *(float2*)(out + (size_t)(rlo + 8) * NHEAD + qid * 2) = o;
    o.x = acc1[0] + bv1.x; o.y = acc1[1] + bv1.y;
    *(float2*)(out + (size_t)rlo * NHEAD + 8 + qid * 2) = o;
    o.x = acc1[2] + bv1.x; o.y = acc1[3] + bv1.y;
    *(float2*)(out + (size_t)(rlo + 8) * NHEAD + 8 + qid * 2) = o;
}

// ============================================================================
// Combined fp32 -> fp16 conversion of X, Wq, Wk in ONE launch
// ============================================================================
constexpr int N4_X = MROWS * HID / 4;         // 8388608
constexpr int N4_W = HID * HID / 4;           // 262144

__global__ void f2h3_kernel(const float* __restrict__ X,
                            const float* __restrict__ Wq,
                            const float* __restrict__ Wk,
                            __half* __restrict__ xh,
                            __half* __restrict__ wqh,
                            __half* __restrict__ wkh)
{
    const int i = blockIdx.x * 256 + threadIdx.x;
    const float* src; __half* dst; int j;
    if (i < N4_X)            { src = X;  dst = xh;  j = i; }
    else if (i < N4_X + N4_W){ src = Wq; dst = wqh; j = i - N4_X; }
    else                     { src = Wk; dst = wkh; j = i - N4_X - N4_W; }
    float4 v = ((const float4*)src)[j];
    ((__half2*)dst)[2 * j]     = __floats2half2_rn(v.x, v.y);
    ((__half2*)dst)[2 * j + 1] = __floats2half2_rn(v.z, v.w);
}

// ============================================================================
// accum: per (bh, 512-row chunk) chunk-local softmax + partial pool.
// Emits UNNORMALIZED vec_c[64] plus (m_c, s_c); finalize combines chunks.
// No separate stats kernel needed.
// ============================================================================
__global__ void accum_kernel(const __half* __restrict__ src,
                             const float* __restrict__ scores,
                             const float* __restrict__ mask,
                             float* __restrict__ part, float2* __restrict__ ms)
{
    __shared__ float sL[512];
    __shared__ float red[256];
    const int blk = blockIdx.x, bh = blk >> 3, ch = blk & 7;
    const int b = bh >> 4, h = bh & 15;
    const int t = threadIdx.x, d = t & 63, sg = t >> 6;
    const int s0 = ch * 512;
    const float* sc = scores + ((size_t)(b * SEQ + s0)) * NHEAD + h;
    const float* mk = mask + b * SEQ + s0;

    // logits + chunk max
    float l0 = sc[(size_t)t * NHEAD] * 0.125f + mk[t];
    float l1 = sc[(size_t)(t + 256) * NHEAD] * 0.125f + mk[t + 256];
    sL[t] = l0; sL[t + 256] = l1;
    red[t] = fmaxf(l0, l1); __syncthreads();
    for (int o = 128; o; o >>= 1) { if (t < o) red[t] = fmaxf(red[t], red[t + o]); __syncthreads(); }
    const float mc = red[0]; __syncthreads();

    // chunk sum of exp
    float ps = __expf(l0 - mc) + __expf(l1 - mc);
    red[t] = ps; __syncthreads();
    for (int o = 128; o; o >>= 1) { if (t < o) red[t] += red[t + o]; __syncthreads(); }
    const float ssum = red[0]; __syncthreads();

    // weighted pool (unnormalized)
    const __half* base = src + (size_t)(b * SEQ + s0) * HID + h * 64 + d;
    float acc = 0.f;
    for (int s = sg; s < 512; s += 4)
        acc += __expf(sL[s] - mc) * __half2float(base[(size_t)s * HID]);
    red[t] = acc; __syncthreads();
    if (sg == 0) {
        part[(size_t)blk * 64 + d] = red[d] + red[64 + d] + red[128 + d] + red[192 + d];
        if (d == 0) ms[blk] = make_float2(mc, ssum);
    }
}

__global__ void finalize_kernel(const float* __restrict__ part,
                                const float2* __restrict__ ms,
                                const float* __restrict__ postgate, float* __restrict__ out)
{
    const int idx = blockIdx.x * 256 + threadIdx.x;   // 8192
    const int bh = idx >> 6, d = idx & 63;
    float2 m8[8];
    float M = -1e30f;
#pragma unroll
    for (int c = 0; c < 8; c++) { m8[c] = ms[bh * 8 + c]; M = fmaxf(M, m8[c].x); }
    float num = 0.f, den = 0.f;
#pragma unroll
    for (int c = 0; c < 8; c++) {
        const float w = __expf(m8[c].x - M);
        num += w * part[(size_t)(bh * 8 + c) * 64 + d];
        den += w * m8[c].y;
    }
    float v = num / den;
    if (postgate) v *= postgate[idx];
    out[idx] = v;
}

// wtgh[b,n,k] = (half)(Wt[n,k] * pk[b,k] * 2^14)   (scale avoids fp16 subnormals)
__global__ void wtg_kernel(const float* __restrict__ Wt, const float* __restrict__ pk,
                           __half* __restrict__ wtgh)
{
    const size_t i4 = (size_t)blockIdx.x * 256 + threadIdx.x;  // 2,097,152
    const int j4 = (int)(i4 & 255);
    const int n  = (int)((i4 >> 8) & 1023);
    const int b  = (int)(i4 >> 18);
    float4 w = ((const float4*)Wt)[n * 256 + j4];
    float4 g = ((const float4*)pk)[b * 256 + j4];
    const float S = 16384.0f;
    __half2 h0 = __floats2half2_rn(w.x * g.x * S, w.y * g.y * S);
    __half2 h1 = __floats2half2_rn(w.z * g.z * S, w.w * g.w * S);
    ((__half2*)wtgh)[2 * i4]     = h0;
    ((__half2*)wtgh)[2 * i4 + 1] = h1;
}

// ============================================================================
extern "C" void kernel_launch(void* const* d_in, const int* in_sizes, int n_in,
                              void* d_out, int out_size)
{
    const float* X    = (const float*)d_in[0];
    const float* mask = (const float*)d_in[1];
    const float* Wq   = (const float*)d_in[2];
    const float* bq   = (const float*)d_in[3];
    const float* Wqa  = (const float*)d_in[4];
    const float* bqa  = (const float*)d_in[5];
    const float* Wk   = (const float*)d_in[6];
    const float* bk   = (const float*)d_in[7];
    const float* Wka  = (const float*)d_in[8];
    const float* bka  = (const float*)d_in[9];
    const float* Wt   = (const float*)d_in[10];
    const float* bt   = (const float*)d_in[11];
    float* out = (float*)d_out;

    float *qs, *ks, *pq, *pk, *part;
    float2 *ms;
    __half *xh, *mqh, *mkh, *wqh, *wkh, *wtgh;
    cudaGetSymbolAddress((void**)&qs, g_qs);
    cudaGetSymbolAddress((void**)&ks, g_ks);
    cudaGetSymbolAddress((void**)&pq, g_pq);
    cudaGetSymbolAddress((void**)&pk, g_pk);
    cudaGetSymbolAddress((void**)&part, g_part);
    cudaGetSymbolAddress((void**)&ms, g_ms);
    cudaGetSymbolAddress((void**)&xh, g_xh);
    cudaGetSymbolAddress((void**)&mqh, g_mqh);
    cudaGetSymbolAddress((void**)&mkh, g_mkh);
    cudaGetSymbolAddress((void**)&wqh, g_wqh);
    cudaGetSymbolAddress((void**)&wkh, g_wkh);
    cudaGetSymbolAddress((void**)&wtgh, g_wtgh);

    cudaFuncSetAttribute(gemm_fp16<true, false, true, false>,
                         cudaFuncAttributeMaxDynamicSharedMemorySize, (int)GEMM_SMEM);
    cudaFuncSetAttribute(gemm_fp16<false, true, false, true>,
                         cudaFuncAttributeMaxDynamicSharedMemorySize, (int)GEMM_SMEM);
    cudaFuncSetAttribute(score_mma,
                         cudaFuncAttributeMaxDynamicSharedMemorySize, (int)SC_SMEM);

    const float* nullf = nullptr;

    // 0) single fused fp32->fp16 conversion (X, Wq, Wk)
    f2h3_kernel<<<(N4_X + 2 * N4_W + 255) / 256, 256>>>(X, Wq, Wk, xh, wqh, wkh);

    // 1) fused: mqh = X@Wq^T + bq ; mkh = X@Wk^T + bk  (fp16 outputs)
    gemm_fp16<true, false, true, false><<<dim3(16, MROWS / BM), 128, GEMM_SMEM>>>(
        xh, wqh, wkh, bq, bk, (const __half*)nullptr, (float*)nullptr, mqh, mkh);

    // 2) q scores -> pooled_q (chunk-local softmax; no stats kernel)
    score_mma<<<MROWS / 128, 256, SC_SMEM>>>(mqh, Wqa, bqa, nullf, qs);
    accum_kernel<<<BATCH * NHEAD * 8, 256>>>(mqh, qs, mask, part, ms);
    finalize_kernel<<<BATCH * HID / 256, 256>>>(part, ms, nullf, pq);

    // 3) qk scores (gate folded into Wka) -> pooled_k (post-gate pq)
    score_mma<<<MROWS / 128, 256, SC_SMEM>>>(mkh, Wka, bka, pq, ks);
    accum_kernel<<<BATCH * NHEAD * 8, 256>>>(mkh, ks, mask, part, ms);
    finalize_kernel<<<BATCH * HID / 256, 256>>>(part, ms, pq, pk);

    // 4) wtgh = Wt * pk_full[b] * 2^14 ; out = mqh @ wtgh[b]^T * 2^-14 + bt + mqh
    wtg_kernel<<<(BATCH * HID * HID / 4) / 256, 256>>>(Wt, pk, wtgh);
    gemm_fp16<false, true, false, true><<<dim3(8, MROWS / BM), 128, GEMM_SMEM>>>(
        mqh, wtgh, (const __half*)nullptr, bt, nullf, mqh, out,
        (__half*)nullptr, (__half*)nullptr);
}

// round 13
// speedup vs baseline: 3.1497x; 1.0401x over previous
#include <cuda_runtime.h>
#include <cuda_fp16.h>
#include <cstdint>
#include <cstddef>

#define BATCH 8
#define SEQ   4096
#define HID   1024
#define NHEAD 16
#define MROWS (BATCH * SEQ)   // 32768

// ---------------- scratch (device globals; allocations forbidden) ----------
__device__ __half g_xh[(size_t)MROWS * HID];
__device__ __half g_mqh[(size_t)MROWS * HID];
__device__ __half g_mkh[(size_t)MROWS * HID];
__device__ __half g_wqh[(size_t)HID * HID];
__device__ __half g_wkh[(size_t)HID * HID];
__device__ __half g_wtgh[(size_t)BATCH * HID * HID];
__device__ float  g_qs[(size_t)MROWS * NHEAD];
__device__ float  g_ks[(size_t)MROWS * NHEAD];
__device__ float  g_pq[BATCH * HID];
__device__ float  g_pk[BATCH * HID];
__device__ float  g_part[BATCH * NHEAD * 16 * 64];
__device__ float2 g_ms[BATCH * NHEAD * 16];

#define LDSM_X4(r0, r1, r2, r3, addr)                                             \
    asm volatile("ldmatrix.sync.aligned.m8n8.x4.shared.b16 {%0,%1,%2,%3}, [%4];"  \
                 : "=r"(r0), "=r"(r1), "=r"(r2), "=r"(r3) : "r"(addr))

#define BAR_ARRIVE(id) asm volatile("bar.arrive %0, 256;" :: "r"(id) : "memory")
#define BAR_SYNCN(id)  asm volatile("bar.sync %0, 256;"   :: "r"(id) : "memory")

// ============================================================================
// fp16 GEMM: acc[m,n] = sum_k A[m,k]*W[n,k]; out = acc*sc + bias (+resid)
// BM=64, BN=128, BK=64; 128 thr (4 warps, 2x2 grid, warp tile 32x64);
// 2-stage cp.async with split producer/consumer named barriers.
// 4 CTAs/SM (55.3KB smem, <=128 regs).
// DUAL: grid.x=16, nb<8 -> (W0,b0,H0), else (W1,b1,H1).
// PERB: W indexed per batch. OUTH: write __half outputs H0/H1.
// !OUTH: write float Cf with fp16 residual residH added. SCALED: acc *= 2^-14.
// ============================================================================
constexpr int BM = 64, BN = 128, BK = 64;
constexpr int SROW = 72;                      // halves per smem row (144B, padded)
constexpr int NKB = HID / BK;                 // 16
constexpr int STGH = (BM + BN) * SROW;        // 13824 halves per stage
constexpr size_t GEMM_SMEM = (size_t)2 * STGH * sizeof(__half);  // 55296 B

template <bool DUAL, bool PERB, bool OUTH, bool SCALED>
__global__ void __launch_bounds__(128, 4) gemm_fp16(
    const __half* __restrict__ A, const __half* __restrict__ W0, const __half* __restrict__ W1,
    const float* __restrict__ b0, const float* __restrict__ b1,
    const __half* __restrict__ residH, float* __restrict__ Cf,
    __half* __restrict__ H0, __half* __restrict__ H1)
{
    extern __shared__ __half smh[];
    const int tid = threadIdx.x;
    const int m0 = blockIdx.y * BM;
    int nb = blockIdx.x;

    const __half* W; const float* bias; __half* H = H0;
    if (DUAL) {
        if (nb < 8) { W = W0; bias = b0; H = H0; }
        else        { nb -= 8; W = W1; bias = b1; H = H1; }
    } else {
        W = W0 + (PERB ? (size_t)(m0 / SEQ) * HID * HID : 0);
        bias = b0;
    }
    const int n0 = nb * BN;

    const int warp = tid >> 5, lane = tid & 31;
    const int wm = warp & 1, wn = warp >> 1;    // 2x2 warps -> 32x64 per warp
    const int grp = lane >> 2, qid = lane & 3;

    const int lr = lane & 7;
    const int lh = (lane >> 3) & 1;
    const int lk = (lane >> 4) & 1;

    uint32_t offA[2], offB[4];
#pragma unroll
    for (int mt = 0; mt < 2; mt++)
        offA[mt] = (uint32_t)(((wm * 32 + mt * 16 + lh * 8 + lr) * SROW + lk * 8) * 2);
#pragma unroll
    for (int p = 0; p < 4; p++)
        offB[p] = (uint32_t)(((wn * 64 + p * 16 + lk * 8 + lr) * SROW + lh * 8) * 2
                             + BM * SROW * 2);

    const uint32_t smBase = (uint32_t)__cvta_generic_to_shared(smh);

    float acc[2][8][4];
#pragma unroll
    for (int i = 0; i < 2; i++)
#pragma unroll
        for (int j = 0; j < 8; j++)
#pragma unroll
            for (int l = 0; l < 4; l++) acc[i][j][l] = 0.f;

    const __half* Ab = A + (size_t)m0 * HID;
    const __half* Wb = W + (size_t)n0 * HID;

    auto loadTile = [&](int kb, int s) {
        __half* sa = smh + s * STGH;
        __half* sb = sa + BM * SROW;
        const __half* Ag = Ab + kb * BK;
        const __half* Wg = Wb + kb * BK;
#pragma unroll
        for (int i = 0; i < 12; i++) {         // 1536 granules of 16B
            const int id = tid + 128 * i;
            if (id < 512) {                    // A: 64 rows x 8 granules
                const int r = id >> 3, c = id & 7;
                uint32_t d = (uint32_t)__cvta_generic_to_shared(sa + r * SROW + c * 8);
                asm volatile("cp.async.cg.shared.global [%0], [%1], 16;"
                             :: "r"(d), "l"(Ag + (size_t)r * HID + c * 8));
            } else {                           // B: 128 rows x 8 granules
                const int id2 = id - 512;
                const int r = id2 >> 3, c = id2 & 7;
                uint32_t d = (uint32_t)__cvta_generic_to_shared(sb + r * SROW + c * 8);
                asm volatile("cp.async.cg.shared.global [%0], [%1], 16;"
                             :: "r"(d), "l"(Wg + (size_t)r * HID + c * 8));
            }
        }
        asm volatile("cp.async.commit_group;");
    };

    loadTile(0, 0);

    for (int kb = 0; kb < NKB; kb++) {
        const int b = kb & 1, onb = b ^ 1;
        asm volatile("cp.async.wait_group 0;");   // my loads for tile kb landed
        BAR_ARRIVE(1 + b);                        // A_b: my data for kb ready
        if (kb >= 1) BAR_SYNCN(3 + onb);          // F_onb: buffer onb freed
        if (kb + 1 < NKB) loadTile(kb + 1, onb);
        BAR_SYNCN(1 + b);                         // A_b: ALL data for kb visible

        const uint32_t stBase = smBase + b * (STGH * 2);

#pragma unroll
        for (int ks = 0; ks < 4; ks++) {
            const uint32_t kkb = ks * 32;
            uint32_t af[2][4], bf[8][2];
#pragma unroll
            for (int mt = 0; mt < 2; mt++)
                LDSM_X4(af[mt][0], af[mt][1], af[mt][2], af[mt][3],
                        stBase + offA[mt] + kkb);
#pragma unroll
            for (int p = 0; p < 4; p++)
                LDSM_X4(bf[2 * p][0], bf[2 * p][1], bf[2 * p + 1][0], bf[2 * p + 1][1],
                        stBase + offB[p] + kkb);
#pragma unroll
            for (int mt = 0; mt < 2; mt++)
#pragma unroll
                for (int nt = 0; nt < 8; nt++) {
                    asm volatile(
                        "mma.sync.aligned.m16n8k16.row.col.f32.f16.f16.f32 "
                        "{%0,%1,%2,%3}, {%4,%5,%6,%7}, {%8,%9}, {%0,%1,%2,%3};"
                        : "+f"(acc[mt][nt][0]), "+f"(acc[mt][nt][1]),
                          "+f"(acc[mt][nt][2]), "+f"(acc[mt][nt][3])
                        : "r"(af[mt][0]), "r"(af[mt][1]), "r"(af[mt][2]), "r"(af[mt][3]),
                          "r"(bf[nt][0]), "r"(bf[nt][1]));
                }
        }
        BAR_ARRIVE(3 + b);                        // F_b: I'm done reading buffer b
    }

    const float sc = SCALED ? 6.103515625e-5f : 1.0f;   // 2^-14

    // epilogue
#pragma unroll
    for (int mt = 0; mt < 2; mt++) {
        const int r0 = m0 + wm * 32 + mt * 16 + grp;
#pragma unroll
        for (int nt = 0; nt < 8; nt++) {
            const int c = n0 + wn * 64 + nt * 8 + qid * 2;
            const float bv0 = bias[c], bv1 = bias[c + 1];
            float v0 = acc[mt][nt][0] * sc + bv0, v1 = acc[mt][nt][1] * sc + bv1;
            float v2 = acc[mt][nt][2] * sc + bv0, v3 = acc[mt][nt][3] * sc + bv1;
            if (OUTH) {
                *(__half2*)(H + (size_t)r0 * HID + c)       = __floats2half2_rn(v0, v1);
                *(__half2*)(H + (size_t)(r0 + 8) * HID + c) = __floats2half2_rn(v2, v3);
            } else {
                __half2 ra = *(const __half2*)(residH + (size_t)r0 * HID + c);
                __half2 rb = *(const __half2*)(residH + (size_t)(r0 + 8) * HID + c);
                float2 raf = __half22float2(ra), rbf = __half22float2(rb);
                float2 oa = {v0 + raf.x, v1 + raf.y};
                float2 ob = {v2 + rbf.x, v3 + rbf.y};
                *(float2*)(Cf + (size_t)r0 * HID + c) = oa;
                *(float2*)(Cf + (size_t)(r0 + 8) * HID + c) = ob;
            }
        }
    }
}

// ============================================================================
// score_mma: out[m,h] = sum_k src[m,k]*(W[h,k]*(gate?g[b,k]:1)) + bias[h]
// Tensor-core skinny GEMM (N=16). Gated W resident in smem as fp16
// (row stride 1032 halves -> conflict-free LDSM); A 3-stage cp.async.
// 256 thr (8 warps x m16 = 128 rows/CTA), m16n8k16.
// ============================================================================
constexpr int SC_WROW = 1032;                 // Wg smem row stride (halves)
constexpr int SC_SROW = 72;                   // A smem row stride (halves)
constexpr int SC_NKT  = HID / 64;             // 16 K-tiles of 64
constexpr size_t SC_SMEM = (size_t)(16 * SC_WROW + 3 * 128 * SC_SROW) * 2; // 88320 B

__global__ void __launch_bounds__(256, 2) score_mma(
    const __half* __restrict__ src, const float* __restrict__ W,
    const float* __restrict__ bias, const float* __restrict__ gate,
    float* __restrict__ out)
{
    extern __shared__ __half ssc[];
    __half* sWg = ssc;                        // 16 x 1032
    __half* sA  = ssc + 16 * SC_WROW;         // 3 x 128 x 72
    const int tid = threadIdx.x, warp = tid >> 5, lane = tid & 31;
    const int row0 = blockIdx.x * 128;
    const int b = row0 / SEQ;

    // build gated fp16 weight in smem
    for (int i = tid; i < NHEAD * HID; i += 256) {
        const int h = i >> 10, k = i & 1023;
        float w = W[i];
        if (gate) w *= gate[b * HID + k];
        sWg[h * SC_WROW + k] = __float2half_rn(w);
    }

    const __half* Ab = src + (size_t)row0 * HID;
    auto loadA = [&](int kt, int s) {
        __half* sa = sA + s * 128 * SC_SROW;
        const __half* Ag = Ab + kt * 64;
#pragma unroll
        for (int i = 0; i < 4; i++) {          // 1024 granules of 16B
            const int id = tid + 256 * i;
            const int r = id >> 3, c = id & 7;
            uint32_t d = (uint32_t)__cvta_generic_to_shared(sa + r * SC_SROW + c * 8);
            asm volatile("cp.async.cg.shared.global [%0], [%1], 16;"
                         :: "r"(d), "l"(Ag + (size_t)r * HID + c * 8));
        }
        asm volatile("cp.async.commit_group;");
    };

    loadA(0, 0);
    loadA(1, 1);
    __syncthreads();                           // Wg visible to all warps

    const int lr = lane & 7;
    const int lh = (lane >> 3) & 1;
    const int lk = lane >> 4;
    const uint32_t offA = (uint32_t)(((warp * 16 + lh * 8 + lr) * SC_SROW + lk * 8) * 2);
    const uint32_t offBW = (uint32_t)(((lk * 8 + lr) * SC_WROW + lh * 8) * 2);
    const uint32_t smA = (uint32_t)__cvta_generic_to_shared(sA);
    const uint32_t smW = (uint32_t)__cvta_generic_to_shared(sWg);

    float acc0[4] = {0.f, 0.f, 0.f, 0.f};
    float acc1[4] = {0.f, 0.f, 0.f, 0.f};

    int s = 0;
    for (int kt = 0; kt < SC_NKT; kt++) {
        if (kt + 1 < SC_NKT) asm volatile("cp.async.wait_group 1;");
        else                 asm volatile("cp.async.wait_group 0;");
        __syncthreads();
        if (kt + 2 < SC_NKT) loadA(kt + 2, (s + 2) % 3);

        const uint32_t stA = smA + s * (128 * SC_SROW * 2);
#pragma unroll
        for (int ks = 0; ks < 4; ks++) {
            uint32_t a0, a1, a2, a3, b0, b1, b2, b3;
            LDSM_X4(a0, a1, a2, a3, stA + offA + ks * 32);
            LDSM_X4(b0, b1, b2, b3, smW + offBW + (uint32_t)((kt * 64 + ks * 16) * 2));
            asm volatile(
                "mma.sync.aligned.m16n8k16.row.col.f32.f16.f16.f32 "
                "{%0,%1,%2,%3}, {%4,%5,%6,%7}, {%8,%9}, {%0,%1,%2,%3};"
                : "+f"(acc0[0]), "+f"(acc0[1]), "+f"(acc0[2]), "+f"(acc0[3])
                : "r"(a0), "r"(a1), "r"(a2), "r"(a3), "r"(b0), "r"(b1));
            asm volatile(
                "mma.sync.aligned.m16n8k16.row.col.f32.f16.f16.f32 "
                "{%0,%1,%2,%3}, {%4,%5,%6,%7}, {%8,%9}, {%0,%1,%2,%3};"
                : "+f"(acc1[0]), "+f"(acc1[1]), "+f"(acc1[2]), "+f"(acc1[3])
                : "r"(a0), "r"(a1), "r"(a2), "r"(a3), "r"(b2), "r"(b3));
        }
        s = (s + 1) % 3;
    }

    const int grp = lane >> 2, qid = lane & 3;
    const int rlo = row0 + warp * 16 + grp;
    float2 bv0 = ((const float2*)bias)[qid];
    float2 bv1 = ((const float2*)bias)[4 + qid];
    float2 o;
    o.x = acc0[0] + bv0.x; o.y = acc0[1] + bv0.y;
    *(float2*)(out + (size_t)rlo * NHEAD + qid * 2) = o;
    o.x = acc0[2] + bv0.x; o.y = acc0[3] + bv0.y;
    *(float2*)(out + (size_t)(rlo + 8) * NHEAD + qid * 2) = o;
    o.x = acc1[0] + bv1.x; o.y = acc1[1] + bv1.y;
    *(float2*)(out + (size_t)rlo * NHEAD + 8 + qid * 2) = o;
    o.x = acc1[2] + bv1.x; o.y = acc1[3] + bv1.y;
    *(float2*)(out + (size_t)(rlo + 8) * NHEAD + 8 + qid * 2) = o;
}

// ============================================================================
// Combined fp32 -> fp16 conversion of X, Wq, Wk in ONE launch
// ============================================================================
constexpr int N4_X = MROWS * HID / 4;         // 8388608
constexpr int N4_W = HID * HID / 4;           // 262144

__global__ void f2h3_kernel(const float* __restrict__ X,
                            const float* __restrict__ Wq,
                            const float* __restrict__ Wk,
                            __half* __restrict__ xh,
                            __half* __restrict__ wqh,
                            __half* __restrict__ wkh)
{
    const int i = blockIdx.x * 256 + threadIdx.x;
    const float* src; __half* dst; int j;
    if (i < N4_X)            { src = X;  dst = xh;  j = i; }
    else if (i < N4_X + N4_W){ src = Wq; dst = wqh; j = i - N4_X; }
    else                     { src = Wk; dst = wkh; j = i - N4_X - N4_W; }
    float4 v = ((const float4*)src)[j];
    ((__half2*)dst)[2 * j]     = __floats2half2_rn(v.x, v.y);
    ((__half2*)dst)[2 * j + 1] = __floats2half2_rn(v.z, v.w);
}

// ============================================================================
// accum: per (bh, 256-row chunk) chunk-local softmax + partial pool.
// exp computed ONCE per row (stored in smem), pooling is pure LDG+FMA.
// Emits UNNORMALIZED vec_c[64] plus (m_c, s_c); finalize combines chunks.
// ============================================================================
constexpr int ACH = 16;                       // chunks per (b,h)
constexpr int ACS = SEQ / ACH;                // 256 rows per chunk

__global__ void accum_kernel(const __half* __restrict__ src,
                             const float* __restrict__ scores,
                             const float* __restrict__ mask,
                             float* __restrict__ part, float2* __restrict__ ms)
{
    __shared__ float  sL[ACS];
    __shared__ float  red[256];
    __shared__ float2 red2[256];
    const int blk = blockIdx.x, bh = blk >> 4, ch = blk & 15;
    const int b = bh >> 4, h = bh & 15;
    const int t = threadIdx.x;
    const int s0 = ch * ACS;
    const float* sc = scores + ((size_t)(b * SEQ + s0)) * NHEAD + h;
    const float* mk = mask + b * SEQ + s0;

    // logits + chunk max
    const float l = sc[(size_t)t * NHEAD] * 0.125f + mk[t];
    red[t] = l; __syncthreads();
    for (int o = 128; o; o >>= 1) { if (t < o) red[t] = fmaxf(red[t], red[t + o]); __syncthreads(); }
    const float mc = red[0]; __syncthreads();

    // exp once per row -> smem weights; chunk sum
    const float e = __expf(l - mc);
    sL[t] = e;
    red[t] = e; __syncthreads();
    for (int o = 128; o; o >>= 1) { if (t < o) red[t] += red[t + o]; __syncthreads(); }
    const float ssum = red[0];

    // weighted pool (unnormalized): 32 d2-threads x 8 row-groups, half2 loads
    const int d2 = t & 31, sg = t >> 5;
    const __half2* base = (const __half2*)(src + (size_t)(b * SEQ + s0) * HID + h * 64) + d2;
    float2 acc = {0.f, 0.f};
    for (int s = sg; s < ACS; s += 8) {
        const float w = sL[s];
        float2 v = __half22float2(base[(size_t)s * (HID / 2)]);
        acc.x += w * v.x; acc.y += w * v.y;
    }
    red2[t] = acc; __syncthreads();
    if (sg < 4) { red2[t].x += red2[t + 128].x; red2[t].y += red2[t + 128].y; } __syncthreads();
    if (sg < 2) { red2[t].x += red2[t + 64].x;  red2[t].y += red2[t + 64].y; }  __syncthreads();
    if (sg == 0) {
        float2 r = red2[t];
        r.x += red2[t + 32].x; r.y += red2[t + 32].y;
        ((float2*)(part + (size_t)blk * 64))[d2] = r;
        if (d2 == 0) ms[blk] = make_float2(mc, ssum);
    }
}

__global__ void finalize_kernel(const float* __restrict__ part,
                                const float2* __restrict__ ms,
                                const float* __restrict__ postgate, float* __restrict__ out)
{
    const int idx = blockIdx.x * 256 + threadIdx.x;   // 8192
    const int bh = idx >> 6, d = idx & 63;
    float2 mv[ACH];
    float M = -1e30f;
#pragma unroll
    for (int c = 0; c < ACH; c++) { mv[c] = ms[bh * ACH + c]; M = fmaxf(M, mv[c].x); }
    float num = 0.f, den = 0.f;
#pragma unroll
    for (int c = 0; c < ACH; c++) {
        const float w = __expf(mv[c].x - M);
        num += w * part[(size_t)(bh * ACH + c) * 64 + d];
        den += w * mv[c].y;
    }
    float v = num / den;
    if (postgate) v *= postgate[idx];
    out[idx] = v;
}

// wtgh[b,n,k] = (half)(Wt[n,k] * pk[b,k] * 2^14)   (scale avoids fp16 subnormals)
__global__ void wtg_kernel(const float* __restrict__ Wt, const float* __restrict__ pk,
                           __half* __restrict__ wtgh)
{
    const size_t i4 = (size_t)blockIdx.x * 256 + threadIdx.x;  // 2,097,152
    const int j4 = (int)(i4 & 255);
    const int n  = (int)((i4 >> 8) & 1023);
    const int b  = (int)(i4 >> 18);
    float4 w = ((const float4*)Wt)[n * 256 + j4];
    float4 g = ((const float4*)pk)[b * 256 + j4];
    const float S = 16384.0f;
    __half2 h0 = __floats2half2_rn(w.x * g.x * S, w.y * g.y * S);
    __half2 h1 = __floats2half2_rn(w.z * g.z * S, w.w * g.w * S);
    ((__half2*)wtgh)[2 * i4]     = h0;
    ((__half2*)wtgh)[2 * i4 + 1] = h1;
}

// ============================================================================
extern "C" void kernel_launch(void* const* d_in, const int* in_sizes, int n_in,
                              void* d_out, int out_size)
{
    const float* X    = (const float*)d_in[0];
    const float* mask = (const float*)d_in[1];
    const float* Wq   = (const float*)d_in[2];
    const float* bq   = (const float*)d_in[3];
    const float* Wqa  = (const float*)d_in[4];
    const float* bqa  = (const float*)d_in[5];
    const float* Wk   = (const float*)d_in[6];
    const float* bk   = (const float*)d_in[7];
    const float* Wka  = (const float*)d_in[8];
    const float* bka  = (const float*)d_in[9];
    const float* Wt   = (const float*)d_in[10];
    const float* bt   = (const float*)d_in[11];
    float* out = (float*)d_out;

    float *qs, *ks, *pq, *pk, *part;
    float2 *ms;
    __half *xh, *mqh, *mkh, *wqh, *wkh, *wtgh;
    cudaGetSymbolAddress((void**)&qs, g_qs);
    cudaGetSymbolAddress((void**)&ks, g_ks);
    cudaGetSymbolAddress((void**)&pq, g_pq);
    cudaGetSymbolAddress((void**)&pk, g_pk);
    cudaGetSymbolAddress((void**)&part, g_part);
    cudaGetSymbolAddress((void**)&ms, g_ms);
    cudaGetSymbolAddress((void**)&xh, g_xh);
    cudaGetSymbolAddress((void**)&mqh, g_mqh);
    cudaGetSymbolAddress((void**)&mkh, g_mkh);
    cudaGetSymbolAddress((void**)&wqh, g_wqh);
    cudaGetSymbolAddress((void**)&wkh, g_wkh);
    cudaGetSymbolAddress((void**)&wtgh, g_wtgh);

    cudaFuncSetAttribute(gemm_fp16<true, false, true, false>,
                         cudaFuncAttributeMaxDynamicSharedMemorySize, (int)GEMM_SMEM);
    cudaFuncSetAttribute(gemm_fp16<false, true, false, true>,
                         cudaFuncAttributeMaxDynamicSharedMemorySize, (int)GEMM_SMEM);
    cudaFuncSetAttribute(score_mma,
                         cudaFuncAttributeMaxDynamicSharedMemorySize, (int)SC_SMEM);

    const float* nullf = nullptr;

    // 0) single fused fp32->fp16 conversion (X, Wq, Wk)
    f2h3_kernel<<<(N4_X + 2 * N4_W + 255) / 256, 256>>>(X, Wq, Wk, xh, wqh, wkh);

    // 1) fused: mqh = X@Wq^T + bq ; mkh = X@Wk^T + bk  (fp16 outputs)
    gemm_fp16<true, false, true, false><<<dim3(16, MROWS / BM), 128, GEMM_SMEM>>>(
        xh, wqh, wkh, bq, bk, (const __half*)nullptr, (float*)nullptr, mqh, mkh);

    // 2) q scores -> pooled_q (chunk-local softmax; no stats kernel)
    score_mma<<<MROWS / 128, 256, SC_SMEM>>>(mqh, Wqa, bqa, nullf, qs);
    accum_kernel<<<BATCH * NHEAD * ACH, 256>>>(mqh, qs, mask, part, ms);
    finalize_kernel<<<BATCH * HID / 256, 256>>>(part, ms, nullf, pq);

    // 3) qk scores (gate folded into Wka) -> pooled_k (post-gate pq)
    score_mma<<<MROWS / 128, 256, SC_SMEM>>>(mkh, Wka, bka, pq, ks);
    accum_kernel<<<BATCH * NHEAD * ACH, 256>>>(mkh, ks, mask, part, ms);
    finalize_kernel<<<BATCH * HID / 256, 256>>>(part, ms, pq, pk);

    // 4) wtgh = Wt * pk_full[b] * 2^14 ; out = mqh @ wtgh[b]^T * 2^-14 + bt + mqh
    wtg_kernel<<<(BATCH * HID * HID / 4) / 256, 256>>>(Wt, pk, wtgh);
    gemm_fp16<false, true, false, true><<<dim3(8, MROWS / BM), 128, GEMM_SMEM>>>(
        mqh, wtgh, (const __half*)nullptr, bt, nullf, mqh, out,
        (__half*)nullptr, (__half*)nullptr);
}